// round 2
// baseline (speedup 1.0000x reference)
#include <cuda_runtime.h>
#include <cuda_bf16.h>
#include <math.h>

// Problem dims
#define BB   16
#define N1   2048
#define N2   2048
#define HH   768
#define LAT  128
#define MID  256
#define RTOT (BB * N1)          // 32768 rows for all row-major GEMMs

// ---------------------------------------------------------------------------
// Scratch (device globals: allocation-free, graph-capturable)
// ---------------------------------------------------------------------------
__device__ float g_mid [RTOT * MID];   // 32 MB, reused: enc-main hid, enc-feat hid, dec hid
__device__ float g_m   [RTOT * LAT];
__device__ float g_f   [RTOT * LAT];
__device__ float g_q   [RTOT * LAT];
__device__ float g_k   [RTOT * LAT];
__device__ float g_v   [RTOT * LAT];
__device__ float g_attn[RTOT * LAT];

// ---------------------------------------------------------------------------
// GEMM: C[M,N] = act(A[M,K] @ W[K,N] + bias[N])
// BM=128, BN=64, BK=16, 256 threads, 8x4 register tile per thread.
// ACT: 0 = none, 1 = relu, 2 = sigmoid
// M % 128 == 0, N % 64 == 0, K % 16 == 0 hold for all call sites.
// ---------------------------------------------------------------------------
template <int ACT>
__global__ __launch_bounds__(256) void gemm_bias_act(
    const float* __restrict__ A, const float* __restrict__ W,
    const float* __restrict__ bias, float* __restrict__ C,
    int M, int N, int K)
{
    __shared__ float As[16][132];   // [k][m], padded
    __shared__ float Bs[16][68];    // [k][n], padded

    const int tid = threadIdx.x;
    const int m0 = blockIdx.y * 128;
    const int n0 = blockIdx.x * 64;
    const int ty = tid >> 4;        // 0..15 -> rows ty*8..ty*8+7
    const int tx = tid & 15;        // 0..15 -> cols tx*4..tx*4+3

    float acc[8][4];
#pragma unroll
    for (int i = 0; i < 8; i++)
#pragma unroll
        for (int j = 0; j < 4; j++) acc[i][j] = 0.f;

    for (int k0 = 0; k0 < K; k0 += 16) {
        // Load A tile [128 x 16] -> As[k][m] (transposed store)
#pragma unroll
        for (int i = 0; i < 2; i++) {
            int idx = tid + i * 256;       // 0..511
            int r   = idx >> 2;            // 0..127
            int c4  = idx & 3;             // 0..3 (16 cols / 4)
            float4 v = *(const float4*)(A + (long)(m0 + r) * K + k0 + c4 * 4);
            As[c4 * 4 + 0][r] = v.x;
            As[c4 * 4 + 1][r] = v.y;
            As[c4 * 4 + 2][r] = v.z;
            As[c4 * 4 + 3][r] = v.w;
        }
        // Load B tile [16 x 64]
        {
            int k  = tid >> 4;             // 0..15
            int n4 = tid & 15;             // 0..15
            *(float4*)&Bs[k][n4 * 4] =
                *(const float4*)(W + (long)(k0 + k) * N + n0 + n4 * 4);
        }
        __syncthreads();

#pragma unroll
        for (int kk = 0; kk < 16; kk++) {
            float4 a0 = *(float4*)&As[kk][ty * 8];
            float4 a1 = *(float4*)&As[kk][ty * 8 + 4];
            float4 b  = *(float4*)&Bs[kk][tx * 4];
            float av[8] = {a0.x, a0.y, a0.z, a0.w, a1.x, a1.y, a1.z, a1.w};
            float bv[4] = {b.x, b.y, b.z, b.w};
#pragma unroll
            for (int i = 0; i < 8; i++)
#pragma unroll
                for (int j = 0; j < 4; j++)
                    acc[i][j] += av[i] * bv[j];
        }
        __syncthreads();
    }

    float4 bq = *(const float4*)(bias + n0 + tx * 4);
    float bv[4] = {bq.x, bq.y, bq.z, bq.w};

#pragma unroll
    for (int i = 0; i < 8; i++) {
        float o[4];
#pragma unroll
        for (int j = 0; j < 4; j++) {
            float x = acc[i][j] + bv[j];
            if (ACT == 1) x = fmaxf(x, 0.f);
            if (ACT == 2) x = 1.f / (1.f + __expf(-x));
            o[j] = x;
        }
        *(float4*)(C + (long)(m0 + ty * 8 + i) * N + n0 + tx * 4) =
            make_float4(o[0], o[1], o[2], o[3]);
    }
}

// ---------------------------------------------------------------------------
// Flash attention (unscaled scores): per block: 128 query rows of one batch.
// BM=128 (query tile), BN=64 (key tile), D=128. 256 threads.
// Q tile resident in SMEM (XOR-swizzled for conflict-free k-major reads).
// K and V share one 32KB buffer. Online softmax; O accum in registers (8x8).
// ---------------------------------------------------------------------------
#define FA_BM 128
#define FA_BN 64

// smem floats: Qs 128*128, KVs 64*128, Ssh 128*68, m/l/alpha 3*128
#define FA_SMEM_FLOATS (128*128 + 64*128 + 128*68 + 3*128)

__global__ __launch_bounds__(256, 1) void flash_attn_kernel(
    const float* __restrict__ Q, const float* __restrict__ K,
    const float* __restrict__ V, float* __restrict__ O)
{
    extern __shared__ float sm[];
    float* Qs  = sm;                    // [r][swz(k4)] 128x128
    float* KVs = Qs + 128 * 128;        // K: swizzled 64x128 / V: natural 64x128
    float* Ssh = KVs + 64 * 128;        // [128][68]
    float* msh = Ssh + 128 * 68;
    float* lsh = msh + 128;
    float* ash = lsh + 128;

    const int tid = threadIdx.x;
    const int b   = blockIdx.y;
    const int m0  = blockIdx.x * FA_BM;

    const float* Qb = Q + ((long)b * N1 + m0) * LAT;
    const float* Kb = K + (long)b * N2 * LAT;
    const float* Vb = V + (long)b * N2 * LAT;

    // Load Q tile [128][128], swizzled: float4 col c4 stored at c4 ^ ((r>>2)&7)
#pragma unroll
    for (int i = 0; i < 16; i++) {
        int idx = tid + i * 256;
        int r   = idx >> 5;             // 0..127
        int c4  = idx & 31;             // 0..31
        float4 v = *(const float4*)(Qb + r * LAT + c4 * 4);
        int sw = c4 ^ ((r >> 2) & 7);
        *(float4*)(Qs + r * 128 + sw * 4) = v;
    }
    if (tid < 128) {
        msh[tid] = -INFINITY;
        lsh[tid] = 0.f;
    }

    const int sty = tid >> 4, stx = tid & 15;   // S tile: rows sty*8, cols stx*4
    const int oty = tid >> 4, otx = tid & 15;   // O tile: rows oty*8, cols otx*8

    float Oacc[8][8];
#pragma unroll
    for (int i = 0; i < 8; i++)
#pragma unroll
        for (int j = 0; j < 8; j++) Oacc[i][j] = 0.f;

    __syncthreads();

    for (int t0 = 0; t0 < N2; t0 += FA_BN) {
        // --- Load K tile [64][128], swizzled ---
#pragma unroll
        for (int i = 0; i < 8; i++) {
            int idx = tid + i * 256;
            int r   = idx >> 5;         // 0..63
            int c4  = idx & 31;
            float4 v = *(const float4*)(Kb + (t0 + r) * LAT + c4 * 4);
            int sw = c4 ^ ((r >> 2) & 7);
            *(float4*)(KVs + r * 128 + sw * 4) = v;
        }
        __syncthreads();

        // --- S = Q @ K^T (8x4 per thread, vectorized over k) ---
        float acc[8][4];
#pragma unroll
        for (int i = 0; i < 8; i++)
#pragma unroll
            for (int j = 0; j < 4; j++) acc[i][j] = 0.f;

#pragma unroll 4
        for (int k4 = 0; k4 < 32; k4++) {
            float4 a[8], bb[4];
#pragma unroll
            for (int i = 0; i < 8; i++) {
                int r = sty * 8 + i;
                a[i] = *(float4*)(Qs + r * 128 + ((k4 ^ ((r >> 2) & 7)) << 2));
            }
#pragma unroll
            for (int j = 0; j < 4; j++) {
                int c = stx * 4 + j;
                bb[j] = *(float4*)(KVs + c * 128 + ((k4 ^ ((c >> 2) & 7)) << 2));
            }
#pragma unroll
            for (int i = 0; i < 8; i++)
#pragma unroll
                for (int j = 0; j < 4; j++) {
                    acc[i][j] += a[i].x * bb[j].x;
                    acc[i][j] += a[i].y * bb[j].y;
                    acc[i][j] += a[i].z * bb[j].z;
                    acc[i][j] += a[i].w * bb[j].w;
                }
        }

        // --- Stage S to shared ---
#pragma unroll
        for (int i = 0; i < 8; i++)
            *(float4*)(Ssh + (sty * 8 + i) * 68 + stx * 4) =
                make_float4(acc[i][0], acc[i][1], acc[i][2], acc[i][3]);
        __syncthreads();   // KVs free now; Ssh complete

        // --- Load V tile [64][128] natural layout (all threads) ---
#pragma unroll
        for (int i = 0; i < 8; i++) {
            int idx = tid + i * 256;
            int r   = idx >> 5;
            int c4  = idx & 31;
            *(float4*)(KVs + r * 128 + c4 * 4) =
                *(const float4*)(Vb + (t0 + r) * LAT + c4 * 4);
        }

        // --- Online softmax row pass (threads 0..127, one row each) ---
        if (tid < 128) {
            float mold = msh[tid];
            float mnew = mold;
            float* srow = Ssh + tid * 68;
#pragma unroll
            for (int j = 0; j < 64; j++) mnew = fmaxf(mnew, srow[j]);
            float alpha = __expf(mold - mnew);
            float lsum = 0.f;
#pragma unroll
            for (int j = 0; j < 64; j++) {
                float e = __expf(srow[j] - mnew);
                srow[j] = e;
                lsum += e;
            }
            lsh[tid] = lsh[tid] * alpha + lsum;
            msh[tid] = mnew;
            ash[tid] = alpha;
        }
        __syncthreads();

        // --- O = O*alpha + P @ V (8x8 per thread) ---
        float alpha_r[8];
#pragma unroll
        for (int i = 0; i < 8; i++) alpha_r[i] = ash[oty * 8 + i];
#pragma unroll
        for (int i = 0; i < 8; i++)
#pragma unroll
            for (int j = 0; j < 8; j++) Oacc[i][j] *= alpha_r[i];

#pragma unroll 4
        for (int j = 0; j < 64; j++) {
            float4 v0 = *(float4*)(KVs + j * 128 + otx * 8);
            float4 v1 = *(float4*)(KVs + j * 128 + otx * 8 + 4);
            float p[8];
#pragma unroll
            for (int i = 0; i < 8; i++) p[i] = Ssh[(oty * 8 + i) * 68 + j];
#pragma unroll
            for (int i = 0; i < 8; i++) {
                Oacc[i][0] += p[i] * v0.x;
                Oacc[i][1] += p[i] * v0.y;
                Oacc[i][2] += p[i] * v0.z;
                Oacc[i][3] += p[i] * v0.w;
                Oacc[i][4] += p[i] * v1.x;
                Oacc[i][5] += p[i] * v1.y;
                Oacc[i][6] += p[i] * v1.z;
                Oacc[i][7] += p[i] * v1.w;
            }
        }
        __syncthreads();   // protect KVs/Ssh before next tile
    }

    // --- Epilogue: divide by l, write out ---
#pragma unroll
    for (int i = 0; i < 8; i++) {
        float inv_l = 1.f / lsh[oty * 8 + i];
        long row = (long)b * N1 + m0 + oty * 8 + i;
        float4 o0 = make_float4(Oacc[i][0] * inv_l, Oacc[i][1] * inv_l,
                                Oacc[i][2] * inv_l, Oacc[i][3] * inv_l);
        float4 o1 = make_float4(Oacc[i][4] * inv_l, Oacc[i][5] * inv_l,
                                Oacc[i][6] * inv_l, Oacc[i][7] * inv_l);
        *(float4*)(O + row * LAT + otx * 8)     = o0;
        *(float4*)(O + row * LAT + otx * 8 + 4) = o1;
    }
}

// ---------------------------------------------------------------------------
// Host launcher
// ---------------------------------------------------------------------------
extern "C" void kernel_launch(void* const* d_in, const int* in_sizes, int n_in,
                              void* d_out, int out_size)
{
    const float* mainf = (const float*)d_in[0];
    const float* feat  = (const float*)d_in[1];
    const float* We1   = (const float*)d_in[2];
    const float* be1   = (const float*)d_in[3];
    const float* We2   = (const float*)d_in[4];
    const float* be2   = (const float*)d_in[5];
    const float* Wq    = (const float*)d_in[6];
    const float* bq    = (const float*)d_in[7];
    const float* Wk    = (const float*)d_in[8];
    const float* bk    = (const float*)d_in[9];
    const float* Wv    = (const float*)d_in[10];
    const float* bv    = (const float*)d_in[11];
    const float* Wd1   = (const float*)d_in[12];
    const float* bd1   = (const float*)d_in[13];
    const float* Wd2   = (const float*)d_in[14];
    const float* bd2   = (const float*)d_in[15];
    float* out = (float*)d_out;

    float *p_mid, *p_m, *p_f, *p_q, *p_k, *p_v, *p_attn;
    cudaError_t e = cudaSuccess;
    e = cudaGetSymbolAddress((void**)&p_mid,  g_mid);
    e = cudaGetSymbolAddress((void**)&p_m,    g_m);
    e = cudaGetSymbolAddress((void**)&p_f,    g_f);
    e = cudaGetSymbolAddress((void**)&p_q,    g_q);
    e = cudaGetSymbolAddress((void**)&p_k,    g_k);
    e = cudaGetSymbolAddress((void**)&p_v,    g_v);
    e = cudaGetSymbolAddress((void**)&p_attn, g_attn);
    (void)e;

    const int fa_smem = FA_SMEM_FLOATS * sizeof(float);  // ~131.5 KB
    cudaFuncSetAttribute(flash_attn_kernel,
                         cudaFuncAttributeMaxDynamicSharedMemorySize, fa_smem);

    dim3 blk(256);
    const int M = RTOT;

    // encode(main): relu(main @ We1 + be1) -> mid ; relu(mid @ We2 + be2) -> m
    gemm_bias_act<1><<<dim3(MID / 64, M / 128), blk>>>(mainf, We1, be1, p_mid, M, MID, HH);
    gemm_bias_act<1><<<dim3(LAT / 64, M / 128), blk>>>(p_mid, We2, be2, p_m,  M, LAT, MID);
    // encode(feature)
    gemm_bias_act<1><<<dim3(MID / 64, M / 128), blk>>>(feat,  We1, be1, p_mid, M, MID, HH);
    gemm_bias_act<1><<<dim3(LAT / 64, M / 128), blk>>>(p_mid, We2, be2, p_f,  M, LAT, MID);
    // q, k, v
    gemm_bias_act<0><<<dim3(LAT / 64, M / 128), blk>>>(p_m, Wq, bq, p_q, M, LAT, LAT);
    gemm_bias_act<0><<<dim3(LAT / 64, M / 128), blk>>>(p_f, Wk, bk, p_k, M, LAT, LAT);
    gemm_bias_act<0><<<dim3(LAT / 64, M / 128), blk>>>(p_f, Wv, bv, p_v, M, LAT, LAT);
    // attention
    flash_attn_kernel<<<dim3(N1 / FA_BM, BB), blk, fa_smem>>>(p_q, p_k, p_v, p_attn);
    // decode: relu(attn @ Wd1 + bd1) -> mid ; sigmoid(mid @ Wd2 + bd2) -> out
    gemm_bias_act<1><<<dim3(MID / 64, M / 128), blk>>>(p_attn, Wd1, bd1, p_mid, M, MID, LAT);
    gemm_bias_act<2><<<dim3(HH  / 64, M / 128), blk>>>(p_mid,  Wd2, bd2, out,  M, HH,  MID);
}

// round 6
// speedup vs baseline: 1.4521x; 1.4521x over previous
#include <cuda_runtime.h>
#include <math.h>
#include <cstdint>

// Problem dims
#define BB   16
#define N1   2048
#define N2   2048
#define HH   768
#define LAT  128
#define MID  256
#define RTOT (BB * N1)          // 32768 rows

// ---------------------------------------------------------------------------
// Scratch (device globals: allocation-free, graph-capturable)
// ---------------------------------------------------------------------------
__device__ float g_mid [RTOT * MID];
__device__ float g_m   [RTOT * LAT];
__device__ float g_f   [RTOT * LAT];
__device__ float g_q   [RTOT * LAT];
__device__ float g_k   [RTOT * LAT];
__device__ float g_v   [RTOT * LAT];
__device__ float g_attn[RTOT * LAT];
// Transposed weights [N, K] row-major
__device__ float g_wt_e1[MID * HH];
__device__ float g_wt_e2[LAT * MID];
__device__ float g_wt_q [LAT * LAT];
__device__ float g_wt_k [LAT * LAT];
__device__ float g_wt_v [LAT * LAT];
__device__ float g_wt_d1[MID * LAT];
__device__ float g_wt_d2[HH * MID];

// ---------------------------------------------------------------------------
// Helpers
// ---------------------------------------------------------------------------
__device__ __forceinline__ float tf32r(float x) {
    uint32_t u;
    asm("cvt.rna.tf32.f32 %0, %1;" : "=r"(u) : "f"(x));
    return __uint_as_float(u);
}
// D += A(16x8,row) * B(8x8,col)  tf32, fp32 accum
__device__ __forceinline__ void mma8(float c[4], const uint32_t a[4], const uint32_t b[2]) {
    asm volatile(
        "mma.sync.aligned.m16n8k8.row.col.f32.tf32.tf32.f32 "
        "{%0,%1,%2,%3}, {%4,%5,%6,%7}, {%8,%9}, {%0,%1,%2,%3};"
        : "+f"(c[0]), "+f"(c[1]), "+f"(c[2]), "+f"(c[3])
        : "r"(a[0]), "r"(a[1]), "r"(a[2]), "r"(a[3]), "r"(b[0]), "r"(b[1]));
}
__device__ __forceinline__ uint32_t fu(float x) { return __float_as_uint(x); }

// ---------------------------------------------------------------------------
// Weight transpose: in [K, N] row-major -> out [N, K] row-major
// ---------------------------------------------------------------------------
__global__ void transpose_kernel(const float* __restrict__ in, float* __restrict__ out,
                                 int K, int N)
{
    __shared__ float t[32][33];
    int nx = blockIdx.x * 32, kx = blockIdx.y * 32;
    int x = threadIdx.x, y = threadIdx.y;   // 32 x 8
#pragma unroll
    for (int i = 0; i < 32; i += 8)
        t[y + i][x] = in[(long)(kx + y + i) * N + nx + x];
    __syncthreads();
#pragma unroll
    for (int i = 0; i < 32; i += 8)
        out[(long)(nx + y + i) * K + kx + x] = t[x][y + i];
}

// ---------------------------------------------------------------------------
// tf32 mma GEMM: C[M,N] = act(A[M,K] @ Wt[N,K]^T + bias[N])
// CTA tile 128x128, 128 threads = 4 warps of 64x64, BK=32 double-buffered.
// SMEM padded stride 36 -> conflict-free fragment loads.
// ACT: 0=none, 1=relu, 2=sigmoid
// ---------------------------------------------------------------------------
#define GPAD 36

template <int ACT>
__global__ __launch_bounds__(128) void gemm_mma(
    const float* __restrict__ A, const float* __restrict__ Wt,
    const float* __restrict__ bias, float* __restrict__ C,
    int M, int N, int K)
{
    extern __shared__ float sm[];
    float* As = sm;                       // [2][128*GPAD]
    float* Bs = sm + 2 * 128 * GPAD;      // [2][128*GPAD]

    const int tid = threadIdx.x;
    const int wid = tid >> 5, lane = tid & 31;
    const int g = lane >> 2, t4 = lane & 3;
    const int wm = (wid & 1) * 64, wn = (wid >> 1) * 64;
    const int m0 = blockIdx.y * 128, n0 = blockIdx.x * 128;

    float c[4][8][4];
#pragma unroll
    for (int mt = 0; mt < 4; mt++)
#pragma unroll
        for (int nt = 0; nt < 8; nt++)
#pragma unroll
            for (int i = 0; i < 4; i++) c[mt][nt][i] = 0.f;

    const int nk = K >> 5;

    // loader: thread tid loads one full A row and one full B row (32 floats each)
    auto load = [&](int kt, int buf) {
        const float* Ar = A + (long)(m0 + tid) * K + kt * 32;
        const float* Br = Wt + (long)(n0 + tid) * K + kt * 32;
        float* dA = As + buf * 128 * GPAD + tid * GPAD;
        float* dB = Bs + buf * 128 * GPAD + tid * GPAD;
#pragma unroll
        for (int c4 = 0; c4 < 8; c4++) {
            float4 v = *(const float4*)(Ar + c4 * 4);
            v.x = tf32r(v.x); v.y = tf32r(v.y); v.z = tf32r(v.z); v.w = tf32r(v.w);
            *(float4*)(dA + c4 * 4) = v;
            float4 w = *(const float4*)(Br + c4 * 4);
            w.x = tf32r(w.x); w.y = tf32r(w.y); w.z = tf32r(w.z); w.w = tf32r(w.w);
            *(float4*)(dB + c4 * 4) = w;
        }
    };

    load(0, 0);
    __syncthreads();

    for (int kt = 0; kt < nk; kt++) {
        int buf = kt & 1;
        if (kt + 1 < nk) load(kt + 1, buf ^ 1);

        const float* Ab = As + buf * 128 * GPAD;
        const float* Bb = Bs + buf * 128 * GPAD;
#pragma unroll
        for (int ks = 0; ks < 4; ks++) {
            int kb = ks * 8;
            uint32_t af[4][4], bf[8][2];
#pragma unroll
            for (int mt = 0; mt < 4; mt++) {
                int r = wm + mt * 16;
                af[mt][0] = fu(Ab[(r + g)     * GPAD + kb + t4]);
                af[mt][1] = fu(Ab[(r + g + 8) * GPAD + kb + t4]);
                af[mt][2] = fu(Ab[(r + g)     * GPAD + kb + t4 + 4]);
                af[mt][3] = fu(Ab[(r + g + 8) * GPAD + kb + t4 + 4]);
            }
#pragma unroll
            for (int nt = 0; nt < 8; nt++) {
                int cc = wn + nt * 8;
                bf[nt][0] = fu(Bb[(cc + g) * GPAD + kb + t4]);
                bf[nt][1] = fu(Bb[(cc + g) * GPAD + kb + t4 + 4]);
            }
#pragma unroll
            for (int mt = 0; mt < 4; mt++)
#pragma unroll
                for (int nt = 0; nt < 8; nt++)
                    mma8(c[mt][nt], af[mt], bf[nt]);
        }
        __syncthreads();
    }

    // Epilogue: bias + act, float2 stores
#pragma unroll
    for (int mt = 0; mt < 4; mt++) {
        int r0 = m0 + wm + mt * 16 + g;
#pragma unroll
        for (int nt = 0; nt < 8; nt++) {
            int col = n0 + wn + nt * 8 + 2 * t4;
            float2 bv = *(const float2*)(bias + col);
            float x0 = c[mt][nt][0] + bv.x;
            float x1 = c[mt][nt][1] + bv.y;
            float x2 = c[mt][nt][2] + bv.x;
            float x3 = c[mt][nt][3] + bv.y;
            if (ACT == 1) {
                x0 = fmaxf(x0, 0.f); x1 = fmaxf(x1, 0.f);
                x2 = fmaxf(x2, 0.f); x3 = fmaxf(x3, 0.f);
            }
            if (ACT == 2) {
                x0 = 1.f / (1.f + __expf(-x0)); x1 = 1.f / (1.f + __expf(-x1));
                x2 = 1.f / (1.f + __expf(-x2)); x3 = 1.f / (1.f + __expf(-x3));
            }
            *(float2*)(C + (long)r0 * N + col)       = make_float2(x0, x1);
            *(float2*)(C + (long)(r0 + 8) * N + col) = make_float2(x2, x3);
        }
    }
}

// ---------------------------------------------------------------------------
// Flash attention: SIMT QK^T (fp32 exact) + smem softmax + tf32 mma P@V.
// Per block: 128 query rows of one batch; key tiles of 64. 256 threads.
// ---------------------------------------------------------------------------
#define FA_BM 128
#define FA_BN 64
#define VSTR  136   // V smem row stride (floats): 136 % 32 = 8 -> conflict-free B frags
// floats: Qs 128*128, KVs max(64*128 swizzled K, 64*136 V) = 8704, Ssh 128*68, m/l/a 3*128
#define FA_SMEM_FLOATS (128*128 + 64*VSTR + 128*68 + 3*128)

__global__ __launch_bounds__(256, 1) void flash_attn_kernel(
    const float* __restrict__ Q, const float* __restrict__ K,
    const float* __restrict__ V, float* __restrict__ O)
{
    extern __shared__ float sm[];
    float* Qs  = sm;                    // swizzled [128][128]
    float* KVs = Qs + 128 * 128;        // K: swizzled 64x128 / V: [64][VSTR]
    float* Ssh = KVs + 64 * VSTR;       // [128][68]
    float* msh = Ssh + 128 * 68;
    float* lsh = msh + 128;
    float* ash = lsh + 128;

    const int tid = threadIdx.x;
    const int b   = blockIdx.y;
    const int m0  = blockIdx.x * FA_BM;

    const float* Qb = Q + ((long)b * N1 + m0) * LAT;
    const float* Kb = K + (long)b * N2 * LAT;
    const float* Vb = V + (long)b * N2 * LAT;

    // Load Q tile [128][128], swizzled
#pragma unroll
    for (int i = 0; i < 16; i++) {
        int idx = tid + i * 256;
        int r   = idx >> 5;
        int c4  = idx & 31;
        float4 v = *(const float4*)(Qb + r * LAT + c4 * 4);
        int sw = c4 ^ ((r >> 2) & 7);
        *(float4*)(Qs + r * 128 + sw * 4) = v;
    }
    if (tid < 128) { msh[tid] = -INFINITY; lsh[tid] = 0.f; }

    const int sty = tid >> 4, stx = tid & 15;   // S tile thread mapping

    // mma fragment mapping for P@V
    const int wid = tid >> 5, lane = tid & 31;
    const int g = lane >> 2, t4 = lane & 3;
    const int wm = (wid & 3) * 32;     // O rows: warp covers 32 rows (2 m-tiles)
    const int wn = (wid >> 2) * 64;    // O cols: warp covers 64 cols (8 n-tiles)

    float oc[2][8][4];
#pragma unroll
    for (int mt = 0; mt < 2; mt++)
#pragma unroll
        for (int nt = 0; nt < 8; nt++)
#pragma unroll
            for (int i = 0; i < 4; i++) oc[mt][nt][i] = 0.f;

    __syncthreads();

    for (int t0 = 0; t0 < N2; t0 += FA_BN) {
        // --- Load K tile [64][128], swizzled (stride 128) ---
#pragma unroll
        for (int i = 0; i < 8; i++) {
            int idx = tid + i * 256;
            int r   = idx >> 5;
            int c4  = idx & 31;
            float4 v = *(const float4*)(Kb + (t0 + r) * LAT + c4 * 4);
            int sw = c4 ^ ((r >> 2) & 7);
            *(float4*)(KVs + r * 128 + sw * 4) = v;
        }
        __syncthreads();

        // --- S = Q @ K^T (SIMT fp32, 8x4 per thread) ---
        float acc[8][4];
#pragma unroll
        for (int i = 0; i < 8; i++)
#pragma unroll
            for (int j = 0; j < 4; j++) acc[i][j] = 0.f;

#pragma unroll 4
        for (int k4 = 0; k4 < 32; k4++) {
            float4 a[8], bb[4];
#pragma unroll
            for (int i = 0; i < 8; i++) {
                int r = sty * 8 + i;
                a[i] = *(float4*)(Qs + r * 128 + ((k4 ^ ((r >> 2) & 7)) << 2));
            }
#pragma unroll
            for (int j = 0; j < 4; j++) {
                int cq = stx * 4 + j;
                bb[j] = *(float4*)(KVs + cq * 128 + ((k4 ^ ((cq >> 2) & 7)) << 2));
            }
#pragma unroll
            for (int i = 0; i < 8; i++)
#pragma unroll
                for (int j = 0; j < 4; j++) {
                    acc[i][j] += a[i].x * bb[j].x;
                    acc[i][j] += a[i].y * bb[j].y;
                    acc[i][j] += a[i].z * bb[j].z;
                    acc[i][j] += a[i].w * bb[j].w;
                }
        }

#pragma unroll
        for (int i = 0; i < 8; i++)
            *(float4*)(Ssh + (sty * 8 + i) * 68 + stx * 4) =
                make_float4(acc[i][0], acc[i][1], acc[i][2], acc[i][3]);
        __syncthreads();   // KVs free; Ssh complete

        // --- Load V tile [64][VSTR] natural layout ---
#pragma unroll
        for (int i = 0; i < 8; i++) {
            int idx = tid + i * 256;
            int r   = idx >> 5;
            int c4  = idx & 31;
            float4 v = *(const float4*)(Vb + (t0 + r) * LAT + c4 * 4);
            v.x = tf32r(v.x); v.y = tf32r(v.y); v.z = tf32r(v.z); v.w = tf32r(v.w);
            *(float4*)(KVs + r * VSTR + c4 * 4) = v;
        }

        // --- Online softmax rows (threads 0..127), P rounded to tf32 ---
        if (tid < 128) {
            float mold = msh[tid];
            float mnew = mold;
            float* srow = Ssh + tid * 68;
#pragma unroll
            for (int j = 0; j < 64; j++) mnew = fmaxf(mnew, srow[j]);
            float alpha = __expf(mold - mnew);
            float lsum = 0.f;
#pragma unroll
            for (int j = 0; j < 64; j++) {
                float e = tf32r(__expf(srow[j] - mnew));
                srow[j] = e;
                lsum += e;
            }
            lsh[tid] = lsh[tid] * alpha + lsum;
            msh[tid] = mnew;
            ash[tid] = alpha;
        }
        __syncthreads();

        // --- O = O*alpha + P @ V via tf32 mma (k=64, 8 ksteps) ---
#pragma unroll
        for (int mt = 0; mt < 2; mt++) {
            float al0 = ash[wm + mt * 16 + g];
            float al1 = ash[wm + mt * 16 + 8 + g];
#pragma unroll
            for (int nt = 0; nt < 8; nt++) {
                oc[mt][nt][0] *= al0; oc[mt][nt][1] *= al0;
                oc[mt][nt][2] *= al1; oc[mt][nt][3] *= al1;
            }
        }
#pragma unroll
        for (int ks = 0; ks < 8; ks++) {
            int kb = ks * 8;
            uint32_t af[2][4], bf[8][2];
#pragma unroll
            for (int mt = 0; mt < 2; mt++) {
                int r = wm + mt * 16;
                af[mt][0] = fu(Ssh[(r + g)     * 68 + kb + t4]);
                af[mt][1] = fu(Ssh[(r + g + 8) * 68 + kb + t4]);
                af[mt][2] = fu(Ssh[(r + g)     * 68 + kb + t4 + 4]);
                af[mt][3] = fu(Ssh[(r + g + 8) * 68 + kb + t4 + 4]);
            }
#pragma unroll
            for (int nt = 0; nt < 8; nt++) {
                int cc = wn + nt * 8;
                bf[nt][0] = fu(KVs[(kb + t4)     * VSTR + cc + g]);
                bf[nt][1] = fu(KVs[(kb + t4 + 4) * VSTR + cc + g]);
            }
#pragma unroll
            for (int mt = 0; mt < 2; mt++)
#pragma unroll
                for (int nt = 0; nt < 8; nt++)
                    mma8(oc[mt][nt], af[mt], bf[nt]);
        }
        __syncthreads();   // protect KVs/Ssh before next tile
    }

    // --- Epilogue: divide by l, write out (float2 per fragment row) ---
#pragma unroll
    for (int mt = 0; mt < 2; mt++) {
        int r0 = wm + mt * 16 + g;
        float inv0 = 1.f / lsh[r0];
        float inv1 = 1.f / lsh[r0 + 8];
        long row0 = (long)b * N1 + m0 + r0;
#pragma unroll
        for (int nt = 0; nt < 8; nt++) {
            int col = wn + nt * 8 + 2 * t4;
            *(float2*)(O + row0 * LAT + col) =
                make_float2(oc[mt][nt][0] * inv0, oc[mt][nt][1] * inv0);
            *(float2*)(O + (row0 + 8) * LAT + col) =
                make_float2(oc[mt][nt][2] * inv1, oc[mt][nt][3] * inv1);
        }
    }
}

// ---------------------------------------------------------------------------
// Host launcher
// ---------------------------------------------------------------------------
extern "C" void kernel_launch(void* const* d_in, const int* in_sizes, int n_in,
                              void* d_out, int out_size)
{
    const float* mainf = (const float*)d_in[0];
    const float* feat  = (const float*)d_in[1];
    const float* We1   = (const float*)d_in[2];
    const float* be1   = (const float*)d_in[3];
    const float* We2   = (const float*)d_in[4];
    const float* be2   = (const float*)d_in[5];
    const float* Wq    = (const float*)d_in[6];
    const float* bq    = (const float*)d_in[7];
    const float* Wk    = (const float*)d_in[8];
    const float* bk    = (const float*)d_in[9];
    const float* Wv    = (const float*)d_in[10];
    const float* bv    = (const float*)d_in[11];
    const float* Wd1   = (const float*)d_in[12];
    const float* bd1   = (const float*)d_in[13];
    const float* Wd2   = (const float*)d_in[14];
    const float* bd2   = (const float*)d_in[15];
    float* out = (float*)d_out;

    float *p_mid, *p_m, *p_f, *p_q, *p_k, *p_v, *p_attn;
    float *wt_e1, *wt_e2, *wt_q, *wt_k, *wt_v, *wt_d1, *wt_d2;
    cudaGetSymbolAddress((void**)&p_mid,  g_mid);
    cudaGetSymbolAddress((void**)&p_m,    g_m);
    cudaGetSymbolAddress((void**)&p_f,    g_f);
    cudaGetSymbolAddress((void**)&p_q,    g_q);
    cudaGetSymbolAddress((void**)&p_k,    g_k);
    cudaGetSymbolAddress((void**)&p_v,    g_v);
    cudaGetSymbolAddress((void**)&p_attn, g_attn);
    cudaGetSymbolAddress((void**)&wt_e1, g_wt_e1);
    cudaGetSymbolAddress((void**)&wt_e2, g_wt_e2);
    cudaGetSymbolAddress((void**)&wt_q,  g_wt_q);
    cudaGetSymbolAddress((void**)&wt_k,  g_wt_k);
    cudaGetSymbolAddress((void**)&wt_v,  g_wt_v);
    cudaGetSymbolAddress((void**)&wt_d1, g_wt_d1);
    cudaGetSymbolAddress((void**)&wt_d2, g_wt_d2);

    const int fa_smem = FA_SMEM_FLOATS * sizeof(float);        // ~134 KB
    const int gm_smem = 2 * 2 * 128 * GPAD * sizeof(float);    // 73728 B
    cudaFuncSetAttribute(flash_attn_kernel,
                         cudaFuncAttributeMaxDynamicSharedMemorySize, fa_smem);
    cudaFuncSetAttribute(gemm_mma<0>, cudaFuncAttributeMaxDynamicSharedMemorySize, gm_smem);
    cudaFuncSetAttribute(gemm_mma<1>, cudaFuncAttributeMaxDynamicSharedMemorySize, gm_smem);
    cudaFuncSetAttribute(gemm_mma<2>, cudaFuncAttributeMaxDynamicSharedMemorySize, gm_smem);

    dim3 tb(32, 8);
    transpose_kernel<<<dim3(MID / 32, HH  / 32), tb>>>(We1, wt_e1, HH,  MID);
    transpose_kernel<<<dim3(LAT / 32, MID / 32), tb>>>(We2, wt_e2, MID, LAT);
    transpose_kernel<<<dim3(LAT / 32, LAT / 32), tb>>>(Wq,  wt_q,  LAT, LAT);
    transpose_kernel<<<dim3(LAT / 32, LAT / 32), tb>>>(Wk,  wt_k,  LAT, LAT);
    transpose_kernel<<<dim3(LAT / 32, LAT / 32), tb>>>(Wv,  wt_v,  LAT, LAT);
    transpose_kernel<<<dim3(MID / 32, LAT / 32), tb>>>(Wd1, wt_d1, LAT, MID);
    transpose_kernel<<<dim3(HH  / 32, MID / 32), tb>>>(Wd2, wt_d2, MID, HH);

    const int M = RTOT;
    // encode(main)
    gemm_mma<1><<<dim3(MID / 128, M / 128), 128, gm_smem>>>(mainf, wt_e1, be1, p_mid, M, MID, HH);
    gemm_mma<1><<<dim3(LAT / 128, M / 128), 128, gm_smem>>>(p_mid, wt_e2, be2, p_m,  M, LAT, MID);
    // encode(feature)
    gemm_mma<1><<<dim3(MID / 128, M / 128), 128, gm_smem>>>(feat,  wt_e1, be1, p_mid, M, MID, HH);
    gemm_mma<1><<<dim3(LAT / 128, M / 128), 128, gm_smem>>>(p_mid, wt_e2, be2, p_f,  M, LAT, MID);
    // q, k, v
    gemm_mma<0><<<dim3(LAT / 128, M / 128), 128, gm_smem>>>(p_m, wt_q, bq, p_q, M, LAT, LAT);
    gemm_mma<0><<<dim3(LAT / 128, M / 128), 128, gm_smem>>>(p_f, wt_k, bk, p_k, M, LAT, LAT);
    gemm_mma<0><<<dim3(LAT / 128, M / 128), 128, gm_smem>>>(p_f, wt_v, bv, p_v, M, LAT, LAT);
    // attention
    flash_attn_kernel<<<dim3(N1 / FA_BM, BB), 256, fa_smem>>>(p_q, p_k, p_v, p_attn);
    // decode
    gemm_mma<1><<<dim3(MID / 128, M / 128), 128, gm_smem>>>(p_attn, wt_d1, bd1, p_mid, M, MID, LAT);
    gemm_mma<2><<<dim3(HH  / 128, M / 128), 128, gm_smem>>>(p_mid,  wt_d2, bd2, out,  M, HH,  MID);
}

// round 7
// speedup vs baseline: 1.9129x; 1.3174x over previous
#include <cuda_runtime.h>
#include <math.h>
#include <cstdint>

// Problem dims
#define BB   16
#define N1   2048
#define N2   2048
#define HH   768
#define LAT  128
#define MID  256
#define RTOT (BB * N1)          // 32768 rows

// ---------------------------------------------------------------------------
// Scratch (device globals: allocation-free, graph-capturable)
// ---------------------------------------------------------------------------
__device__ float g_mid [RTOT * MID];
__device__ float g_m   [RTOT * LAT];
__device__ float g_f   [RTOT * LAT];
__device__ float g_q   [RTOT * LAT];
__device__ float g_k   [RTOT * LAT];
__device__ float g_v   [RTOT * LAT];
__device__ float g_attn[RTOT * LAT];
// Transposed weights [N, K] row-major
__device__ float g_wt_e1[MID * HH];
__device__ float g_wt_e2[LAT * MID];
__device__ float g_wt_q [LAT * LAT];
__device__ float g_wt_k [LAT * LAT];
__device__ float g_wt_v [LAT * LAT];
__device__ float g_wt_d1[MID * LAT];
__device__ float g_wt_d2[HH * MID];

// ---------------------------------------------------------------------------
// Helpers
// ---------------------------------------------------------------------------
__device__ __forceinline__ float tf32r(float x) {
    uint32_t u;
    asm("cvt.rna.tf32.f32 %0, %1;" : "=r"(u) : "f"(x));
    return __uint_as_float(u);
}
// D += A(16x8,row) * B(8x8,col)  tf32, fp32 accum
__device__ __forceinline__ void mma8(float c[4], const uint32_t a[4], const uint32_t b[2]) {
    asm volatile(
        "mma.sync.aligned.m16n8k8.row.col.f32.tf32.tf32.f32 "
        "{%0,%1,%2,%3}, {%4,%5,%6,%7}, {%8,%9}, {%0,%1,%2,%3};"
        : "+f"(c[0]), "+f"(c[1]), "+f"(c[2]), "+f"(c[3])
        : "r"(a[0]), "r"(a[1]), "r"(a[2]), "r"(a[3]), "r"(b[0]), "r"(b[1]));
}
__device__ __forceinline__ uint32_t fu(float x) { return __float_as_uint(x); }

// ---------------------------------------------------------------------------
// Fused weight transpose: all 7 weights in one launch.
// in [K, N] row-major -> out [N, K] row-major. 496 tiles of 32x32.
// ---------------------------------------------------------------------------
__global__ void transpose_all(
    const float* __restrict__ We1, float* __restrict__ wt_e1,
    const float* __restrict__ We2, float* __restrict__ wt_e2,
    const float* __restrict__ Wq,  float* __restrict__ wt_q,
    const float* __restrict__ Wk,  float* __restrict__ wt_k,
    const float* __restrict__ Wv,  float* __restrict__ wt_v,
    const float* __restrict__ Wd1, float* __restrict__ wt_d1,
    const float* __restrict__ Wd2, float* __restrict__ wt_d2)
{
    __shared__ float t[32][33];
    int idx = blockIdx.x;
    const float* in; float* out; int K, N, l;
    if (idx < 192)      { in = We1; out = wt_e1; K = HH;  N = MID; l = idx; }
    else if (idx < 224) { in = We2; out = wt_e2; K = MID; N = LAT; l = idx - 192; }
    else if (idx < 240) { in = Wq;  out = wt_q;  K = LAT; N = LAT; l = idx - 224; }
    else if (idx < 256) { in = Wk;  out = wt_k;  K = LAT; N = LAT; l = idx - 240; }
    else if (idx < 272) { in = Wv;  out = wt_v;  K = LAT; N = LAT; l = idx - 256; }
    else if (idx < 304) { in = Wd1; out = wt_d1; K = LAT; N = MID; l = idx - 272; }
    else                { in = Wd2; out = wt_d2; K = MID; N = HH;  l = idx - 304; }
    int tx = N >> 5;
    int nx = (l % tx) * 32, kx = (l / tx) * 32;
    int x = threadIdx.x, y = threadIdx.y;   // 32 x 8
#pragma unroll
    for (int i = 0; i < 32; i += 8)
        t[y + i][x] = in[(long)(kx + y + i) * N + nx + x];
    __syncthreads();
#pragma unroll
    for (int i = 0; i < 32; i += 8)
        out[(long)(nx + y + i) * K + kx + x] = t[x][y + i];
}

// ---------------------------------------------------------------------------
// tf32 mma GEMM: C[M,N] = act(A[M,K] @ Wt[N,K]^T + bias[N])
// CTA tile 128x128, 128 threads = 4 warps of 64x64, BK=32 double-buffered.
// ACT: 0=none, 1=relu, 2=sigmoid
// ---------------------------------------------------------------------------
#define GPAD 36

template <int ACT>
__global__ __launch_bounds__(128) void gemm_mma(
    const float* __restrict__ A, const float* __restrict__ Wt,
    const float* __restrict__ bias, float* __restrict__ C,
    int M, int N, int K)
{
    extern __shared__ float sm[];
    float* As = sm;                       // [2][128*GPAD]
    float* Bs = sm + 2 * 128 * GPAD;      // [2][128*GPAD]

    const int tid = threadIdx.x;
    const int wid = tid >> 5, lane = tid & 31;
    const int g = lane >> 2, t4 = lane & 3;
    const int wm = (wid & 1) * 64, wn = (wid >> 1) * 64;
    const int m0 = blockIdx.y * 128, n0 = blockIdx.x * 128;

    float c[4][8][4];
#pragma unroll
    for (int mt = 0; mt < 4; mt++)
#pragma unroll
        for (int nt = 0; nt < 8; nt++)
#pragma unroll
            for (int i = 0; i < 4; i++) c[mt][nt][i] = 0.f;

    const int nk = K >> 5;

    auto load = [&](int kt, int buf) {
        const float* Ar = A + (long)(m0 + tid) * K + kt * 32;
        const float* Br = Wt + (long)(n0 + tid) * K + kt * 32;
        float* dA = As + buf * 128 * GPAD + tid * GPAD;
        float* dB = Bs + buf * 128 * GPAD + tid * GPAD;
#pragma unroll
        for (int c4 = 0; c4 < 8; c4++) {
            float4 v = *(const float4*)(Ar + c4 * 4);
            v.x = tf32r(v.x); v.y = tf32r(v.y); v.z = tf32r(v.z); v.w = tf32r(v.w);
            *(float4*)(dA + c4 * 4) = v;
            float4 w = *(const float4*)(Br + c4 * 4);
            w.x = tf32r(w.x); w.y = tf32r(w.y); w.z = tf32r(w.z); w.w = tf32r(w.w);
            *(float4*)(dB + c4 * 4) = w;
        }
    };

    load(0, 0);
    __syncthreads();

    for (int kt = 0; kt < nk; kt++) {
        int buf = kt & 1;
        if (kt + 1 < nk) load(kt + 1, buf ^ 1);

        const float* Ab = As + buf * 128 * GPAD;
        const float* Bb = Bs + buf * 128 * GPAD;
#pragma unroll
        for (int ks = 0; ks < 4; ks++) {
            int kb = ks * 8;
            uint32_t af[4][4], bf[8][2];
#pragma unroll
            for (int mt = 0; mt < 4; mt++) {
                int r = wm + mt * 16;
                af[mt][0] = fu(Ab[(r + g)     * GPAD + kb + t4]);
                af[mt][1] = fu(Ab[(r + g + 8) * GPAD + kb + t4]);
                af[mt][2] = fu(Ab[(r + g)     * GPAD + kb + t4 + 4]);
                af[mt][3] = fu(Ab[(r + g + 8) * GPAD + kb + t4 + 4]);
            }
#pragma unroll
            for (int nt = 0; nt < 8; nt++) {
                int cc = wn + nt * 8;
                bf[nt][0] = fu(Bb[(cc + g) * GPAD + kb + t4]);
                bf[nt][1] = fu(Bb[(cc + g) * GPAD + kb + t4 + 4]);
            }
#pragma unroll
            for (int mt = 0; mt < 4; mt++)
#pragma unroll
                for (int nt = 0; nt < 8; nt++)
                    mma8(c[mt][nt], af[mt], bf[nt]);
        }
        __syncthreads();
    }

#pragma unroll
    for (int mt = 0; mt < 4; mt++) {
        int r0 = m0 + wm + mt * 16 + g;
#pragma unroll
        for (int nt = 0; nt < 8; nt++) {
            int col = n0 + wn + nt * 8 + 2 * t4;
            float2 bv = *(const float2*)(bias + col);
            float x0 = c[mt][nt][0] + bv.x;
            float x1 = c[mt][nt][1] + bv.y;
            float x2 = c[mt][nt][2] + bv.x;
            float x3 = c[mt][nt][3] + bv.y;
            if (ACT == 1) {
                x0 = fmaxf(x0, 0.f); x1 = fmaxf(x1, 0.f);
                x2 = fmaxf(x2, 0.f); x3 = fmaxf(x3, 0.f);
            }
            if (ACT == 2) {
                x0 = 1.f / (1.f + __expf(-x0)); x1 = 1.f / (1.f + __expf(-x1));
                x2 = 1.f / (1.f + __expf(-x2)); x3 = 1.f / (1.f + __expf(-x3));
            }
            *(float2*)(C + (long)r0 * N + col)       = make_float2(x0, x1);
            *(float2*)(C + (long)(r0 + 8) * N + col) = make_float2(x2, x3);
        }
    }
}

// ---------------------------------------------------------------------------
// Flash attention, full-mma: tf32 mma QK^T + smem softmax + tf32 mma P@V.
// Per block: 128 query rows of one batch; key tiles of 64. 256 threads.
// Q tile [128][QSTR], K tile [64][QSTR], V tile [64][VSTR], S [128][68].
// ---------------------------------------------------------------------------
#define FA_BM 128
#define FA_BN 64
#define QSTR  132   // 132 % 32 = 4 -> conflict-free scalar fragment loads
#define VSTR  136
#define FA_SMEM_FLOATS (128*QSTR + 64*VSTR + 128*68 + 3*128)

__global__ __launch_bounds__(256, 1) void flash_attn_kernel(
    const float* __restrict__ Q, const float* __restrict__ K,
    const float* __restrict__ V, float* __restrict__ O)
{
    extern __shared__ float sm[];
    float* Qs  = sm;                    // [128][QSTR] tf32-rounded
    float* KVs = Qs + 128 * QSTR;       // K: [64][QSTR] / V: [64][VSTR]
    float* Ssh = KVs + 64 * VSTR;       // [128][68]
    float* msh = Ssh + 128 * 68;
    float* lsh = msh + 128;
    float* ash = lsh + 128;

    const int tid = threadIdx.x;
    const int b   = blockIdx.y;
    const int m0  = blockIdx.x * FA_BM;

    const float* Qb = Q + ((long)b * N1 + m0) * LAT;
    const float* Kb = K + (long)b * N2 * LAT;
    const float* Vb = V + (long)b * N2 * LAT;

    const int wid = tid >> 5, lane = tid & 31;
    const int g = lane >> 2, t4 = lane & 3;
    const int qr0 = wid * 16;          // QK: warp covers 16 query rows x 64 keys
    const int wm = (wid & 3) * 32;     // PV: warp covers 32 rows x 64 cols
    const int wn = (wid >> 2) * 64;

    // Load Q tile, tf32-rounded
#pragma unroll
    for (int i = 0; i < 16; i++) {
        int idx = tid + i * 256;
        int r   = idx >> 5;
        int c4  = idx & 31;
        float4 v = *(const float4*)(Qb + r * LAT + c4 * 4);
        v.x = tf32r(v.x); v.y = tf32r(v.y); v.z = tf32r(v.z); v.w = tf32r(v.w);
        *(float4*)(Qs + r * QSTR + c4 * 4) = v;
    }
    if (tid < 128) { msh[tid] = -INFINITY; lsh[tid] = 0.f; }

    float oc[2][8][4];
#pragma unroll
    for (int mt = 0; mt < 2; mt++)
#pragma unroll
        for (int nt = 0; nt < 8; nt++)
#pragma unroll
            for (int i = 0; i < 4; i++) oc[mt][nt][i] = 0.f;

    __syncthreads();

    for (int t0 = 0; t0 < N2; t0 += FA_BN) {
        // --- Load K tile [64][QSTR], tf32-rounded ---
#pragma unroll
        for (int i = 0; i < 8; i++) {
            int idx = tid + i * 256;
            int r   = idx >> 5;
            int c4  = idx & 31;
            float4 v = *(const float4*)(Kb + (t0 + r) * LAT + c4 * 4);
            v.x = tf32r(v.x); v.y = tf32r(v.y); v.z = tf32r(v.z); v.w = tf32r(v.w);
            *(float4*)(KVs + r * QSTR + c4 * 4) = v;
        }
        __syncthreads();

        // --- S = Q @ K^T via tf32 mma: 16 rows x 64 keys per warp ---
        float c[8][4];
#pragma unroll
        for (int nt = 0; nt < 8; nt++)
#pragma unroll
            for (int i = 0; i < 4; i++) c[nt][i] = 0.f;

#pragma unroll
        for (int ks = 0; ks < 16; ks++) {
            int kb = ks * 8;
            uint32_t af[4], bf[8][2];
            af[0] = fu(Qs[(qr0 + g)     * QSTR + kb + t4]);
            af[1] = fu(Qs[(qr0 + g + 8) * QSTR + kb + t4]);
            af[2] = fu(Qs[(qr0 + g)     * QSTR + kb + t4 + 4]);
            af[3] = fu(Qs[(qr0 + g + 8) * QSTR + kb + t4 + 4]);
#pragma unroll
            for (int nt = 0; nt < 8; nt++) {
                int cc = nt * 8;
                bf[nt][0] = fu(KVs[(cc + g) * QSTR + kb + t4]);
                bf[nt][1] = fu(KVs[(cc + g) * QSTR + kb + t4 + 4]);
            }
#pragma unroll
            for (int nt = 0; nt < 8; nt++)
                mma8(c[nt], af, bf[nt]);
        }

        // --- Stage S fragments to Ssh ---
#pragma unroll
        for (int nt = 0; nt < 8; nt++) {
            int col = nt * 8 + 2 * t4;
            *(float2*)(Ssh + (qr0 + g)     * 68 + col) = make_float2(c[nt][0], c[nt][1]);
            *(float2*)(Ssh + (qr0 + g + 8) * 68 + col) = make_float2(c[nt][2], c[nt][3]);
        }
        __syncthreads();   // K consumed; S complete

        // --- Load V tile [64][VSTR], tf32-rounded (overwrites K) ---
#pragma unroll
        for (int i = 0; i < 8; i++) {
            int idx = tid + i * 256;
            int r   = idx >> 5;
            int c4  = idx & 31;
            float4 v = *(const float4*)(Vb + (t0 + r) * LAT + c4 * 4);
            v.x = tf32r(v.x); v.y = tf32r(v.y); v.z = tf32r(v.z); v.w = tf32r(v.w);
            *(float4*)(KVs + r * VSTR + c4 * 4) = v;
        }

        // --- Online softmax rows (threads 0..127), P rounded to tf32 ---
        if (tid < 128) {
            float mold = msh[tid];
            float mnew = mold;
            float* srow = Ssh + tid * 68;
#pragma unroll
            for (int j = 0; j < 64; j++) mnew = fmaxf(mnew, srow[j]);
            float alpha = __expf(mold - mnew);
            float lsum = 0.f;
#pragma unroll
            for (int j = 0; j < 64; j++) {
                float e = tf32r(__expf(srow[j] - mnew));
                srow[j] = e;
                lsum += e;
            }
            lsh[tid] = lsh[tid] * alpha + lsum;
            msh[tid] = mnew;
            ash[tid] = alpha;
        }
        __syncthreads();

        // --- O = O*alpha + P @ V via tf32 mma ---
#pragma unroll
        for (int mt = 0; mt < 2; mt++) {
            float al0 = ash[wm + mt * 16 + g];
            float al1 = ash[wm + mt * 16 + 8 + g];
#pragma unroll
            for (int nt = 0; nt < 8; nt++) {
                oc[mt][nt][0] *= al0; oc[mt][nt][1] *= al0;
                oc[mt][nt][2] *= al1; oc[mt][nt][3] *= al1;
            }
        }
#pragma unroll
        for (int ks = 0; ks < 8; ks++) {
            int kb = ks * 8;
            uint32_t af[2][4], bf[8][2];
#pragma unroll
            for (int mt = 0; mt < 2; mt++) {
                int r = wm + mt * 16;
                af[mt][0] = fu(Ssh[(r + g)     * 68 + kb + t4]);
                af[mt][1] = fu(Ssh[(r + g + 8) * 68 + kb + t4]);
                af[mt][2] = fu(Ssh[(r + g)     * 68 + kb + t4 + 4]);
                af[mt][3] = fu(Ssh[(r + g + 8) * 68 + kb + t4 + 4]);
            }
#pragma unroll
            for (int nt = 0; nt < 8; nt++) {
                int cc = wn + nt * 8;
                bf[nt][0] = fu(KVs[(kb + t4)     * VSTR + cc + g]);
                bf[nt][1] = fu(KVs[(kb + t4 + 4) * VSTR + cc + g]);
            }
#pragma unroll
            for (int mt = 0; mt < 2; mt++)
#pragma unroll
                for (int nt = 0; nt < 8; nt++)
                    mma8(oc[mt][nt], af[mt], bf[nt]);
        }
        __syncthreads();
    }

    // --- Epilogue: divide by l, write out ---
#pragma unroll
    for (int mt = 0; mt < 2; mt++) {
        int r0 = wm + mt * 16 + g;
        float inv0 = 1.f / lsh[r0];
        float inv1 = 1.f / lsh[r0 + 8];
        long row0 = (long)b * N1 + m0 + r0;
#pragma unroll
        for (int nt = 0; nt < 8; nt++) {
            int col = wn + nt * 8 + 2 * t4;
            *(float2*)(O + row0 * LAT + col) =
                make_float2(oc[mt][nt][0] * inv0, oc[mt][nt][1] * inv0);
            *(float2*)(O + (row0 + 8) * LAT + col) =
                make_float2(oc[mt][nt][2] * inv1, oc[mt][nt][3] * inv1);
        }
    }
}

// ---------------------------------------------------------------------------
// Host launcher
// ---------------------------------------------------------------------------
extern "C" void kernel_launch(void* const* d_in, const int* in_sizes, int n_in,
                              void* d_out, int out_size)
{
    const float* mainf = (const float*)d_in[0];
    const float* feat  = (const float*)d_in[1];
    const float* We1   = (const float*)d_in[2];
    const float* be1   = (const float*)d_in[3];
    const float* We2   = (const float*)d_in[4];
    const float* be2   = (const float*)d_in[5];
    const float* Wq    = (const float*)d_in[6];
    const float* bq    = (const float*)d_in[7];
    const float* Wk    = (const float*)d_in[8];
    const float* bk    = (const float*)d_in[9];
    const float* Wv    = (const float*)d_in[10];
    const float* bv    = (const float*)d_in[11];
    const float* Wd1   = (const float*)d_in[12];
    const float* bd1   = (const float*)d_in[13];
    const float* Wd2   = (const float*)d_in[14];
    const float* bd2   = (const float*)d_in[15];
    float* out = (float*)d_out;

    float *p_mid, *p_m, *p_f, *p_q, *p_k, *p_v, *p_attn;
    float *wt_e1, *wt_e2, *wt_q, *wt_k, *wt_v, *wt_d1, *wt_d2;
    cudaGetSymbolAddress((void**)&p_mid,  g_mid);
    cudaGetSymbolAddress((void**)&p_m,    g_m);
    cudaGetSymbolAddress((void**)&p_f,    g_f);
    cudaGetSymbolAddress((void**)&p_q,    g_q);
    cudaGetSymbolAddress((void**)&p_k,    g_k);
    cudaGetSymbolAddress((void**)&p_v,    g_v);
    cudaGetSymbolAddress((void**)&p_attn, g_attn);
    cudaGetSymbolAddress((void**)&wt_e1, g_wt_e1);
    cudaGetSymbolAddress((void**)&wt_e2, g_wt_e2);
    cudaGetSymbolAddress((void**)&wt_q,  g_wt_q);
    cudaGetSymbolAddress((void**)&wt_k,  g_wt_k);
    cudaGetSymbolAddress((void**)&wt_v,  g_wt_v);
    cudaGetSymbolAddress((void**)&wt_d1, g_wt_d1);
    cudaGetSymbolAddress((void**)&wt_d2, g_wt_d2);

    const int fa_smem = FA_SMEM_FLOATS * sizeof(float);        // ~138.8 KB
    const int gm_smem = 2 * 2 * 128 * GPAD * sizeof(float);    // 73728 B
    cudaFuncSetAttribute(flash_attn_kernel,
                         cudaFuncAttributeMaxDynamicSharedMemorySize, fa_smem);
    cudaFuncSetAttribute(gemm_mma<0>, cudaFuncAttributeMaxDynamicSharedMemorySize, gm_smem);
    cudaFuncSetAttribute(gemm_mma<1>, cudaFuncAttributeMaxDynamicSharedMemorySize, gm_smem);
    cudaFuncSetAttribute(gemm_mma<2>, cudaFuncAttributeMaxDynamicSharedMemorySize, gm_smem);

    transpose_all<<<496, dim3(32, 8)>>>(We1, wt_e1, We2, wt_e2, Wq, wt_q,
                                        Wk, wt_k, Wv, wt_v, Wd1, wt_d1, Wd2, wt_d2);

    const int M = RTOT;
    // encode(main)
    gemm_mma<1><<<dim3(MID / 128, M / 128), 128, gm_smem>>>(mainf, wt_e1, be1, p_mid, M, MID, HH);
    gemm_mma<1><<<dim3(LAT / 128, M / 128), 128, gm_smem>>>(p_mid, wt_e2, be2, p_m,  M, LAT, MID);
    // encode(feature)
    gemm_mma<1><<<dim3(MID / 128, M / 128), 128, gm_smem>>>(feat,  wt_e1, be1, p_mid, M, MID, HH);
    gemm_mma<1><<<dim3(LAT / 128, M / 128), 128, gm_smem>>>(p_mid, wt_e2, be2, p_f,  M, LAT, MID);
    // q, k, v
    gemm_mma<0><<<dim3(LAT / 128, M / 128), 128, gm_smem>>>(p_m, wt_q, bq, p_q, M, LAT, LAT);
    gemm_mma<0><<<dim3(LAT / 128, M / 128), 128, gm_smem>>>(p_f, wt_k, bk, p_k, M, LAT, LAT);
    gemm_mma<0><<<dim3(LAT / 128, M / 128), 128, gm_smem>>>(p_f, wt_v, bv, p_v, M, LAT, LAT);
    // attention
    flash_attn_kernel<<<dim3(N1 / FA_BM, BB), 256, fa_smem>>>(p_q, p_k, p_v, p_attn);
    // decode
    gemm_mma<1><<<dim3(MID / 128, M / 128), 128, gm_smem>>>(p_attn, wt_d1, bd1, p_mid, M, MID, LAT);
    gemm_mma<2><<<dim3(HH  / 128, M / 128), 128, gm_smem>>>(p_mid,  wt_d2, bd2, out,  M, HH,  MID);
}

// round 8
// speedup vs baseline: 2.4768x; 1.2948x over previous
#include <cuda_runtime.h>
#include <math.h>
#include <cstdint>

// Problem dims
#define BB   16
#define N1   2048
#define N2   2048
#define HH   768
#define LAT  128
#define MID  256
#define RTOT (BB * N1)          // 32768 rows

// ---------------------------------------------------------------------------
// Scratch (device globals: allocation-free, graph-capturable)
// ---------------------------------------------------------------------------
__device__ float g_mid [RTOT * MID];
__device__ float g_m   [RTOT * LAT];
__device__ float g_f   [RTOT * LAT];
__device__ float g_q   [RTOT * LAT];
__device__ float g_k   [RTOT * LAT];
__device__ float g_v   [RTOT * LAT];
__device__ float g_attn[RTOT * LAT];
// Transposed weights [N, K] row-major
__device__ float g_wt_e1[MID * HH];
__device__ float g_wt_e2[LAT * MID];
__device__ float g_wt_q [LAT * LAT];
__device__ float g_wt_k [LAT * LAT];
__device__ float g_wt_v [LAT * LAT];
__device__ float g_wt_d1[MID * LAT];
__device__ float g_wt_d2[HH * MID];

// ---------------------------------------------------------------------------
// Helpers
// ---------------------------------------------------------------------------
__device__ __forceinline__ float tf32r(float x) {
    uint32_t u;
    asm("cvt.rna.tf32.f32 %0, %1;" : "=r"(u) : "f"(x));
    return __uint_as_float(u);
}
// D += A(16x8,row) * B(8x8,col)  tf32, fp32 accum
__device__ __forceinline__ void mma8(float c[4], const uint32_t a[4], const uint32_t b[2]) {
    asm volatile(
        "mma.sync.aligned.m16n8k8.row.col.f32.tf32.tf32.f32 "
        "{%0,%1,%2,%3}, {%4,%5,%6,%7}, {%8,%9}, {%0,%1,%2,%3};"
        : "+f"(c[0]), "+f"(c[1]), "+f"(c[2]), "+f"(c[3])
        : "r"(a[0]), "r"(a[1]), "r"(a[2]), "r"(a[3]), "r"(b[0]), "r"(b[1]));
}
__device__ __forceinline__ uint32_t fu(float x) { return __float_as_uint(x); }
__device__ __forceinline__ uint32_t smem_u32(const void* p) {
    uint32_t a;
    asm("{ .reg .u64 t; cvta.to.shared.u64 t, %1; cvt.u32.u64 %0, t; }"
        : "=r"(a) : "l"(p));
    return a;
}
// Four 8x8 b16 matrices; for fp32 data each lane receives one whole fp32.
__device__ __forceinline__ void ldsm4(uint32_t& r0, uint32_t& r1, uint32_t& r2,
                                      uint32_t& r3, uint32_t addr) {
    asm volatile("ldmatrix.sync.aligned.m8n8.x4.shared.b16 {%0,%1,%2,%3}, [%4];"
                 : "=r"(r0), "=r"(r1), "=r"(r2), "=r"(r3) : "r"(addr));
}

// ---------------------------------------------------------------------------
// Fused weight transpose: all 7 weights in one launch.
// ---------------------------------------------------------------------------
__global__ void transpose_all(
    const float* __restrict__ We1, float* __restrict__ wt_e1,
    const float* __restrict__ We2, float* __restrict__ wt_e2,
    const float* __restrict__ Wq,  float* __restrict__ wt_q,
    const float* __restrict__ Wk,  float* __restrict__ wt_k,
    const float* __restrict__ Wv,  float* __restrict__ wt_v,
    const float* __restrict__ Wd1, float* __restrict__ wt_d1,
    const float* __restrict__ Wd2, float* __restrict__ wt_d2)
{
    __shared__ float t[32][33];
    int idx = blockIdx.x;
    const float* in; float* out; int K, N, l;
    if (idx < 192)      { in = We1; out = wt_e1; K = HH;  N = MID; l = idx; }
    else if (idx < 224) { in = We2; out = wt_e2; K = MID; N = LAT; l = idx - 192; }
    else if (idx < 240) { in = Wq;  out = wt_q;  K = LAT; N = LAT; l = idx - 224; }
    else if (idx < 256) { in = Wk;  out = wt_k;  K = LAT; N = LAT; l = idx - 240; }
    else if (idx < 272) { in = Wv;  out = wt_v;  K = LAT; N = LAT; l = idx - 256; }
    else if (idx < 304) { in = Wd1; out = wt_d1; K = LAT; N = MID; l = idx - 272; }
    else                { in = Wd2; out = wt_d2; K = MID; N = HH;  l = idx - 304; }
    int tx = N >> 5;
    int nx = (l % tx) * 32, kx = (l / tx) * 32;
    int x = threadIdx.x, y = threadIdx.y;   // 32 x 8
#pragma unroll
    for (int i = 0; i < 32; i += 8)
        t[y + i][x] = in[(long)(kx + y + i) * N + nx + x];
    __syncthreads();
#pragma unroll
    for (int i = 0; i < 32; i += 8)
        out[(long)(nx + y + i) * K + kx + x] = t[x][y + i];
}

// ---------------------------------------------------------------------------
// tf32 mma GEMM v2: C[M,N] = act(A[M,K] @ Wt[N,K]^T + bias[N])
// CTA 128x128, 256 threads = 8 warps of 32x64, BK=32 double-buffered,
// ldmatrix.x4 fragment loads. ACT: 0=none, 1=relu, 2=sigmoid
// ---------------------------------------------------------------------------
#define GPAD 36

template <int ACT>
__global__ __launch_bounds__(256, 2) void gemm_mma(
    const float* __restrict__ A, const float* __restrict__ Wt,
    const float* __restrict__ bias, float* __restrict__ C,
    int M, int N, int K)
{
    extern __shared__ float sm[];
    float* As = sm;                       // [2][128*GPAD]
    float* Bs = sm + 2 * 128 * GPAD;      // [2][128*GPAD]

    const int tid = threadIdx.x;
    const int wid = tid >> 5, lane = tid & 31;
    const int g = lane >> 2, t4 = lane & 3;
    const int wm = (wid & 3) * 32;        // warp rows (2 m-tiles of 16)
    const int wn = (wid >> 2) * 64;       // warp cols (8 n-tiles of 8)
    const int m0 = blockIdx.y * 128, n0 = blockIdx.x * 128;

    float c[2][8][4];
#pragma unroll
    for (int mt = 0; mt < 2; mt++)
#pragma unroll
        for (int nt = 0; nt < 8; nt++)
#pragma unroll
            for (int i = 0; i < 4; i++) c[mt][nt][i] = 0.f;

    const int nk = K >> 5;

    // ldmatrix lane addressing
    const int mat = lane >> 3, rowin = lane & 7;
    const uint32_t BUFB = 128 * GPAD * 4;
    // A matrices: 0: rows 0-7 kLo, 1: rows 8-15 kLo, 2: rows 0-7 kHi, 3: rows 8-15 kHi
    uint32_t aaddr = smem_u32(As)
        + ((uint32_t)((wm + (mat & 1) * 8 + rowin) * GPAD + (mat >> 1) * 4) << 2);
    // B matrices: 0: n 0-7 kLo, 1: n 0-7 kHi, 2: n 8-15 kLo, 3: n 8-15 kHi
    uint32_t baddr = smem_u32(Bs)
        + ((uint32_t)((wn + (mat >> 1) * 8 + rowin) * GPAD + (mat & 1) * 4) << 2);

    // loader: thread loads 16 floats of A and 16 of B (half a 32-float row)
    auto load = [&](int kt, int buf) {
        int r = tid >> 1, h = (tid & 1) * 16;
        const float* Ar = A + (long)(m0 + r) * K + kt * 32 + h;
        const float* Br = Wt + (long)(n0 + r) * K + kt * 32 + h;
        float* dA = As + buf * 128 * GPAD + r * GPAD + h;
        float* dB = Bs + buf * 128 * GPAD + r * GPAD + h;
#pragma unroll
        for (int c4 = 0; c4 < 4; c4++) {
            float4 v = *(const float4*)(Ar + c4 * 4);
            v.x = tf32r(v.x); v.y = tf32r(v.y); v.z = tf32r(v.z); v.w = tf32r(v.w);
            *(float4*)(dA + c4 * 4) = v;
            float4 w = *(const float4*)(Br + c4 * 4);
            w.x = tf32r(w.x); w.y = tf32r(w.y); w.z = tf32r(w.z); w.w = tf32r(w.w);
            *(float4*)(dB + c4 * 4) = w;
        }
    };

    load(0, 0);
    __syncthreads();

    for (int kt = 0; kt < nk; kt++) {
        int buf = kt & 1;
        if (kt + 1 < nk) load(kt + 1, buf ^ 1);

        uint32_t ab = aaddr + buf * BUFB;
        uint32_t bb = baddr + buf * BUFB;
#pragma unroll
        for (int ks = 0; ks < 4; ks++) {
            uint32_t af[2][4], bf[8][2];
            ldsm4(af[0][0], af[0][1], af[0][2], af[0][3], ab + ks * 32);
            ldsm4(af[1][0], af[1][1], af[1][2], af[1][3],
                  ab + 16 * GPAD * 4 + ks * 32);
#pragma unroll
            for (int p = 0; p < 4; p++)
                ldsm4(bf[2 * p][0], bf[2 * p][1], bf[2 * p + 1][0], bf[2 * p + 1][1],
                      bb + p * 16 * GPAD * 4 + ks * 32);
#pragma unroll
            for (int mt = 0; mt < 2; mt++)
#pragma unroll
                for (int nt = 0; nt < 8; nt++)
                    mma8(c[mt][nt], af[mt], bf[nt]);
        }
        __syncthreads();
    }

    // Epilogue: bias + act
#pragma unroll
    for (int mt = 0; mt < 2; mt++) {
        int r0 = m0 + wm + mt * 16 + g;
#pragma unroll
        for (int nt = 0; nt < 8; nt++) {
            int col = n0 + wn + nt * 8 + 2 * t4;
            float2 bv = *(const float2*)(bias + col);
            float x0 = c[mt][nt][0] + bv.x;
            float x1 = c[mt][nt][1] + bv.y;
            float x2 = c[mt][nt][2] + bv.x;
            float x3 = c[mt][nt][3] + bv.y;
            if (ACT == 1) {
                x0 = fmaxf(x0, 0.f); x1 = fmaxf(x1, 0.f);
                x2 = fmaxf(x2, 0.f); x3 = fmaxf(x3, 0.f);
            }
            if (ACT == 2) {
                x0 = 1.f / (1.f + __expf(-x0)); x1 = 1.f / (1.f + __expf(-x1));
                x2 = 1.f / (1.f + __expf(-x2)); x3 = 1.f / (1.f + __expf(-x3));
            }
            *(float2*)(C + (long)r0 * N + col)       = make_float2(x0, x1);
            *(float2*)(C + (long)(r0 + 8) * N + col) = make_float2(x2, x3);
        }
    }
}

// ---------------------------------------------------------------------------
// Flash attention (identical to passing round-7 kernel)
// ---------------------------------------------------------------------------
#define FA_BM 128
#define FA_BN 64
#define QSTR  132
#define VSTR  136
#define FA_SMEM_FLOATS (128*QSTR + 64*VSTR + 128*68 + 3*128)

__global__ __launch_bounds__(256, 1) void flash_attn_kernel(
    const float* __restrict__ Q, const float* __restrict__ K,
    const float* __restrict__ V, float* __restrict__ O)
{
    extern __shared__ float sm[];
    float* Qs  = sm;
    float* KVs = Qs + 128 * QSTR;
    float* Ssh = KVs + 64 * VSTR;
    float* msh = Ssh + 128 * 68;
    float* lsh = msh + 128;
    float* ash = lsh + 128;

    const int tid = threadIdx.x;
    const int b   = blockIdx.y;
    const int m0  = blockIdx.x * FA_BM;

    const float* Qb = Q + ((long)b * N1 + m0) * LAT;
    const float* Kb = K + (long)b * N2 * LAT;
    const float* Vb = V + (long)b * N2 * LAT;

    const int wid = tid >> 5, lane = tid & 31;
    const int g = lane >> 2, t4 = lane & 3;
    const int qr0 = wid * 16;
    const int wm = (wid & 3) * 32;
    const int wn = (wid >> 2) * 64;

#pragma unroll
    for (int i = 0; i < 16; i++) {
        int idx = tid + i * 256;
        int r   = idx >> 5;
        int c4  = idx & 31;
        float4 v = *(const float4*)(Qb + r * LAT + c4 * 4);
        v.x = tf32r(v.x); v.y = tf32r(v.y); v.z = tf32r(v.z); v.w = tf32r(v.w);
        *(float4*)(Qs + r * QSTR + c4 * 4) = v;
    }
    if (tid < 128) { msh[tid] = -INFINITY; lsh[tid] = 0.f; }

    float oc[2][8][4];
#pragma unroll
    for (int mt = 0; mt < 2; mt++)
#pragma unroll
        for (int nt = 0; nt < 8; nt++)
#pragma unroll
            for (int i = 0; i < 4; i++) oc[mt][nt][i] = 0.f;

    __syncthreads();

    for (int t0 = 0; t0 < N2; t0 += FA_BN) {
#pragma unroll
        for (int i = 0; i < 8; i++) {
            int idx = tid + i * 256;
            int r   = idx >> 5;
            int c4  = idx & 31;
            float4 v = *(const float4*)(Kb + (t0 + r) * LAT + c4 * 4);
            v.x = tf32r(v.x); v.y = tf32r(v.y); v.z = tf32r(v.z); v.w = tf32r(v.w);
            *(float4*)(KVs + r * QSTR + c4 * 4) = v;
        }
        __syncthreads();

        float c[8][4];
#pragma unroll
        for (int nt = 0; nt < 8; nt++)
#pragma unroll
            for (int i = 0; i < 4; i++) c[nt][i] = 0.f;

#pragma unroll
        for (int ks = 0; ks < 16; ks++) {
            int kb = ks * 8;
            uint32_t af[4], bf[8][2];
            af[0] = fu(Qs[(qr0 + g)     * QSTR + kb + t4]);
            af[1] = fu(Qs[(qr0 + g + 8) * QSTR + kb + t4]);
            af[2] = fu(Qs[(qr0 + g)     * QSTR + kb + t4 + 4]);
            af[3] = fu(Qs[(qr0 + g + 8) * QSTR + kb + t4 + 4]);
#pragma unroll
            for (int nt = 0; nt < 8; nt++) {
                int cc = nt * 8;
                bf[nt][0] = fu(KVs[(cc + g) * QSTR + kb + t4]);
                bf[nt][1] = fu(KVs[(cc + g) * QSTR + kb + t4 + 4]);
            }
#pragma unroll
            for (int nt = 0; nt < 8; nt++)
                mma8(c[nt], af, bf[nt]);
        }

#pragma unroll
        for (int nt = 0; nt < 8; nt++) {
            int col = nt * 8 + 2 * t4;
            *(float2*)(Ssh + (qr0 + g)     * 68 + col) = make_float2(c[nt][0], c[nt][1]);
            *(float2*)(Ssh + (qr0 + g + 8) * 68 + col) = make_float2(c[nt][2], c[nt][3]);
        }
        __syncthreads();

#pragma unroll
        for (int i = 0; i < 8; i++) {
            int idx = tid + i * 256;
            int r   = idx >> 5;
            int c4  = idx & 31;
            float4 v = *(const float4*)(Vb + (t0 + r) * LAT + c4 * 4);
            v.x = tf32r(v.x); v.y = tf32r(v.y); v.z = tf32r(v.z); v.w = tf32r(v.w);
            *(float4*)(KVs + r * VSTR + c4 * 4) = v;
        }

        if (tid < 128) {
            float mold = msh[tid];
            float mnew = mold;
            float* srow = Ssh + tid * 68;
#pragma unroll
            for (int j = 0; j < 64; j++) mnew = fmaxf(mnew, srow[j]);
            float alpha = __expf(mold - mnew);
            float lsum = 0.f;
#pragma unroll
            for (int j = 0; j < 64; j++) {
                float e = tf32r(__expf(srow[j] - mnew));
                srow[j] = e;
                lsum += e;
            }
            lsh[tid] = lsh[tid] * alpha + lsum;
            msh[tid] = mnew;
            ash[tid] = alpha;
        }
        __syncthreads();

#pragma unroll
        for (int mt = 0; mt < 2; mt++) {
            float al0 = ash[wm + mt * 16 + g];
            float al1 = ash[wm + mt * 16 + 8 + g];
#pragma unroll
            for (int nt = 0; nt < 8; nt++) {
                oc[mt][nt][0] *= al0; oc[mt][nt][1] *= al0;
                oc[mt][nt][2] *= al1; oc[mt][nt][3] *= al1;
            }
        }
#pragma unroll
        for (int ks = 0; ks < 8; ks++) {
            int kb = ks * 8;
            uint32_t af[2][4], bf[8][2];
#pragma unroll
            for (int mt = 0; mt < 2; mt++) {
                int r = wm + mt * 16;
                af[mt][0] = fu(Ssh[(r + g)     * 68 + kb + t4]);
                af[mt][1] = fu(Ssh[(r + g + 8) * 68 + kb + t4]);
                af[mt][2] = fu(Ssh[(r + g)     * 68 + kb + t4 + 4]);
                af[mt][3] = fu(Ssh[(r + g + 8) * 68 + kb + t4 + 4]);
            }
#pragma unroll
            for (int nt = 0; nt < 8; nt++) {
                int cc = wn + nt * 8;
                bf[nt][0] = fu(KVs[(kb + t4)     * VSTR + cc + g]);
                bf[nt][1] = fu(KVs[(kb + t4 + 4) * VSTR + cc + g]);
            }
#pragma unroll
            for (int mt = 0; mt < 2; mt++)
#pragma unroll
                for (int nt = 0; nt < 8; nt++)
                    mma8(oc[mt][nt], af[mt], bf[nt]);
        }
        __syncthreads();
    }

#pragma unroll
    for (int mt = 0; mt < 2; mt++) {
        int r0 = wm + mt * 16 + g;
        float inv0 = 1.f / lsh[r0];
        float inv1 = 1.f / lsh[r0 + 8];
        long row0 = (long)b * N1 + m0 + r0;
#pragma unroll
        for (int nt = 0; nt < 8; nt++) {
            int col = wn + nt * 8 + 2 * t4;
            *(float2*)(O + row0 * LAT + col) =
                make_float2(oc[mt][nt][0] * inv0, oc[mt][nt][1] * inv0);
            *(float2*)(O + (row0 + 8) * LAT + col) =
                make_float2(oc[mt][nt][2] * inv1, oc[mt][nt][3] * inv1);
        }
    }
}

// ---------------------------------------------------------------------------
// Host launcher
// ---------------------------------------------------------------------------
extern "C" void kernel_launch(void* const* d_in, const int* in_sizes, int n_in,
                              void* d_out, int out_size)
{
    const float* mainf = (const float*)d_in[0];
    const float* feat  = (const float*)d_in[1];
    const float* We1   = (const float*)d_in[2];
    const float* be1   = (const float*)d_in[3];
    const float* We2   = (const float*)d_in[4];
    const float* be2   = (const float*)d_in[5];
    const float* Wq    = (const float*)d_in[6];
    const float* bq    = (const float*)d_in[7];
    const float* Wk    = (const float*)d_in[8];
    const float* bk    = (const float*)d_in[9];
    const float* Wv    = (const float*)d_in[10];
    const float* bv    = (const float*)d_in[11];
    const float* Wd1   = (const float*)d_in[12];
    const float* bd1   = (const float*)d_in[13];
    const float* Wd2   = (const float*)d_in[14];
    const float* bd2   = (const float*)d_in[15];
    float* out = (float*)d_out;

    float *p_mid, *p_m, *p_f, *p_q, *p_k, *p_v, *p_attn;
    float *wt_e1, *wt_e2, *wt_q, *wt_k, *wt_v, *wt_d1, *wt_d2;
    cudaGetSymbolAddress((void**)&p_mid,  g_mid);
    cudaGetSymbolAddress((void**)&p_m,    g_m);
    cudaGetSymbolAddress((void**)&p_f,    g_f);
    cudaGetSymbolAddress((void**)&p_q,    g_q);
    cudaGetSymbolAddress((void**)&p_k,    g_k);
    cudaGetSymbolAddress((void**)&p_v,    g_v);
    cudaGetSymbolAddress((void**)&p_attn, g_attn);
    cudaGetSymbolAddress((void**)&wt_e1, g_wt_e1);
    cudaGetSymbolAddress((void**)&wt_e2, g_wt_e2);
    cudaGetSymbolAddress((void**)&wt_q,  g_wt_q);
    cudaGetSymbolAddress((void**)&wt_k,  g_wt_k);
    cudaGetSymbolAddress((void**)&wt_v,  g_wt_v);
    cudaGetSymbolAddress((void**)&wt_d1, g_wt_d1);
    cudaGetSymbolAddress((void**)&wt_d2, g_wt_d2);

    const int fa_smem = FA_SMEM_FLOATS * sizeof(float);        // ~138.8 KB
    const int gm_smem = 2 * 2 * 128 * GPAD * sizeof(float);    // 73728 B
    cudaFuncSetAttribute(flash_attn_kernel,
                         cudaFuncAttributeMaxDynamicSharedMemorySize, fa_smem);
    cudaFuncSetAttribute(gemm_mma<0>, cudaFuncAttributeMaxDynamicSharedMemorySize, gm_smem);
    cudaFuncSetAttribute(gemm_mma<1>, cudaFuncAttributeMaxDynamicSharedMemorySize, gm_smem);
    cudaFuncSetAttribute(gemm_mma<2>, cudaFuncAttributeMaxDynamicSharedMemorySize, gm_smem);

    transpose_all<<<496, dim3(32, 8)>>>(We1, wt_e1, We2, wt_e2, Wq, wt_q,
                                        Wk, wt_k, Wv, wt_v, Wd1, wt_d1, Wd2, wt_d2);

    const int M = RTOT;
    // encode(main)
    gemm_mma<1><<<dim3(MID / 128, M / 128), 256, gm_smem>>>(mainf, wt_e1, be1, p_mid, M, MID, HH);
    gemm_mma<1><<<dim3(LAT / 128, M / 128), 256, gm_smem>>>(p_mid, wt_e2, be2, p_m,  M, LAT, MID);
    // encode(feature)
    gemm_mma<1><<<dim3(MID / 128, M / 128), 256, gm_smem>>>(feat,  wt_e1, be1, p_mid, M, MID, HH);
    gemm_mma<1><<<dim3(LAT / 128, M / 128), 256, gm_smem>>>(p_mid, wt_e2, be2, p_f,  M, LAT, MID);
    // q, k, v
    gemm_mma<0><<<dim3(LAT / 128, M / 128), 256, gm_smem>>>(p_m, wt_q, bq, p_q, M, LAT, LAT);
    gemm_mma<0><<<dim3(LAT / 128, M / 128), 256, gm_smem>>>(p_f, wt_k, bk, p_k, M, LAT, LAT);
    gemm_mma<0><<<dim3(LAT / 128, M / 128), 256, gm_smem>>>(p_f, wt_v, bv, p_v, M, LAT, LAT);
    // attention
    flash_attn_kernel<<<dim3(N1 / FA_BM, BB), 256, fa_smem>>>(p_q, p_k, p_v, p_attn);
    // decode
    gemm_mma<1><<<dim3(MID / 128, M / 128), 256, gm_smem>>>(p_attn, wt_d1, bd1, p_mid, M, MID, LAT);
    gemm_mma<2><<<dim3(HH  / 128, M / 128), 256, gm_smem>>>(p_mid,  wt_d2, bd2, out,  M, HH,  MID);
}

// round 11
// speedup vs baseline: 2.9051x; 1.1729x over previous
#include <cuda_runtime.h>
#include <math.h>
#include <cstdint>

// Problem dims
#define BB   16
#define N1   2048
#define N2   2048
#define HH   768
#define LAT  128
#define MID  256
#define RTOT (BB * N1)          // 32768 rows

// ---------------------------------------------------------------------------
// Scratch (device globals: allocation-free, graph-capturable)
// ---------------------------------------------------------------------------
__device__ float g_mid [RTOT * MID];
__device__ float g_m   [RTOT * LAT];
__device__ float g_f   [RTOT * LAT];
__device__ float g_q   [RTOT * LAT];
__device__ float g_k   [RTOT * LAT];
__device__ float g_v   [RTOT * LAT];
__device__ float g_attn[RTOT * LAT];
// Transposed weights [N, K] row-major (tf32-rounded)
__device__ float g_wt_e1[MID * HH];
__device__ float g_wt_e2[LAT * MID];
__device__ float g_wt_q [LAT * LAT];
__device__ float g_wt_k [LAT * LAT];
__device__ float g_wt_v [LAT * LAT];
__device__ float g_wt_d1[MID * LAT];
__device__ float g_wt_d2[HH * MID];

// ---------------------------------------------------------------------------
// Helpers
// ---------------------------------------------------------------------------
__device__ __forceinline__ float tf32r(float x) {
    uint32_t u;
    asm("cvt.rna.tf32.f32 %0, %1;" : "=r"(u) : "f"(x));
    return __uint_as_float(u);
}
__device__ __forceinline__ void mma8(float c[4], const uint32_t a[4], const uint32_t b[2]) {
    asm volatile(
        "mma.sync.aligned.m16n8k8.row.col.f32.tf32.tf32.f32 "
        "{%0,%1,%2,%3}, {%4,%5,%6,%7}, {%8,%9}, {%0,%1,%2,%3};"
        : "+f"(c[0]), "+f"(c[1]), "+f"(c[2]), "+f"(c[3])
        : "r"(a[0]), "r"(a[1]), "r"(a[2]), "r"(a[3]), "r"(b[0]), "r"(b[1]));
}
__device__ __forceinline__ uint32_t fu(float x) { return __float_as_uint(x); }
__device__ __forceinline__ uint32_t smem_u32(const void* p) {
    uint32_t a;
    asm("{ .reg .u64 t; cvta.to.shared.u64 t, %1; cvt.u32.u64 %0, t; }"
        : "=r"(a) : "l"(p));
    return a;
}
__device__ __forceinline__ void ldsm4(uint32_t& r0, uint32_t& r1, uint32_t& r2,
                                      uint32_t& r3, uint32_t addr) {
    asm volatile("ldmatrix.sync.aligned.m8n8.x4.shared.b16 {%0,%1,%2,%3}, [%4];"
                 : "=r"(r0), "=r"(r1), "=r"(r2), "=r"(r3) : "r"(addr));
}
__device__ __forceinline__ void cpa16(uint32_t dst, const void* src) {
    asm volatile("cp.async.cg.shared.global [%0], [%1], 16;" :: "r"(dst), "l"(src));
}
#define CP_COMMIT() asm volatile("cp.async.commit_group;")
#define CP_WAIT1()  asm volatile("cp.async.wait_group 1;")

// ---------------------------------------------------------------------------
// Fused weight transpose with tf32 rounding: in [K,N] -> out [N,K]
// ---------------------------------------------------------------------------
__global__ void transpose_all(
    const float* __restrict__ We1, float* __restrict__ wt_e1,
    const float* __restrict__ We2, float* __restrict__ wt_e2,
    const float* __restrict__ Wq,  float* __restrict__ wt_q,
    const float* __restrict__ Wk,  float* __restrict__ wt_k,
    const float* __restrict__ Wv,  float* __restrict__ wt_v,
    const float* __restrict__ Wd1, float* __restrict__ wt_d1,
    const float* __restrict__ Wd2, float* __restrict__ wt_d2)
{
    __shared__ float t[32][33];
    int idx = blockIdx.x;
    const float* in; float* out; int K, N, l;
    if (idx < 192)      { in = We1; out = wt_e1; K = HH;  N = MID; l = idx; }
    else if (idx < 224) { in = We2; out = wt_e2; K = MID; N = LAT; l = idx - 192; }
    else if (idx < 240) { in = Wq;  out = wt_q;  K = LAT; N = LAT; l = idx - 224; }
    else if (idx < 256) { in = Wk;  out = wt_k;  K = LAT; N = LAT; l = idx - 240; }
    else if (idx < 272) { in = Wv;  out = wt_v;  K = LAT; N = LAT; l = idx - 256; }
    else if (idx < 304) { in = Wd1; out = wt_d1; K = LAT; N = MID; l = idx - 272; }
    else                { in = Wd2; out = wt_d2; K = MID; N = HH;  l = idx - 304; }
    int tx = N >> 5;
    int nx = (l % tx) * 32, kx = (l / tx) * 32;
    int x = threadIdx.x, y = threadIdx.y;
#pragma unroll
    for (int i = 0; i < 32; i += 8)
        t[y + i][x] = in[(long)(kx + y + i) * N + nx + x];
    __syncthreads();
#pragma unroll
    for (int i = 0; i < 32; i += 8)
        out[(long)(nx + y + i) * K + kx + x] = tf32r(t[x][y + i]);
}

// ---------------------------------------------------------------------------
// tf32 mma GEMM v3: C[M,N] = act(A[M,K] @ Wt[N,K]^T + bias[N])
// CTA 128xBN, 256 threads = 8 warps of 64x(BN/4), BK=32, 3-stage cp.async.
// ACT: 0=none, 1=relu, 2=sigmoid. ACT 0/1 round output to tf32.
// ---------------------------------------------------------------------------
#define GPAD 36

template <int ACT, int BN>
__global__ __launch_bounds__(256) void gemm_mma(
    const float* __restrict__ A, const float* __restrict__ Wt,
    const float* __restrict__ bias, float* __restrict__ C,
    int M, int N, int K)
{
    extern __shared__ float sm[];
    constexpr int STG_A = 128 * GPAD;
    constexpr int STG_B = BN * GPAD;
    constexpr int STG   = STG_A + STG_B;
    constexpr int NT    = BN / 32;        // n-tiles per warp: 8 (BN=256) / 4 (BN=128)

    const int tid = threadIdx.x;
    const int wid = tid >> 5, lane = tid & 31;
    const int g = lane >> 2, t4 = lane & 3;
    const int wm = (wid & 1) * 64;
    const int wn = (wid >> 1) * (BN / 4);
    const int m0 = blockIdx.y * 128, n0 = blockIdx.x * BN;

    float c[4][NT][4];
#pragma unroll
    for (int mt = 0; mt < 4; mt++)
#pragma unroll
        for (int nt = 0; nt < NT; nt++)
#pragma unroll
            for (int i = 0; i < 4; i++) c[mt][nt][i] = 0.f;

    const int nk = K >> 5;

    // cp.async loader: stage s <- k-block kt
    auto load_stage = [&](int kt, int s) {
        float* base = sm + s * STG;
#pragma unroll
        for (int i = 0; i < 4; i++) {
            int idx = tid + i * 256;
            int r = idx >> 3, c4 = idx & 7;
            cpa16(smem_u32(base + r * GPAD + c4 * 4),
                  A + (long)(m0 + r) * K + kt * 32 + c4 * 4);
        }
#pragma unroll
        for (int i = 0; i < BN / 32; i++) {
            int idx = tid + i * 256;
            int r = idx >> 3, c4 = idx & 7;
            cpa16(smem_u32(base + STG_A + r * GPAD + c4 * 4),
                  Wt + (long)(n0 + r) * K + kt * 32 + c4 * 4);
        }
    };

    // ldmatrix lane addressing (validated in round 8)
    const int mat = lane >> 3, rowin = lane & 7;
    const uint32_t a0 = smem_u32(sm)
        + ((uint32_t)((wm + (mat & 1) * 8 + rowin) * GPAD + (mat >> 1) * 4) << 2);
    const uint32_t b0 = smem_u32(sm) + (uint32_t)(STG_A << 2)
        + ((uint32_t)((wn + (mat >> 1) * 8 + rowin) * GPAD + (mat & 1) * 4) << 2);

    load_stage(0, 0); CP_COMMIT();
    load_stage(1, 1); CP_COMMIT();

    for (int kt = 0; kt < nk; kt++) {
        CP_WAIT1();
        __syncthreads();
        if (kt + 2 < nk) load_stage(kt + 2, (kt + 2) % 3);
        CP_COMMIT();

        int s = kt % 3;
        uint32_t ab = a0 + (uint32_t)(s * STG) * 4;
        uint32_t bb = b0 + (uint32_t)(s * STG) * 4;
#pragma unroll
        for (int ks = 0; ks < 4; ks++) {
            uint32_t af[4][4], bf[NT][2];
#pragma unroll
            for (int mt = 0; mt < 4; mt++)
                ldsm4(af[mt][0], af[mt][1], af[mt][2], af[mt][3],
                      ab + mt * 16 * GPAD * 4 + ks * 32);
#pragma unroll
            for (int p = 0; p < NT / 2; p++)
                ldsm4(bf[2 * p][0], bf[2 * p][1], bf[2 * p + 1][0], bf[2 * p + 1][1],
                      bb + p * 16 * GPAD * 4 + ks * 32);
#pragma unroll
            for (int mt = 0; mt < 4; mt++)
#pragma unroll
                for (int nt = 0; nt < NT; nt++)
                    mma8(c[mt][nt], af[mt], bf[nt]);
        }
    }

    // Epilogue: bias + act (+ tf32 rounding for downstream GEMM/FA consumers)
#pragma unroll
    for (int mt = 0; mt < 4; mt++) {
        int r0 = m0 + wm + mt * 16 + g;
#pragma unroll
        for (int nt = 0; nt < NT; nt++) {
            int col = n0 + wn + nt * 8 + 2 * t4;
            float2 bv = *(const float2*)(bias + col);
            float x0 = c[mt][nt][0] + bv.x;
            float x1 = c[mt][nt][1] + bv.y;
            float x2 = c[mt][nt][2] + bv.x;
            float x3 = c[mt][nt][3] + bv.y;
            if (ACT == 1) {
                x0 = fmaxf(x0, 0.f); x1 = fmaxf(x1, 0.f);
                x2 = fmaxf(x2, 0.f); x3 = fmaxf(x3, 0.f);
            }
            if (ACT == 2) {
                x0 = 1.f / (1.f + __expf(-x0)); x1 = 1.f / (1.f + __expf(-x1));
                x2 = 1.f / (1.f + __expf(-x2)); x3 = 1.f / (1.f + __expf(-x3));
            }
            if (ACT != 2) {
                x0 = tf32r(x0); x1 = tf32r(x1); x2 = tf32r(x2); x3 = tf32r(x3);
            }
            *(float2*)(C + (long)r0 * N + col)       = make_float2(x0, x1);
            *(float2*)(C + (long)(r0 + 8) * N + col) = make_float2(x2, x3);
        }
    }
}

// ---------------------------------------------------------------------------
// Flash attention (round-7/8 validated structure; output rounded to tf32)
// ---------------------------------------------------------------------------
#define FA_BM 128
#define FA_BN 64
#define QSTR  132
#define VSTR  136
#define FA_SMEM_FLOATS (128*QSTR + 64*VSTR + 128*68 + 3*128)

__global__ __launch_bounds__(256, 1) void flash_attn_kernel(
    const float* __restrict__ Q, const float* __restrict__ K,
    const float* __restrict__ V, float* __restrict__ O)
{
    extern __shared__ float sm[];
    float* Qs  = sm;
    float* KVs = Qs + 128 * QSTR;
    float* Ssh = KVs + 64 * VSTR;
    float* msh = Ssh + 128 * 68;
    float* lsh = msh + 128;
    float* ash = lsh + 128;

    const int tid = threadIdx.x;
    const int b   = blockIdx.y;
    const int m0  = blockIdx.x * FA_BM;

    const float* Qb = Q + ((long)b * N1 + m0) * LAT;
    const float* Kb = K + (long)b * N2 * LAT;
    const float* Vb = V + (long)b * N2 * LAT;

    const int wid = tid >> 5, lane = tid & 31;
    const int g = lane >> 2, t4 = lane & 3;
    const int qr0 = wid * 16;
    const int wm = (wid & 3) * 32;
    const int wn = (wid >> 2) * 64;

#pragma unroll
    for (int i = 0; i < 16; i++) {
        int idx = tid + i * 256;
        int r   = idx >> 5;
        int c4  = idx & 31;
        float4 v = *(const float4*)(Qb + r * LAT + c4 * 4);
        v.x = tf32r(v.x); v.y = tf32r(v.y); v.z = tf32r(v.z); v.w = tf32r(v.w);
        *(float4*)(Qs + r * QSTR + c4 * 4) = v;
    }
    if (tid < 128) { msh[tid] = -INFINITY; lsh[tid] = 0.f; }

    float oc[2][8][4];
#pragma unroll
    for (int mt = 0; mt < 2; mt++)
#pragma unroll
        for (int nt = 0; nt < 8; nt++)
#pragma unroll
            for (int i = 0; i < 4; i++) oc[mt][nt][i] = 0.f;

    __syncthreads();

    for (int t0 = 0; t0 < N2; t0 += FA_BN) {
#pragma unroll
        for (int i = 0; i < 8; i++) {
            int idx = tid + i * 256;
            int r   = idx >> 5;
            int c4  = idx & 31;
            float4 v = *(const float4*)(Kb + (t0 + r) * LAT + c4 * 4);
            v.x = tf32r(v.x); v.y = tf32r(v.y); v.z = tf32r(v.z); v.w = tf32r(v.w);
            *(float4*)(KVs + r * QSTR + c4 * 4) = v;
        }
        __syncthreads();

        float c[8][4];
#pragma unroll
        for (int nt = 0; nt < 8; nt++)
#pragma unroll
            for (int i = 0; i < 4; i++) c[nt][i] = 0.f;

#pragma unroll
        for (int ks = 0; ks < 16; ks++) {
            int kb = ks * 8;
            uint32_t af[4], bf[8][2];
            af[0] = fu(Qs[(qr0 + g)     * QSTR + kb + t4]);
            af[1] = fu(Qs[(qr0 + g + 8) * QSTR + kb + t4]);
            af[2] = fu(Qs[(qr0 + g)     * QSTR + kb + t4 + 4]);
            af[3] = fu(Qs[(qr0 + g + 8) * QSTR + kb + t4 + 4]);
#pragma unroll
            for (int nt = 0; nt < 8; nt++) {
                int cc = nt * 8;
                bf[nt][0] = fu(KVs[(cc + g) * QSTR + kb + t4]);
                bf[nt][1] = fu(KVs[(cc + g) * QSTR + kb + t4 + 4]);
            }
#pragma unroll
            for (int nt = 0; nt < 8; nt++)
                mma8(c[nt], af, bf[nt]);
        }

#pragma unroll
        for (int nt = 0; nt < 8; nt++) {
            int col = nt * 8 + 2 * t4;
            *(float2*)(Ssh + (qr0 + g)     * 68 + col) = make_float2(c[nt][0], c[nt][1]);
            *(float2*)(Ssh + (qr0 + g + 8) * 68 + col) = make_float2(c[nt][2], c[nt][3]);
        }
        __syncthreads();

#pragma unroll
        for (int i = 0; i < 8; i++) {
            int idx = tid + i * 256;
            int r   = idx >> 5;
            int c4  = idx & 31;
            float4 v = *(const float4*)(Vb + (t0 + r) * LAT + c4 * 4);
            v.x = tf32r(v.x); v.y = tf32r(v.y); v.z = tf32r(v.z); v.w = tf32r(v.w);
            *(float4*)(KVs + r * VSTR + c4 * 4) = v;
        }

        if (tid < 128) {
            float mold = msh[tid];
            float mnew = mold;
            float* srow = Ssh + tid * 68;
#pragma unroll
            for (int j = 0; j < 64; j++) mnew = fmaxf(mnew, srow[j]);
            float alpha = __expf(mold - mnew);
            float lsum = 0.f;
#pragma unroll
            for (int j = 0; j < 64; j++) {
                float e = tf32r(__expf(srow[j] - mnew));
                srow[j] = e;
                lsum += e;
            }
            lsh[tid] = lsh[tid] * alpha + lsum;
            msh[tid] = mnew;
            ash[tid] = alpha;
        }
        __syncthreads();

#pragma unroll
        for (int mt = 0; mt < 2; mt++) {
            float al0 = ash[wm + mt * 16 + g];
            float al1 = ash[wm + mt * 16 + 8 + g];
#pragma unroll
            for (int nt = 0; nt < 8; nt++) {
                oc[mt][nt][0] *= al0; oc[mt][nt][1] *= al0;
                oc[mt][nt][2] *= al1; oc[mt][nt][3] *= al1;
            }
        }
#pragma unroll
        for (int ks = 0; ks < 8; ks++) {
            int kb = ks * 8;
            uint32_t af[2][4], bf[8][2];
#pragma unroll
            for (int mt = 0; mt < 2; mt++) {
                int r = wm + mt * 16;
                af[mt][0] = fu(Ssh[(r + g)     * 68 + kb + t4]);
                af[mt][1] = fu(Ssh[(r + g + 8) * 68 + kb + t4]);
                af[mt][2] = fu(Ssh[(r + g)     * 68 + kb + t4 + 4]);
                af[mt][3] = fu(Ssh[(r + g + 8) * 68 + kb + t4 + 4]);
            }
#pragma unroll
            for (int nt = 0; nt < 8; nt++) {
                int cc = wn + nt * 8;
                bf[nt][0] = fu(KVs[(kb + t4)     * VSTR + cc + g]);
                bf[nt][1] = fu(KVs[(kb + t4 + 4) * VSTR + cc + g]);
            }
#pragma unroll
            for (int mt = 0; mt < 2; mt++)
#pragma unroll
                for (int nt = 0; nt < 8; nt++)
                    mma8(oc[mt][nt], af[mt], bf[nt]);
        }
        __syncthreads();
    }

#pragma unroll
    for (int mt = 0; mt < 2; mt++) {
        int r0 = wm + mt * 16 + g;
        float inv0 = 1.f / lsh[r0];
        float inv1 = 1.f / lsh[r0 + 8];
        long row0 = (long)b * N1 + m0 + r0;
#pragma unroll
        for (int nt = 0; nt < 8; nt++) {
            int col = wn + nt * 8 + 2 * t4;
            *(float2*)(O + row0 * LAT + col) =
                make_float2(tf32r(oc[mt][nt][0] * inv0), tf32r(oc[mt][nt][1] * inv0));
            *(float2*)(O + (row0 + 8) * LAT + col) =
                make_float2(tf32r(oc[mt][nt][2] * inv1), tf32r(oc[mt][nt][3] * inv1));
        }
    }
}

// ---------------------------------------------------------------------------
// Host launcher
// ---------------------------------------------------------------------------
extern "C" void kernel_launch(void* const* d_in, const int* in_sizes, int n_in,
                              void* d_out, int out_size)
{
    const float* mainf = (const float*)d_in[0];
    const float* feat  = (const float*)d_in[1];
    const float* We1   = (const float*)d_in[2];
    const float* be1   = (const float*)d_in[3];
    const float* We2   = (const float*)d_in[4];
    const float* be2   = (const float*)d_in[5];
    const float* Wq    = (const float*)d_in[6];
    const float* bq    = (const float*)d_in[7];
    const float* Wk    = (const float*)d_in[8];
    const float* bk    = (const float*)d_in[9];
    const float* Wv    = (const float*)d_in[10];
    const float* bv    = (const float*)d_in[11];
    const float* Wd1   = (const float*)d_in[12];
    const float* bd1   = (const float*)d_in[13];
    const float* Wd2   = (const float*)d_in[14];
    const float* bd2   = (const float*)d_in[15];
    float* out = (float*)d_out;

    float *p_mid, *p_m, *p_f, *p_q, *p_k, *p_v, *p_attn;
    float *wt_e1, *wt_e2, *wt_q, *wt_k, *wt_v, *wt_d1, *wt_d2;
    cudaGetSymbolAddress((void**)&p_mid,  g_mid);
    cudaGetSymbolAddress((void**)&p_m,    g_m);
    cudaGetSymbolAddress((void**)&p_f,    g_f);
    cudaGetSymbolAddress((void**)&p_q,    g_q);
    cudaGetSymbolAddress((void**)&p_k,    g_k);
    cudaGetSymbolAddress((void**)&p_v,    g_v);
    cudaGetSymbolAddress((void**)&p_attn, g_attn);
    cudaGetSymbolAddress((void**)&wt_e1, g_wt_e1);
    cudaGetSymbolAddress((void**)&wt_e2, g_wt_e2);
    cudaGetSymbolAddress((void**)&wt_q,  g_wt_q);
    cudaGetSymbolAddress((void**)&wt_k,  g_wt_k);
    cudaGetSymbolAddress((void**)&wt_v,  g_wt_v);
    cudaGetSymbolAddress((void**)&wt_d1, g_wt_d1);
    cudaGetSymbolAddress((void**)&wt_d2, g_wt_d2);

    const int fa_smem  = FA_SMEM_FLOATS * sizeof(float);          // ~138.8 KB
    const int gm256_sm = 3 * (128 + 256) * GPAD * sizeof(float);  // 165888
    const int gm128_sm = 3 * (128 + 128) * GPAD * sizeof(float);  // 110592
    cudaFuncSetAttribute(flash_attn_kernel,
                         cudaFuncAttributeMaxDynamicSharedMemorySize, fa_smem);
    cudaFuncSetAttribute(gemm_mma<1, 256>, cudaFuncAttributeMaxDynamicSharedMemorySize, gm256_sm);
    cudaFuncSetAttribute(gemm_mma<2, 256>, cudaFuncAttributeMaxDynamicSharedMemorySize, gm256_sm);
    cudaFuncSetAttribute(gemm_mma<0, 128>, cudaFuncAttributeMaxDynamicSharedMemorySize, gm128_sm);
    cudaFuncSetAttribute(gemm_mma<1, 128>, cudaFuncAttributeMaxDynamicSharedMemorySize, gm128_sm);

    transpose_all<<<496, dim3(32, 8)>>>(We1, wt_e1, We2, wt_e2, Wq, wt_q,
                                        Wk, wt_k, Wv, wt_v, Wd1, wt_d1, Wd2, wt_d2);

    const int M = RTOT;
    // encode(main)
    gemm_mma<1, 256><<<dim3(1, M / 128), 256, gm256_sm>>>(mainf, wt_e1, be1, p_mid, M, MID, HH);
    gemm_mma<1, 128><<<dim3(1, M / 128), 256, gm128_sm>>>(p_mid, wt_e2, be2, p_m,  M, LAT, MID);
    // encode(feature)
    gemm_mma<1, 256><<<dim3(1, M / 128), 256, gm256_sm>>>(feat,  wt_e1, be1, p_mid, M, MID, HH);
    gemm_mma<1, 128><<<dim3(1, M / 128), 256, gm128_sm>>>(p_mid, wt_e2, be2, p_f,  M, LAT, MID);
    // q, k, v
    gemm_mma<0, 128><<<dim3(1, M / 128), 256, gm128_sm>>>(p_m, wt_q, bq, p_q, M, LAT, LAT);
    gemm_mma<0, 128><<<dim3(1, M / 128), 256, gm128_sm>>>(p_f, wt_k, bk, p_k, M, LAT, LAT);
    gemm_mma<0, 128><<<dim3(1, M / 128), 256, gm128_sm>>>(p_f, wt_v, bv, p_v, M, LAT, LAT);
    // attention
    flash_attn_kernel<<<dim3(N1 / FA_BM, BB), 256, fa_smem>>>(p_q, p_k, p_v, p_attn);
    // decode
    gemm_mma<1, 256><<<dim3(1, M / 128), 256, gm256_sm>>>(p_attn, wt_d1, bd1, p_mid, M, MID, LAT);
    gemm_mma<2, 256><<<dim3(3, M / 128), 256, gm256_sm>>>(p_mid,  wt_d2, bd2, out,  M, HH,  MID);
}

// round 12
// speedup vs baseline: 3.8919x; 1.3396x over previous
#include <cuda_runtime.h>
#include <cuda_bf16.h>
#include <math.h>
#include <cstdint>

// Problem dims
#define BB   16
#define N1   2048
#define N2   2048
#define HH   768
#define LAT  128
#define MID  256
#define RTOT (BB * N1)

typedef __nv_bfloat16  bf16;
typedef __nv_bfloat162 bf162;

// ---------------------------------------------------------------------------
// Scratch (device globals)
// ---------------------------------------------------------------------------
__device__ bf16 g_mid [RTOT * MID];
__device__ bf16 g_m   [RTOT * LAT];
__device__ bf16 g_f   [RTOT * LAT];
__device__ bf16 g_q   [RTOT * LAT];
__device__ bf16 g_k   [RTOT * LAT];
__device__ bf16 g_v   [RTOT * LAT];
__device__ bf16 g_attn[RTOT * LAT];
__device__ float g_wt_e1[MID * HH];     // tf32-rounded fp32 (stage-1)
__device__ bf16  g_wb_e2[LAT * MID];
__device__ bf16  g_wb_q [LAT * LAT];
__device__ bf16  g_wb_k [LAT * LAT];
__device__ bf16  g_wb_v [LAT * LAT];
__device__ bf16  g_wb_d1[MID * LAT];
__device__ bf16  g_wb_d2[HH * MID];

// ---------------------------------------------------------------------------
// Helpers
// ---------------------------------------------------------------------------
__device__ __forceinline__ float tf32r(float x) {
    uint32_t u;
    asm("cvt.rna.tf32.f32 %0, %1;" : "=r"(u) : "f"(x));
    return __uint_as_float(u);
}
__device__ __forceinline__ void mma8(float c[4], const uint32_t a[4], const uint32_t b[2]) {
    asm volatile(
        "mma.sync.aligned.m16n8k8.row.col.f32.tf32.tf32.f32 "
        "{%0,%1,%2,%3}, {%4,%5,%6,%7}, {%8,%9}, {%0,%1,%2,%3};"
        : "+f"(c[0]), "+f"(c[1]), "+f"(c[2]), "+f"(c[3])
        : "r"(a[0]), "r"(a[1]), "r"(a[2]), "r"(a[3]), "r"(b[0]), "r"(b[1]));
}
__device__ __forceinline__ void mma16(float c[4], const uint32_t a[4], const uint32_t b[2]) {
    asm volatile(
        "mma.sync.aligned.m16n8k16.row.col.f32.bf16.bf16.f32 "
        "{%0,%1,%2,%3}, {%4,%5,%6,%7}, {%8,%9}, {%0,%1,%2,%3};"
        : "+f"(c[0]), "+f"(c[1]), "+f"(c[2]), "+f"(c[3])
        : "r"(a[0]), "r"(a[1]), "r"(a[2]), "r"(a[3]), "r"(b[0]), "r"(b[1]));
}
__device__ __forceinline__ uint32_t smem_u32(const void* p) {
    uint32_t a;
    asm("{ .reg .u64 t; cvta.to.shared.u64 t, %1; cvt.u32.u64 %0, t; }"
        : "=r"(a) : "l"(p));
    return a;
}
__device__ __forceinline__ void ldsm4(uint32_t& r0, uint32_t& r1, uint32_t& r2,
                                      uint32_t& r3, uint32_t addr) {
    asm volatile("ldmatrix.sync.aligned.m8n8.x4.shared.b16 {%0,%1,%2,%3}, [%4];"
                 : "=r"(r0), "=r"(r1), "=r"(r2), "=r"(r3) : "r"(addr));
}
__device__ __forceinline__ void ldsm4t(uint32_t& r0, uint32_t& r1, uint32_t& r2,
                                       uint32_t& r3, uint32_t addr) {
    asm volatile("ldmatrix.sync.aligned.m8n8.x4.trans.shared.b16 {%0,%1,%2,%3}, [%4];"
                 : "=r"(r0), "=r"(r1), "=r"(r2), "=r"(r3) : "r"(addr));
}
__device__ __forceinline__ void cpa16(uint32_t dst, const void* src) {
    asm volatile("cp.async.cg.shared.global [%0], [%1], 16;" :: "r"(dst), "l"(src));
}
#define CP_COMMIT() asm volatile("cp.async.commit_group;")
#define CP_WAIT1()  asm volatile("cp.async.wait_group 1;")

// ---------------------------------------------------------------------------
// Fused weight transpose: We1 -> fp32 tf32-rounded; rest -> bf16
// ---------------------------------------------------------------------------
__global__ void transpose_all(
    const float* __restrict__ We1, float* __restrict__ wt_e1,
    const float* __restrict__ We2, bf16* __restrict__ wb_e2,
    const float* __restrict__ Wq,  bf16* __restrict__ wb_q,
    const float* __restrict__ Wk,  bf16* __restrict__ wb_k,
    const float* __restrict__ Wv,  bf16* __restrict__ wb_v,
    const float* __restrict__ Wd1, bf16* __restrict__ wb_d1,
    const float* __restrict__ Wd2, bf16* __restrict__ wb_d2)
{
    __shared__ float t[32][33];
    int idx = blockIdx.x;
    const float* in; float* outf = nullptr; bf16* outb = nullptr; int K, N, l;
    if (idx < 192)      { in = We1; outf = wt_e1; K = HH;  N = MID; l = idx; }
    else if (idx < 224) { in = We2; outb = wb_e2; K = MID; N = LAT; l = idx - 192; }
    else if (idx < 240) { in = Wq;  outb = wb_q;  K = LAT; N = LAT; l = idx - 224; }
    else if (idx < 256) { in = Wk;  outb = wb_k;  K = LAT; N = LAT; l = idx - 240; }
    else if (idx < 272) { in = Wv;  outb = wb_v;  K = LAT; N = LAT; l = idx - 256; }
    else if (idx < 304) { in = Wd1; outb = wb_d1; K = LAT; N = MID; l = idx - 272; }
    else                { in = Wd2; outb = wb_d2; K = MID; N = HH;  l = idx - 304; }
    int tx = N >> 5;
    int nx = (l % tx) * 32, kx = (l / tx) * 32;
    int x = threadIdx.x, y = threadIdx.y;
#pragma unroll
    for (int i = 0; i < 32; i += 8)
        t[y + i][x] = in[(long)(kx + y + i) * N + nx + x];
    __syncthreads();
    if (outf) {
#pragma unroll
        for (int i = 0; i < 32; i += 8)
            outf[(long)(nx + y + i) * K + kx + x] = tf32r(t[x][y + i]);
    } else {
#pragma unroll
        for (int i = 0; i < 32; i += 8)
            outb[(long)(nx + y + i) * K + kx + x] = __float2bfloat16(t[x][y + i]);
    }
}

// ---------------------------------------------------------------------------
// Stage-1 tf32 GEMM (A fp32 raw input): C_bf16 = relu(A @ Wt^T + bias)
// CTA 128x256, validated round-11 structure. Output bf16.
// ---------------------------------------------------------------------------
#define GPAD 36

__global__ __launch_bounds__(256) void gemm_e1(
    const float* __restrict__ A, const float* __restrict__ Wt,
    const float* __restrict__ bias, bf16* __restrict__ C,
    int M, int N, int K)
{
    extern __shared__ char smraw[];
    float* sm = (float*)smraw;
    constexpr int BN = 256;
    constexpr int STG_A = 128 * GPAD;
    constexpr int STG_B = BN * GPAD;
    constexpr int STG   = STG_A + STG_B;
    constexpr int NT    = 8;

    const int tid = threadIdx.x;
    const int wid = tid >> 5, lane = tid & 31;
    const int g = lane >> 2, t4 = lane & 3;
    const int wm = (wid & 1) * 64;
    const int wn = (wid >> 1) * 64;
    const int m0 = blockIdx.y * 128, n0 = blockIdx.x * BN;

    float c[4][NT][4];
#pragma unroll
    for (int mt = 0; mt < 4; mt++)
#pragma unroll
        for (int nt = 0; nt < NT; nt++)
#pragma unroll
            for (int i = 0; i < 4; i++) c[mt][nt][i] = 0.f;

    const int nk = K >> 5;

    auto load_stage = [&](int kt, int s) {
        float* base = sm + s * STG;
#pragma unroll
        for (int i = 0; i < 4; i++) {
            int idx = tid + i * 256;
            int r = idx >> 3, c4 = idx & 7;
            cpa16(smem_u32(base + r * GPAD + c4 * 4),
                  A + (long)(m0 + r) * K + kt * 32 + c4 * 4);
        }
#pragma unroll
        for (int i = 0; i < 8; i++) {
            int idx = tid + i * 256;
            int r = idx >> 3, c4 = idx & 7;
            cpa16(smem_u32(base + STG_A + r * GPAD + c4 * 4),
                  Wt + (long)(n0 + r) * K + kt * 32 + c4 * 4);
        }
    };

    const int mat = lane >> 3, rowin = lane & 7;
    const uint32_t a0 = smem_u32(sm)
        + ((uint32_t)((wm + (mat & 1) * 8 + rowin) * GPAD + (mat >> 1) * 4) << 2);
    const uint32_t b0 = smem_u32(sm) + (uint32_t)(STG_A << 2)
        + ((uint32_t)((wn + (mat >> 1) * 8 + rowin) * GPAD + (mat & 1) * 4) << 2);

    load_stage(0, 0); CP_COMMIT();
    load_stage(1, 1); CP_COMMIT();

    for (int kt = 0; kt < nk; kt++) {
        CP_WAIT1();
        __syncthreads();
        if (kt + 2 < nk) load_stage(kt + 2, (kt + 2) % 3);
        CP_COMMIT();

        int s = kt % 3;
        uint32_t ab = a0 + (uint32_t)(s * STG) * 4;
        uint32_t bb = b0 + (uint32_t)(s * STG) * 4;
#pragma unroll
        for (int ks = 0; ks < 4; ks++) {
            uint32_t af[4][4], bfr[NT][2];
#pragma unroll
            for (int mt = 0; mt < 4; mt++)
                ldsm4(af[mt][0], af[mt][1], af[mt][2], af[mt][3],
                      ab + mt * 16 * GPAD * 4 + ks * 32);
#pragma unroll
            for (int p = 0; p < NT / 2; p++)
                ldsm4(bfr[2 * p][0], bfr[2 * p][1], bfr[2 * p + 1][0], bfr[2 * p + 1][1],
                      bb + p * 16 * GPAD * 4 + ks * 32);
#pragma unroll
            for (int mt = 0; mt < 4; mt++)
#pragma unroll
                for (int nt = 0; nt < NT; nt++)
                    mma8(c[mt][nt], af[mt], bfr[nt]);
        }
    }

#pragma unroll
    for (int mt = 0; mt < 4; mt++) {
        int r0 = m0 + wm + mt * 16 + g;
#pragma unroll
        for (int nt = 0; nt < NT; nt++) {
            int col = n0 + wn + nt * 8 + 2 * t4;
            float2 bv = *(const float2*)(bias + col);
            float x0 = fmaxf(c[mt][nt][0] + bv.x, 0.f);
            float x1 = fmaxf(c[mt][nt][1] + bv.y, 0.f);
            float x2 = fmaxf(c[mt][nt][2] + bv.x, 0.f);
            float x3 = fmaxf(c[mt][nt][3] + bv.y, 0.f);
            *(bf162*)(C + (long)r0 * N + col)       = __floats2bfloat162_rn(x0, x1);
            *(bf162*)(C + (long)(r0 + 8) * N + col) = __floats2bfloat162_rn(x2, x3);
        }
    }
}

// ---------------------------------------------------------------------------
// bf16 mma GEMM: C = act(A_bf16 @ Wt_bf16^T + bias)
// CTA 128xBN, BK=64 bf16, 3-stage cp.async, m16n8k16.
// ACT: 0=none, 1=relu, 2=sigmoid. OUT32: 1 -> fp32 out, 0 -> bf16 out.
// ---------------------------------------------------------------------------
#define BPAD 72

template <int ACT, int BN, int OUT32>
__global__ __launch_bounds__(256) void gemm_bf16(
    const bf16* __restrict__ A, const bf16* __restrict__ Wt,
    const float* __restrict__ bias, void* __restrict__ Cv,
    int M, int N, int K)
{
    extern __shared__ char smraw[];
    bf16* smb = (bf16*)smraw;
    constexpr int STG_A = 128 * BPAD;
    constexpr int STG_B = BN * BPAD;
    constexpr int STG   = STG_A + STG_B;
    constexpr int NT    = BN / 32;

    const int tid = threadIdx.x;
    const int wid = tid >> 5, lane = tid & 31;
    const int g = lane >> 2, t4 = lane & 3;
    const int wm = (wid & 1) * 64;
    const int wn = (wid >> 1) * (BN / 4);
    const int m0 = blockIdx.y * 128, n0 = blockIdx.x * BN;

    float c[4][NT][4];
#pragma unroll
    for (int mt = 0; mt < 4; mt++)
#pragma unroll
        for (int nt = 0; nt < NT; nt++)
#pragma unroll
            for (int i = 0; i < 4; i++) c[mt][nt][i] = 0.f;

    const int nk = K >> 6;

    auto load_stage = [&](int kt, int s) {
        bf16* base = smb + s * STG;
#pragma unroll
        for (int i = 0; i < 4; i++) {
            int idx = tid + i * 256;
            int r = idx >> 3, c8 = idx & 7;
            cpa16(smem_u32(base + r * BPAD + c8 * 8),
                  A + (long)(m0 + r) * K + kt * 64 + c8 * 8);
        }
#pragma unroll
        for (int i = 0; i < BN / 32; i++) {
            int idx = tid + i * 256;
            int r = idx >> 3, c8 = idx & 7;
            cpa16(smem_u32(base + STG_A + r * BPAD + c8 * 8),
                  Wt + (long)(n0 + r) * K + kt * 64 + c8 * 8);
        }
    };

    const int mat = lane >> 3, rowin = lane & 7;
    const uint32_t a0 = smem_u32(smb)
        + (uint32_t)((wm + (mat & 1) * 8 + rowin) * BPAD + (mat >> 1) * 8) * 2;
    const uint32_t b0 = smem_u32(smb) + (uint32_t)STG_A * 2
        + (uint32_t)((wn + (mat >> 1) * 8 + rowin) * BPAD + (mat & 1) * 8) * 2;

    load_stage(0, 0); CP_COMMIT();
    load_stage(1, 1); CP_COMMIT();

    for (int kt = 0; kt < nk; kt++) {
        CP_WAIT1();
        __syncthreads();
        if (kt + 2 < nk) load_stage(kt + 2, (kt + 2) % 3);
        CP_COMMIT();

        int s = kt % 3;
        uint32_t ab = a0 + (uint32_t)(s * STG) * 2;
        uint32_t bb = b0 + (uint32_t)(s * STG) * 2;
#pragma unroll
        for (int ks = 0; ks < 4; ks++) {
            uint32_t af[4][4], bfr[NT][2];
#pragma unroll
            for (int mt = 0; mt < 4; mt++)
                ldsm4(af[mt][0], af[mt][1], af[mt][2], af[mt][3],
                      ab + mt * (16 * BPAD * 2) + ks * 32);
#pragma unroll
            for (int p = 0; p < NT / 2; p++)
                ldsm4(bfr[2 * p][0], bfr[2 * p][1], bfr[2 * p + 1][0], bfr[2 * p + 1][1],
                      bb + p * (16 * BPAD * 2) + ks * 32);
#pragma unroll
            for (int mt = 0; mt < 4; mt++)
#pragma unroll
                for (int nt = 0; nt < NT; nt++)
                    mma16(c[mt][nt], af[mt], bfr[nt]);
        }
    }

#pragma unroll
    for (int mt = 0; mt < 4; mt++) {
        int r0 = m0 + wm + mt * 16 + g;
#pragma unroll
        for (int nt = 0; nt < NT; nt++) {
            int col = n0 + wn + nt * 8 + 2 * t4;
            float2 bv = *(const float2*)(bias + col);
            float x0 = c[mt][nt][0] + bv.x;
            float x1 = c[mt][nt][1] + bv.y;
            float x2 = c[mt][nt][2] + bv.x;
            float x3 = c[mt][nt][3] + bv.y;
            if (ACT == 1) {
                x0 = fmaxf(x0, 0.f); x1 = fmaxf(x1, 0.f);
                x2 = fmaxf(x2, 0.f); x3 = fmaxf(x3, 0.f);
            }
            if (ACT == 2) {
                x0 = 1.f / (1.f + __expf(-x0)); x1 = 1.f / (1.f + __expf(-x1));
                x2 = 1.f / (1.f + __expf(-x2)); x3 = 1.f / (1.f + __expf(-x3));
            }
            if (OUT32) {
                float* C = (float*)Cv;
                *(float2*)(C + (long)r0 * N + col)       = make_float2(x0, x1);
                *(float2*)(C + (long)(r0 + 8) * N + col) = make_float2(x2, x3);
            } else {
                bf16* C = (bf16*)Cv;
                *(bf162*)(C + (long)r0 * N + col)       = __floats2bfloat162_rn(x0, x1);
                *(bf162*)(C + (long)(r0 + 8) * N + col) = __floats2bfloat162_rn(x2, x3);
            }
        }
    }
}

// ---------------------------------------------------------------------------
// Flash attention, bf16 mma: QK^T + softmax(fp32) + P@V. 128 q-rows/block.
// ---------------------------------------------------------------------------
#define FA_BM 128
#define FA_BN 64
#define FQS   136     // Q/K/V smem stride (bf16): 272B rows, conflict-free ldsm
#define FPS   72      // P smem stride (bf16): 144B rows
#define FA_SMEM_BYTES (128*FQS*2 + 64*FQS*2 + 128*68*4 + 128*FPS*2 + 3*128*4)

__global__ __launch_bounds__(256, 1) void flash_attn_bf16(
    const bf16* __restrict__ Q, const bf16* __restrict__ K,
    const bf16* __restrict__ V, bf16* __restrict__ O)
{
    extern __shared__ char smraw[];
    bf16*  Qs  = (bf16*)smraw;               // [128][FQS]
    bf16*  KVs = Qs + 128 * FQS;             // [64][FQS] (K then V overlay)
    float* Ssh = (float*)(KVs + 64 * FQS);   // [128][68]
    bf16*  Ps  = (bf16*)(Ssh + 128 * 68);    // [128][FPS]
    float* msh = (float*)(Ps + 128 * FPS);
    float* lsh = msh + 128;
    float* ash = lsh + 128;

    const int tid = threadIdx.x;
    const int b   = blockIdx.y;
    const int m0  = blockIdx.x * FA_BM;

    const bf16* Qb = Q + ((long)b * N1 + m0) * LAT;
    const bf16* Kb = K + (long)b * N2 * LAT;
    const bf16* Vb = V + (long)b * N2 * LAT;

    const int wid = tid >> 5, lane = tid & 31;
    const int g = lane >> 2, t4 = lane & 3;
    const int mat = lane >> 3, rowin = lane & 7;
    const int qr0 = wid * 16;          // QK: warp = 16 q-rows x 64 keys
    const int wm = (wid & 3) * 32;     // PV: warp = 32 rows x 64 cols
    const int wn = (wid >> 2) * 64;

    // Load Q tile (bf16, 16B chunks)
#pragma unroll
    for (int i = 0; i < 8; i++) {
        int idx = tid + i * 256;
        int r = idx >> 4, c8 = idx & 15;
        *(uint4*)(Qs + r * FQS + c8 * 8) = *(const uint4*)(Qb + r * LAT + c8 * 8);
    }
    if (tid < 128) { msh[tid] = -INFINITY; lsh[tid] = 0.f; }

    float oc[2][8][4];
#pragma unroll
    for (int mt = 0; mt < 2; mt++)
#pragma unroll
        for (int nt = 0; nt < 8; nt++)
#pragma unroll
            for (int i = 0; i < 4; i++) oc[mt][nt][i] = 0.f;

    // Fragment base addresses
    const uint32_t aq = smem_u32(Qs)
        + (uint32_t)((qr0 + (mat & 1) * 8 + rowin) * FQS + (mat >> 1) * 8) * 2;
    const uint32_t bk = smem_u32(KVs)
        + (uint32_t)(((mat >> 1) * 8 + rowin) * FQS + (mat & 1) * 8) * 2;
    const uint32_t ap = smem_u32(Ps)
        + (uint32_t)((wm + (mat & 1) * 8 + rowin) * FPS + (mat >> 1) * 8) * 2;
    const uint32_t bv = smem_u32(KVs)
        + (uint32_t)(((mat & 1) * 8 + rowin) * FQS + wn + (mat >> 1) * 8) * 2;

    __syncthreads();

    for (int t0 = 0; t0 < N2; t0 += FA_BN) {
        // --- Load K tile [64][FQS] ---
#pragma unroll
        for (int i = 0; i < 4; i++) {
            int idx = tid + i * 256;
            int r = idx >> 4, c8 = idx & 15;
            *(uint4*)(KVs + r * FQS + c8 * 8) =
                *(const uint4*)(Kb + (long)(t0 + r) * LAT + c8 * 8);
        }
        __syncthreads();

        // --- S = Q @ K^T, bf16 mma (8 ksteps of k16) ---
        float c[8][4];
#pragma unroll
        for (int nt = 0; nt < 8; nt++)
#pragma unroll
            for (int i = 0; i < 4; i++) c[nt][i] = 0.f;

#pragma unroll
        for (int ks = 0; ks < 8; ks++) {
            uint32_t af[4], bfr[8][2];
            ldsm4(af[0], af[1], af[2], af[3], aq + ks * 32);
#pragma unroll
            for (int p = 0; p < 4; p++)
                ldsm4(bfr[2 * p][0], bfr[2 * p][1], bfr[2 * p + 1][0], bfr[2 * p + 1][1],
                      bk + p * (16 * FQS * 2) + ks * 32);
#pragma unroll
            for (int nt = 0; nt < 8; nt++)
                mma16(c[nt], af, bfr[nt]);
        }

        // --- Stage S (fp32) ---
#pragma unroll
        for (int nt = 0; nt < 8; nt++) {
            int col = nt * 8 + 2 * t4;
            *(float2*)(Ssh + (qr0 + g)     * 68 + col) = make_float2(c[nt][0], c[nt][1]);
            *(float2*)(Ssh + (qr0 + g + 8) * 68 + col) = make_float2(c[nt][2], c[nt][3]);
        }
        __syncthreads();   // K consumed; S complete

        // --- Load V tile (overwrites K) ---
#pragma unroll
        for (int i = 0; i < 4; i++) {
            int idx = tid + i * 256;
            int r = idx >> 4, c8 = idx & 15;
            *(uint4*)(KVs + r * FQS + c8 * 8) =
                *(const uint4*)(Vb + (long)(t0 + r) * LAT + c8 * 8);
        }

        // --- Online softmax (fp32), P -> bf16 ---
        if (tid < 128) {
            float mold = msh[tid];
            float mnew = mold;
            float* srow = Ssh + tid * 68;
#pragma unroll
            for (int j = 0; j < 64; j++) mnew = fmaxf(mnew, srow[j]);
            float alpha = __expf(mold - mnew);
            float lsum = 0.f;
            bf16* prow = Ps + tid * FPS;
#pragma unroll
            for (int j = 0; j < 64; j += 2) {
                float e0 = __expf(srow[j]     - mnew);
                float e1 = __expf(srow[j + 1] - mnew);
                *(bf162*)(prow + j) = __floats2bfloat162_rn(e0, e1);
                lsum += e0 + e1;
            }
            lsh[tid] = lsh[tid] * alpha + lsum;
            msh[tid] = mnew;
            ash[tid] = alpha;
        }
        __syncthreads();

        // --- O = O*alpha + P @ V, bf16 mma (4 ksteps of k16) ---
#pragma unroll
        for (int mt = 0; mt < 2; mt++) {
            float al0 = ash[wm + mt * 16 + g];
            float al1 = ash[wm + mt * 16 + 8 + g];
#pragma unroll
            for (int nt = 0; nt < 8; nt++) {
                oc[mt][nt][0] *= al0; oc[mt][nt][1] *= al0;
                oc[mt][nt][2] *= al1; oc[mt][nt][3] *= al1;
            }
        }
#pragma unroll
        for (int ks = 0; ks < 4; ks++) {
            uint32_t pf[2][4], vf[8][2];
#pragma unroll
            for (int mt = 0; mt < 2; mt++)
                ldsm4(pf[mt][0], pf[mt][1], pf[mt][2], pf[mt][3],
                      ap + mt * (16 * FPS * 2) + ks * 32);
#pragma unroll
            for (int p = 0; p < 4; p++)
                ldsm4t(vf[2 * p][0], vf[2 * p][1], vf[2 * p + 1][0], vf[2 * p + 1][1],
                       bv + ks * (16 * FQS * 2) + p * 32);
#pragma unroll
            for (int mt = 0; mt < 2; mt++)
#pragma unroll
                for (int nt = 0; nt < 8; nt++)
                    mma16(oc[mt][nt], pf[mt], vf[nt]);
        }
        __syncthreads();
    }

    // --- Epilogue: divide by l, write bf16 ---
#pragma unroll
    for (int mt = 0; mt < 2; mt++) {
        int r0 = wm + mt * 16 + g;
        float inv0 = 1.f / lsh[r0];
        float inv1 = 1.f / lsh[r0 + 8];
        long row0 = (long)b * N1 + m0 + r0;
#pragma unroll
        for (int nt = 0; nt < 8; nt++) {
            int col = wn + nt * 8 + 2 * t4;
            *(bf162*)(O + row0 * LAT + col) =
                __floats2bfloat162_rn(oc[mt][nt][0] * inv0, oc[mt][nt][1] * inv0);
            *(bf162*)(O + (row0 + 8) * LAT + col) =
                __floats2bfloat162_rn(oc[mt][nt][2] * inv1, oc[mt][nt][3] * inv1);
        }
    }
}

// ---------------------------------------------------------------------------
// Host launcher
// ---------------------------------------------------------------------------
extern "C" void kernel_launch(void* const* d_in, const int* in_sizes, int n_in,
                              void* d_out, int out_size)
{
    const float* mainf = (const float*)d_in[0];
    const float* feat  = (const float*)d_in[1];
    const float* We1   = (const float*)d_in[2];
    const float* be1   = (const float*)d_in[3];
    const float* We2   = (const float*)d_in[4];
    const float* be2   = (const float*)d_in[5];
    const float* Wq    = (const float*)d_in[6];
    const float* bq    = (const float*)d_in[7];
    const float* Wk    = (const float*)d_in[8];
    const float* bk    = (const float*)d_in[9];
    const float* Wv    = (const float*)d_in[10];
    const float* bv    = (const float*)d_in[11];
    const float* Wd1   = (const float*)d_in[12];
    const float* bd1   = (const float*)d_in[13];
    const float* Wd2   = (const float*)d_in[14];
    const float* bd2   = (const float*)d_in[15];
    float* out = (float*)d_out;

    bf16 *p_mid, *p_m, *p_f, *p_q, *p_k, *p_v, *p_attn;
    float *wt_e1;
    bf16 *wb_e2, *wb_q, *wb_k, *wb_v, *wb_d1, *wb_d2;
    cudaGetSymbolAddress((void**)&p_mid,  g_mid);
    cudaGetSymbolAddress((void**)&p_m,    g_m);
    cudaGetSymbolAddress((void**)&p_f,    g_f);
    cudaGetSymbolAddress((void**)&p_q,    g_q);
    cudaGetSymbolAddress((void**)&p_k,    g_k);
    cudaGetSymbolAddress((void**)&p_v,    g_v);
    cudaGetSymbolAddress((void**)&p_attn, g_attn);
    cudaGetSymbolAddress((void**)&wt_e1, g_wt_e1);
    cudaGetSymbolAddress((void**)&wb_e2, g_wb_e2);
    cudaGetSymbolAddress((void**)&wb_q,  g_wb_q);
    cudaGetSymbolAddress((void**)&wb_k,  g_wb_k);
    cudaGetSymbolAddress((void**)&wb_v,  g_wb_v);
    cudaGetSymbolAddress((void**)&wb_d1, g_wb_d1);
    cudaGetSymbolAddress((void**)&wb_d2, g_wb_d2);

    const int e1_sm   = 3 * (128 + 256) * GPAD * sizeof(float);   // 165888
    const int gb256_sm = 3 * (128 + 256) * BPAD * 2;              // 165888
    const int gb128_sm = 3 * (128 + 128) * BPAD * 2;              // 110592
    const int fa_sm    = FA_SMEM_BYTES;                           // 107008
    cudaFuncSetAttribute(gemm_e1, cudaFuncAttributeMaxDynamicSharedMemorySize, e1_sm);
    cudaFuncSetAttribute(gemm_bf16<1, 128, 0>, cudaFuncAttributeMaxDynamicSharedMemorySize, gb128_sm);
    cudaFuncSetAttribute(gemm_bf16<0, 128, 0>, cudaFuncAttributeMaxDynamicSharedMemorySize, gb128_sm);
    cudaFuncSetAttribute(gemm_bf16<1, 256, 0>, cudaFuncAttributeMaxDynamicSharedMemorySize, gb256_sm);
    cudaFuncSetAttribute(gemm_bf16<2, 256, 1>, cudaFuncAttributeMaxDynamicSharedMemorySize, gb256_sm);
    cudaFuncSetAttribute(flash_attn_bf16, cudaFuncAttributeMaxDynamicSharedMemorySize, fa_sm);

    transpose_all<<<496, dim3(32, 8)>>>(We1, wt_e1, We2, wb_e2, Wq, wb_q,
                                        Wk, wb_k, Wv, wb_v, Wd1, wb_d1, Wd2, wb_d2);

    const int M = RTOT;
    // encode(main): tf32 stage-1 -> bf16 mid; bf16 stage-2 -> m
    gemm_e1<<<dim3(1, M / 128), 256, e1_sm>>>(mainf, wt_e1, be1, p_mid, M, MID, HH);
    gemm_bf16<1, 128, 0><<<dim3(1, M / 128), 256, gb128_sm>>>(p_mid, wb_e2, be2, p_m, M, LAT, MID);
    // encode(feature)
    gemm_e1<<<dim3(1, M / 128), 256, e1_sm>>>(feat, wt_e1, be1, p_mid, M, MID, HH);
    gemm_bf16<1, 128, 0><<<dim3(1, M / 128), 256, gb128_sm>>>(p_mid, wb_e2, be2, p_f, M, LAT, MID);
    // q, k, v (K = LAT = 128)
    gemm_bf16<0, 128, 0><<<dim3(1, M / 128), 256, gb128_sm>>>(p_m, wb_q, bq, p_q, M, LAT, LAT);
    gemm_bf16<0, 128, 0><<<dim3(1, M / 128), 256, gb128_sm>>>(p_f, wb_k, bk, p_k, M, LAT, LAT);
    gemm_bf16<0, 128, 0><<<dim3(1, M / 128), 256, gb128_sm>>>(p_f, wb_v, bv, p_v, M, LAT, LAT);
    // attention
    flash_attn_bf16<<<dim3(N1 / FA_BM, BB), 256, fa_sm>>>(p_q, p_k, p_v, p_attn);
    // decode
    gemm_bf16<1, 256, 0><<<dim3(1, M / 128), 256, gb256_sm>>>(p_attn, wb_d1, bd1, p_mid, M, MID, LAT);
    gemm_bf16<2, 256, 1><<<dim3(3, M / 128), 256, gb256_sm>>>(p_mid, wb_d2, bd2, out, M, HH, MID);
}

// round 13
// speedup vs baseline: 4.6888x; 1.2048x over previous
#include <cuda_runtime.h>
#include <cuda_bf16.h>
#include <math.h>
#include <cstdint>

// Problem dims
#define BB   16
#define N1   2048
#define N2   2048
#define HH   768
#define LAT  128
#define MID  256
#define RTOT (BB * N1)

typedef __nv_bfloat16  bf16;
typedef __nv_bfloat162 bf162;

// ---------------------------------------------------------------------------
// Scratch (device globals)
// ---------------------------------------------------------------------------
__device__ bf16 g_main_bf[RTOT * HH];
__device__ bf16 g_feat_bf[RTOT * HH];
__device__ bf16 g_mid [RTOT * MID];
__device__ bf16 g_m   [RTOT * LAT];
__device__ bf16 g_f   [RTOT * LAT];
__device__ bf16 g_q   [RTOT * LAT];
__device__ bf16 g_k   [RTOT * LAT];
__device__ bf16 g_v   [RTOT * LAT];
__device__ bf16 g_attn[RTOT * LAT];
__device__ bf16 g_wb_e1[MID * HH];
__device__ bf16 g_wb_e2[LAT * MID];
__device__ bf16 g_wb_q [LAT * LAT];
__device__ bf16 g_wb_k [LAT * LAT];
__device__ bf16 g_wb_v [LAT * LAT];
__device__ bf16 g_wb_d1[MID * LAT];
__device__ bf16 g_wb_d2[HH * MID];

// ---------------------------------------------------------------------------
// Helpers
// ---------------------------------------------------------------------------
__device__ __forceinline__ void mma16(float c[4], const uint32_t a[4], const uint32_t b[2]) {
    asm volatile(
        "mma.sync.aligned.m16n8k16.row.col.f32.bf16.bf16.f32 "
        "{%0,%1,%2,%3}, {%4,%5,%6,%7}, {%8,%9}, {%0,%1,%2,%3};"
        : "+f"(c[0]), "+f"(c[1]), "+f"(c[2]), "+f"(c[3])
        : "r"(a[0]), "r"(a[1]), "r"(a[2]), "r"(a[3]), "r"(b[0]), "r"(b[1]));
}
__device__ __forceinline__ uint32_t smem_u32(const void* p) {
    uint32_t a;
    asm("{ .reg .u64 t; cvta.to.shared.u64 t, %1; cvt.u32.u64 %0, t; }"
        : "=r"(a) : "l"(p));
    return a;
}
__device__ __forceinline__ void ldsm4(uint32_t& r0, uint32_t& r1, uint32_t& r2,
                                      uint32_t& r3, uint32_t addr) {
    asm volatile("ldmatrix.sync.aligned.m8n8.x4.shared.b16 {%0,%1,%2,%3}, [%4];"
                 : "=r"(r0), "=r"(r1), "=r"(r2), "=r"(r3) : "r"(addr));
}
__device__ __forceinline__ void ldsm4t(uint32_t& r0, uint32_t& r1, uint32_t& r2,
                                       uint32_t& r3, uint32_t addr) {
    asm volatile("ldmatrix.sync.aligned.m8n8.x4.trans.shared.b16 {%0,%1,%2,%3}, [%4];"
                 : "=r"(r0), "=r"(r1), "=r"(r2), "=r"(r3) : "r"(addr));
}
__device__ __forceinline__ void cpa16(uint32_t dst, const void* src) {
    asm volatile("cp.async.cg.shared.global [%0], [%1], 16;" :: "r"(dst), "l"(src));
}
#define CP_COMMIT() asm volatile("cp.async.commit_group;")
#define CP_WAIT1()  asm volatile("cp.async.wait_group 1;")
__device__ __forceinline__ uint32_t pkbf(float a, float b) {
    bf162 h = __floats2bfloat162_rn(a, b);
    return *(uint32_t*)&h;
}

// ---------------------------------------------------------------------------
// Input conversion: fp32 -> bf16, both inputs, vectorized
// ---------------------------------------------------------------------------
__global__ __launch_bounds__(256) void convert_inputs(
    const float* __restrict__ a, const float* __restrict__ b,
    bf16* __restrict__ ao, bf16* __restrict__ bo)
{
    long i = ((long)blockIdx.x * 256 + threadIdx.x) * 4;
    if (i >= (long)RTOT * HH) return;
    float4 va = *(const float4*)(a + i);
    float4 vb = *(const float4*)(b + i);
    *(bf162*)(ao + i)     = __floats2bfloat162_rn(va.x, va.y);
    *(bf162*)(ao + i + 2) = __floats2bfloat162_rn(va.z, va.w);
    *(bf162*)(bo + i)     = __floats2bfloat162_rn(vb.x, vb.y);
    *(bf162*)(bo + i + 2) = __floats2bfloat162_rn(vb.z, vb.w);
}

// ---------------------------------------------------------------------------
// Fused weight transpose -> bf16 [N,K]
// ---------------------------------------------------------------------------
__global__ void transpose_all(
    const float* __restrict__ We1, bf16* __restrict__ wb_e1,
    const float* __restrict__ We2, bf16* __restrict__ wb_e2,
    const float* __restrict__ Wq,  bf16* __restrict__ wb_q,
    const float* __restrict__ Wk,  bf16* __restrict__ wb_k,
    const float* __restrict__ Wv,  bf16* __restrict__ wb_v,
    const float* __restrict__ Wd1, bf16* __restrict__ wb_d1,
    const float* __restrict__ Wd2, bf16* __restrict__ wb_d2)
{
    __shared__ float t[32][33];
    int idx = blockIdx.x;
    const float* in; bf16* out; int K, N, l;
    if (idx < 192)      { in = We1; out = wb_e1; K = HH;  N = MID; l = idx; }
    else if (idx < 224) { in = We2; out = wb_e2; K = MID; N = LAT; l = idx - 192; }
    else if (idx < 240) { in = Wq;  out = wb_q;  K = LAT; N = LAT; l = idx - 224; }
    else if (idx < 256) { in = Wk;  out = wb_k;  K = LAT; N = LAT; l = idx - 240; }
    else if (idx < 272) { in = Wv;  out = wb_v;  K = LAT; N = LAT; l = idx - 256; }
    else if (idx < 304) { in = Wd1; out = wb_d1; K = LAT; N = MID; l = idx - 272; }
    else                { in = Wd2; out = wb_d2; K = MID; N = HH;  l = idx - 304; }
    int tx = N >> 5;
    int nx = (l % tx) * 32, kx = (l / tx) * 32;
    int x = threadIdx.x, y = threadIdx.y;
#pragma unroll
    for (int i = 0; i < 32; i += 8)
        t[y + i][x] = in[(long)(kx + y + i) * N + nx + x];
    __syncthreads();
#pragma unroll
    for (int i = 0; i < 32; i += 8)
        out[(long)(nx + y + i) * K + kx + x] = __float2bfloat16(t[x][y + i]);
}

// ---------------------------------------------------------------------------
// bf16 mma GEMM: C = act(A_bf16 @ Wt_bf16^T + bias)
// CTA 128xBN, BK=64 bf16, 3-stage cp.async, m16n8k16.
// ---------------------------------------------------------------------------
#define BPAD 72

template <int ACT, int BN, int OUT32>
__global__ __launch_bounds__(256) void gemm_bf16(
    const bf16* __restrict__ A, const bf16* __restrict__ Wt,
    const float* __restrict__ bias, void* __restrict__ Cv,
    int M, int N, int K)
{
    extern __shared__ char smraw[];
    bf16* smb = (bf16*)smraw;
    constexpr int STG_A = 128 * BPAD;
    constexpr int STG_B = BN * BPAD;
    constexpr int STG   = STG_A + STG_B;
    constexpr int NT    = BN / 32;

    const int tid = threadIdx.x;
    const int wid = tid >> 5, lane = tid & 31;
    const int g = lane >> 2, t4 = lane & 3;
    const int wm = (wid & 1) * 64;
    const int wn = (wid >> 1) * (BN / 4);
    const int m0 = blockIdx.y * 128, n0 = blockIdx.x * BN;

    float c[4][NT][4];
#pragma unroll
    for (int mt = 0; mt < 4; mt++)
#pragma unroll
        for (int nt = 0; nt < NT; nt++)
#pragma unroll
            for (int i = 0; i < 4; i++) c[mt][nt][i] = 0.f;

    const int nk = K >> 6;

    auto load_stage = [&](int kt, int s) {
        bf16* base = smb + s * STG;
#pragma unroll
        for (int i = 0; i < 4; i++) {
            int idx = tid + i * 256;
            int r = idx >> 3, c8 = idx & 7;
            cpa16(smem_u32(base + r * BPAD + c8 * 8),
                  A + (long)(m0 + r) * K + kt * 64 + c8 * 8);
        }
#pragma unroll
        for (int i = 0; i < BN / 32; i++) {
            int idx = tid + i * 256;
            int r = idx >> 3, c8 = idx & 7;
            cpa16(smem_u32(base + STG_A + r * BPAD + c8 * 8),
                  Wt + (long)(n0 + r) * K + kt * 64 + c8 * 8);
        }
    };

    const int mat = lane >> 3, rowin = lane & 7;
    const uint32_t a0 = smem_u32(smb)
        + (uint32_t)((wm + (mat & 1) * 8 + rowin) * BPAD + (mat >> 1) * 8) * 2;
    const uint32_t b0 = smem_u32(smb) + (uint32_t)STG_A * 2
        + (uint32_t)((wn + (mat >> 1) * 8 + rowin) * BPAD + (mat & 1) * 8) * 2;

    load_stage(0, 0); CP_COMMIT();
    load_stage(1, 1); CP_COMMIT();

    for (int kt = 0; kt < nk; kt++) {
        CP_WAIT1();
        __syncthreads();
        if (kt + 2 < nk) load_stage(kt + 2, (kt + 2) % 3);
        CP_COMMIT();

        int s = kt % 3;
        uint32_t ab = a0 + (uint32_t)(s * STG) * 2;
        uint32_t bb = b0 + (uint32_t)(s * STG) * 2;
#pragma unroll
        for (int ks = 0; ks < 4; ks++) {
            uint32_t af[4][4], bfr[NT][2];
#pragma unroll
            for (int mt = 0; mt < 4; mt++)
                ldsm4(af[mt][0], af[mt][1], af[mt][2], af[mt][3],
                      ab + mt * (16 * BPAD * 2) + ks * 32);
#pragma unroll
            for (int p = 0; p < NT / 2; p++)
                ldsm4(bfr[2 * p][0], bfr[2 * p][1], bfr[2 * p + 1][0], bfr[2 * p + 1][1],
                      bb + p * (16 * BPAD * 2) + ks * 32);
#pragma unroll
            for (int mt = 0; mt < 4; mt++)
#pragma unroll
                for (int nt = 0; nt < NT; nt++)
                    mma16(c[mt][nt], af[mt], bfr[nt]);
        }
    }

#pragma unroll
    for (int mt = 0; mt < 4; mt++) {
        int r0 = m0 + wm + mt * 16 + g;
#pragma unroll
        for (int nt = 0; nt < NT; nt++) {
            int col = n0 + wn + nt * 8 + 2 * t4;
            float2 bv = *(const float2*)(bias + col);
            float x0 = c[mt][nt][0] + bv.x;
            float x1 = c[mt][nt][1] + bv.y;
            float x2 = c[mt][nt][2] + bv.x;
            float x3 = c[mt][nt][3] + bv.y;
            if (ACT == 1) {
                x0 = fmaxf(x0, 0.f); x1 = fmaxf(x1, 0.f);
                x2 = fmaxf(x2, 0.f); x3 = fmaxf(x3, 0.f);
            }
            if (ACT == 2) {
                x0 = 1.f / (1.f + __expf(-x0)); x1 = 1.f / (1.f + __expf(-x1));
                x2 = 1.f / (1.f + __expf(-x2)); x3 = 1.f / (1.f + __expf(-x3));
            }
            if (OUT32) {
                float* C = (float*)Cv;
                *(float2*)(C + (long)r0 * N + col)       = make_float2(x0, x1);
                *(float2*)(C + (long)(r0 + 8) * N + col) = make_float2(x2, x3);
            } else {
                bf16* C = (bf16*)Cv;
                *(bf162*)(C + (long)r0 * N + col)       = __floats2bfloat162_rn(x0, x1);
                *(bf162*)(C + (long)(r0 + 8) * N + col) = __floats2bfloat162_rn(x2, x3);
            }
        }
    }
}

// ---------------------------------------------------------------------------
// Flash attention v3: register softmax, S->P fragment reuse, double-buffered
// cp.async K/V. Per block: 128 q-rows; per warp: 16 q-rows x all keys/d.
// ---------------------------------------------------------------------------
#define FA_BM 128
#define FA_BN 64
#define FQS   136
// smem: Qs [128][FQS] + 2 x KV buf [128][FQS] (K rows 0-63, V rows 64-127)
#define FA_SMEM_BYTES ((128 * FQS + 2 * 128 * FQS) * 2)

__global__ __launch_bounds__(256, 1) void flash_attn_bf16(
    const bf16* __restrict__ Q, const bf16* __restrict__ K,
    const bf16* __restrict__ V, bf16* __restrict__ O)
{
    extern __shared__ char smraw[];
    bf16* Qs  = (bf16*)smraw;                // [128][FQS]
    bf16* KVs = Qs + 128 * FQS;              // [2][128][FQS]

    const int tid = threadIdx.x;
    const int b   = blockIdx.y;
    const int m0  = blockIdx.x * FA_BM;

    const bf16* Qb = Q + ((long)b * N1 + m0) * LAT;
    const bf16* Kb = K + (long)b * N2 * LAT;
    const bf16* Vb = V + (long)b * N2 * LAT;

    const int wid = tid >> 5, lane = tid & 31;
    const int g = lane >> 2, t4 = lane & 3;
    const int mat = lane >> 3, rowin = lane & 7;
    const int qr0 = wid * 16;

    // Load Q tile
#pragma unroll
    for (int i = 0; i < 8; i++) {
        int idx = tid + i * 256;
        int r = idx >> 4, c8 = idx & 15;
        *(uint4*)(Qs + r * FQS + c8 * 8) = *(const uint4*)(Qb + r * LAT + c8 * 8);
    }

    // cp.async loader for KV tile t into buffer s
    auto loadKV = [&](int t, int s) {
        bf16* base = KVs + s * 128 * FQS;
#pragma unroll
        for (int i = 0; i < 4; i++) {
            int idx = tid + i * 256;
            int r = idx >> 4, c8 = idx & 15;
            cpa16(smem_u32(base + r * FQS + c8 * 8),
                  Kb + (long)(t * FA_BN + r) * LAT + c8 * 8);
        }
#pragma unroll
        for (int i = 0; i < 4; i++) {
            int idx = tid + i * 256;
            int r = idx >> 4, c8 = idx & 15;
            cpa16(smem_u32(base + (64 + r) * FQS + c8 * 8),
                  Vb + (long)(t * FA_BN + r) * LAT + c8 * 8);
        }
    };

    // Fragment bases
    const uint32_t aq = smem_u32(Qs)
        + (uint32_t)((qr0 + (mat & 1) * 8 + rowin) * FQS + (mat >> 1) * 8) * 2;
    const uint32_t bk0 = smem_u32(KVs)
        + (uint32_t)(((mat >> 1) * 8 + rowin) * FQS + (mat & 1) * 8) * 2;
    const uint32_t bv0 = smem_u32(KVs) + (uint32_t)(64 * FQS) * 2
        + (uint32_t)(((mat & 1) * 8 + rowin) * FQS + (mat >> 1) * 8) * 2;

    float m0r = -INFINITY, m1r = -INFINITY, l0 = 0.f, l1 = 0.f;
    float oc[16][4];
#pragma unroll
    for (int nt = 0; nt < 16; nt++)
#pragma unroll
        for (int i = 0; i < 4; i++) oc[nt][i] = 0.f;

    loadKV(0, 0); CP_COMMIT();
    loadKV(1, 1); CP_COMMIT();
    __syncthreads();   // Q tile visible

    const int NTILES = N2 / FA_BN;
    for (int t = 0; t < NTILES; t++) {
        CP_WAIT1();
        __syncthreads();

        int s = t & 1;
        uint32_t bk = bk0 + (uint32_t)(s * 128 * FQS) * 2;
        uint32_t bv = bv0 + (uint32_t)(s * 128 * FQS) * 2;

        // --- S = Q @ K^T (8 ksteps of k16, 64 keys) ---
        float c[8][4];
#pragma unroll
        for (int nt = 0; nt < 8; nt++)
#pragma unroll
            for (int i = 0; i < 4; i++) c[nt][i] = 0.f;

#pragma unroll
        for (int ks = 0; ks < 8; ks++) {
            uint32_t af[4], bfr[8][2];
            ldsm4(af[0], af[1], af[2], af[3], aq + ks * 32);
#pragma unroll
            for (int p = 0; p < 4; p++)
                ldsm4(bfr[2 * p][0], bfr[2 * p][1], bfr[2 * p + 1][0], bfr[2 * p + 1][1],
                      bk + p * (16 * FQS * 2) + ks * 32);
#pragma unroll
            for (int nt = 0; nt < 8; nt++)
                mma16(c[nt], af, bfr[nt]);
        }

        // --- Register online softmax (rows qr0+g and qr0+g+8) ---
        float mx0 = c[0][0], mx1 = c[0][2];
#pragma unroll
        for (int nt = 0; nt < 8; nt++) {
            mx0 = fmaxf(mx0, fmaxf(c[nt][0], c[nt][1]));
            mx1 = fmaxf(mx1, fmaxf(c[nt][2], c[nt][3]));
        }
        mx0 = fmaxf(mx0, __shfl_xor_sync(0xFFFFFFFFu, mx0, 1));
        mx0 = fmaxf(mx0, __shfl_xor_sync(0xFFFFFFFFu, mx0, 2));
        mx1 = fmaxf(mx1, __shfl_xor_sync(0xFFFFFFFFu, mx1, 1));
        mx1 = fmaxf(mx1, __shfl_xor_sync(0xFFFFFFFFu, mx1, 2));
        float mn0 = fmaxf(m0r, mx0), mn1 = fmaxf(m1r, mx1);
        float al0 = __expf(m0r - mn0), al1 = __expf(m1r - mn1);
        float s0 = 0.f, s1 = 0.f;
#pragma unroll
        for (int nt = 0; nt < 8; nt++) {
            float e0 = __expf(c[nt][0] - mn0);
            float e1 = __expf(c[nt][1] - mn0);
            float e2 = __expf(c[nt][2] - mn1);
            float e3 = __expf(c[nt][3] - mn1);
            c[nt][0] = e0; c[nt][1] = e1; c[nt][2] = e2; c[nt][3] = e3;
            s0 += e0 + e1; s1 += e2 + e3;
        }
        s0 += __shfl_xor_sync(0xFFFFFFFFu, s0, 1);
        s0 += __shfl_xor_sync(0xFFFFFFFFu, s0, 2);
        s1 += __shfl_xor_sync(0xFFFFFFFFu, s1, 1);
        s1 += __shfl_xor_sync(0xFFFFFFFFu, s1, 2);
        l0 = l0 * al0 + s0; l1 = l1 * al1 + s1;
        m0r = mn0; m1r = mn1;

        // Rescale O
#pragma unroll
        for (int nt = 0; nt < 16; nt++) {
            oc[nt][0] *= al0; oc[nt][1] *= al0;
            oc[nt][2] *= al1; oc[nt][3] *= al1;
        }

        // --- O += P @ V (4 ksteps of k16; P from S fragments directly) ---
#pragma unroll
        for (int ks = 0; ks < 4; ks++) {
            uint32_t pf[4];
            pf[0] = pkbf(c[2 * ks][0],     c[2 * ks][1]);
            pf[1] = pkbf(c[2 * ks][2],     c[2 * ks][3]);
            pf[2] = pkbf(c[2 * ks + 1][0], c[2 * ks + 1][1]);
            pf[3] = pkbf(c[2 * ks + 1][2], c[2 * ks + 1][3]);
            uint32_t vf[16][2];
#pragma unroll
            for (int p = 0; p < 8; p++)
                ldsm4t(vf[2 * p][0], vf[2 * p][1], vf[2 * p + 1][0], vf[2 * p + 1][1],
                       bv + ks * (16 * FQS * 2) + p * 32);
#pragma unroll
            for (int nt = 0; nt < 16; nt++)
                mma16(oc[nt], pf, vf[nt]);
        }
        __syncthreads();   // all warps done with buffer s before refill
        if (t + 2 < NTILES) loadKV(t + 2, s);
        CP_COMMIT();
    }

    // --- Epilogue ---
    float inv0 = 1.f / l0, inv1 = 1.f / l1;
    long row0 = (long)b * N1 + m0 + qr0 + g;
#pragma unroll
    for (int nt = 0; nt < 16; nt++) {
        int col = nt * 8 + 2 * t4;
        *(bf162*)(O + row0 * LAT + col) =
            __floats2bfloat162_rn(oc[nt][0] * inv0, oc[nt][1] * inv0);
        *(bf162*)(O + (row0 + 8) * LAT + col) =
            __floats2bfloat162_rn(oc[nt][2] * inv1, oc[nt][3] * inv1);
    }
}

// ---------------------------------------------------------------------------
// Host launcher
// ---------------------------------------------------------------------------
extern "C" void kernel_launch(void* const* d_in, const int* in_sizes, int n_in,
                              void* d_out, int out_size)
{
    const float* mainf = (const float*)d_in[0];
    const float* feat  = (const float*)d_in[1];
    const float* We1   = (const float*)d_in[2];
    const float* be1   = (const float*)d_in[3];
    const float* We2   = (const float*)d_in[4];
    const float* be2   = (const float*)d_in[5];
    const float* Wq    = (const float*)d_in[6];
    const float* bq    = (const float*)d_in[7];
    const float* Wk    = (const float*)d_in[8];
    const float* bk    = (const float*)d_in[9];
    const float* Wv    = (const float*)d_in[10];
    const float* bv    = (const float*)d_in[11];
    const float* Wd1   = (const float*)d_in[12];
    const float* bd1   = (const float*)d_in[13];
    const float* Wd2   = (const float*)d_in[14];
    const float* bd2   = (const float*)d_in[15];
    float* out = (float*)d_out;

    bf16 *p_main, *p_feat, *p_mid, *p_m, *p_f, *p_q, *p_k, *p_v, *p_attn;
    bf16 *wb_e1, *wb_e2, *wb_q, *wb_k, *wb_v, *wb_d1, *wb_d2;
    cudaGetSymbolAddress((void**)&p_main, g_main_bf);
    cudaGetSymbolAddress((void**)&p_feat, g_feat_bf);
    cudaGetSymbolAddress((void**)&p_mid,  g_mid);
    cudaGetSymbolAddress((void**)&p_m,    g_m);
    cudaGetSymbolAddress((void**)&p_f,    g_f);
    cudaGetSymbolAddress((void**)&p_q,    g_q);
    cudaGetSymbolAddress((void**)&p_k,    g_k);
    cudaGetSymbolAddress((void**)&p_v,    g_v);
    cudaGetSymbolAddress((void**)&p_attn, g_attn);
    cudaGetSymbolAddress((void**)&wb_e1, g_wb_e1);
    cudaGetSymbolAddress((void**)&wb_e2, g_wb_e2);
    cudaGetSymbolAddress((void**)&wb_q,  g_wb_q);
    cudaGetSymbolAddress((void**)&wb_k,  g_wb_k);
    cudaGetSymbolAddress((void**)&wb_v,  g_wb_v);
    cudaGetSymbolAddress((void**)&wb_d1, g_wb_d1);
    cudaGetSymbolAddress((void**)&wb_d2, g_wb_d2);

    const int gb256_sm = 3 * (128 + 256) * BPAD * 2;              // 165888
    const int gb128_sm = 3 * (128 + 128) * BPAD * 2;              // 110592
    const int fa_sm    = FA_SMEM_BYTES;                           // 104448
    cudaFuncSetAttribute(gemm_bf16<1, 128, 0>, cudaFuncAttributeMaxDynamicSharedMemorySize, gb128_sm);
    cudaFuncSetAttribute(gemm_bf16<0, 128, 0>, cudaFuncAttributeMaxDynamicSharedMemorySize, gb128_sm);
    cudaFuncSetAttribute(gemm_bf16<1, 256, 0>, cudaFuncAttributeMaxDynamicSharedMemorySize, gb256_sm);
    cudaFuncSetAttribute(gemm_bf16<2, 256, 1>, cudaFuncAttributeMaxDynamicSharedMemorySize, gb256_sm);
    cudaFuncSetAttribute(flash_attn_bf16, cudaFuncAttributeMaxDynamicSharedMemorySize, fa_sm);

    // Prep: input conversion + weight transpose
    convert_inputs<<<(RTOT * HH / 4 + 255) / 256, 256>>>(mainf, feat, p_main, p_feat);
    transpose_all<<<496, dim3(32, 8)>>>(We1, wb_e1, We2, wb_e2, Wq, wb_q,
                                        Wk, wb_k, Wv, wb_v, Wd1, wb_d1, Wd2, wb_d2);

    const int M = RTOT;
    // encode(main)
    gemm_bf16<1, 256, 0><<<dim3(1, M / 128), 256, gb256_sm>>>(p_main, wb_e1, be1, p_mid, M, MID, HH);
    gemm_bf16<1, 128, 0><<<dim3(1, M / 128), 256, gb128_sm>>>(p_mid, wb_e2, be2, p_m, M, LAT, MID);
    // encode(feature)
    gemm_bf16<1, 256, 0><<<dim3(1, M / 128), 256, gb256_sm>>>(p_feat, wb_e1, be1, p_mid, M, MID, HH);
    gemm_bf16<1, 128, 0><<<dim3(1, M / 128), 256, gb128_sm>>>(p_mid, wb_e2, be2, p_f, M, LAT, MID);
    // q, k, v
    gemm_bf16<0, 128, 0><<<dim3(1, M / 128), 256, gb128_sm>>>(p_m, wb_q, bq, p_q, M, LAT, LAT);
    gemm_bf16<0, 128, 0><<<dim3(1, M / 128), 256, gb128_sm>>>(p_f, wb_k, bk, p_k, M, LAT, LAT);
    gemm_bf16<0, 128, 0><<<dim3(1, M / 128), 256, gb128_sm>>>(p_f, wb_v, bv, p_v, M, LAT, LAT);
    // attention
    flash_attn_bf16<<<dim3(N1 / FA_BM, BB), 256, fa_sm>>>(p_q, p_k, p_v, p_attn);
    // decode
    gemm_bf16<1, 256, 0><<<dim3(1, M / 128), 256, gb256_sm>>>(p_attn, wb_d1, bd1, p_mid, M, MID, LAT);
    gemm_bf16<2, 256, 1><<<dim3(3, M / 128), 256, gb256_sm>>>(p_mid, wb_d2, bd2, out, M, HH, MID);
}

// round 14
// speedup vs baseline: 4.8851x; 1.0419x over previous
#include <cuda_runtime.h>
#include <cuda_bf16.h>
#include <math.h>
#include <cstdint>

// Problem dims
#define BB   16
#define N1   2048
#define N2   2048
#define HH   768
#define LAT  128
#define MID  256
#define RTOT (BB * N1)

typedef __nv_bfloat16  bf16;
typedef __nv_bfloat162 bf162;

// ---------------------------------------------------------------------------
// Scratch (device globals)
// ---------------------------------------------------------------------------
__device__ bf16 g_mid2[2 * RTOT * MID];   // [main | feat] hidden; also decode hidden
__device__ bf16 g_mf  [2 * RTOT * LAT];   // [m | f]
__device__ bf16 g_q   [RTOT * LAT];
__device__ bf16 g_kv  [RTOT * 256];       // interleaved: cols 0-127 K, 128-255 V
__device__ bf16 g_attn[RTOT * LAT];
__device__ bf16 g_wb_e1[MID * HH];
__device__ bf16 g_wb_e2[LAT * MID];
__device__ bf16 g_wb_q [LAT * LAT];
__device__ bf16 g_wb_kv[256 * LAT];       // rows 0-127 Wk^T, 128-255 Wv^T
__device__ bf16 g_wb_d1[MID * LAT];
__device__ bf16 g_wb_d2[HH * MID];
__device__ float g_bias_kv[256];

// ---------------------------------------------------------------------------
// Helpers
// ---------------------------------------------------------------------------
__device__ __forceinline__ void mma16(float c[4], const uint32_t a[4], const uint32_t b[2]) {
    asm volatile(
        "mma.sync.aligned.m16n8k16.row.col.f32.bf16.bf16.f32 "
        "{%0,%1,%2,%3}, {%4,%5,%6,%7}, {%8,%9}, {%0,%1,%2,%3};"
        : "+f"(c[0]), "+f"(c[1]), "+f"(c[2]), "+f"(c[3])
        : "r"(a[0]), "r"(a[1]), "r"(a[2]), "r"(a[3]), "r"(b[0]), "r"(b[1]));
}
__device__ __forceinline__ uint32_t smem_u32(const void* p) {
    uint32_t a;
    asm("{ .reg .u64 t; cvta.to.shared.u64 t, %1; cvt.u32.u64 %0, t; }"
        : "=r"(a) : "l"(p));
    return a;
}
__device__ __forceinline__ void ldsm4(uint32_t& r0, uint32_t& r1, uint32_t& r2,
                                      uint32_t& r3, uint32_t addr) {
    asm volatile("ldmatrix.sync.aligned.m8n8.x4.shared.b16 {%0,%1,%2,%3}, [%4];"
                 : "=r"(r0), "=r"(r1), "=r"(r2), "=r"(r3) : "r"(addr));
}
__device__ __forceinline__ void ldsm4t(uint32_t& r0, uint32_t& r1, uint32_t& r2,
                                       uint32_t& r3, uint32_t addr) {
    asm volatile("ldmatrix.sync.aligned.m8n8.x4.trans.shared.b16 {%0,%1,%2,%3}, [%4];"
                 : "=r"(r0), "=r"(r1), "=r"(r2), "=r"(r3) : "r"(addr));
}
__device__ __forceinline__ void cpa16(uint32_t dst, const void* src) {
    asm volatile("cp.async.cg.shared.global [%0], [%1], 16;" :: "r"(dst), "l"(src));
}
#define CP_COMMIT() asm volatile("cp.async.commit_group;")
#define CP_WAIT1()  asm volatile("cp.async.wait_group 1;")
__device__ __forceinline__ uint32_t pkbf(float a, float b) {
    bf162 h = __floats2bfloat162_rn(a, b);
    return *(uint32_t*)&h;
}

// ---------------------------------------------------------------------------
// Fused weight transpose -> bf16 [N,K]; K/V packed into wb_kv; bias_kv packed.
// ---------------------------------------------------------------------------
__global__ void transpose_all(
    const float* __restrict__ We1, bf16* __restrict__ wb_e1,
    const float* __restrict__ We2, bf16* __restrict__ wb_e2,
    const float* __restrict__ Wq,  bf16* __restrict__ wb_q,
    const float* __restrict__ Wk,
    const float* __restrict__ Wv,  bf16* __restrict__ wb_kv,
    const float* __restrict__ Wd1, bf16* __restrict__ wb_d1,
    const float* __restrict__ Wd2, bf16* __restrict__ wb_d2,
    const float* __restrict__ bk, const float* __restrict__ bv,
    float* __restrict__ bias_kv)
{
    __shared__ float t[32][33];
    int idx = blockIdx.x;
    int x = threadIdx.x, y = threadIdx.y;   // 32 x 8
    if (idx == 496) {                       // bias pack block
        int flat = y * 32 + x;
        bias_kv[flat] = (flat < 128) ? bk[flat] : bv[flat - 128];
        return;
    }
    const float* in; bf16* out; int K, N, l;
    if (idx < 192)      { in = We1; out = wb_e1; K = HH;  N = MID; l = idx; }
    else if (idx < 224) { in = We2; out = wb_e2; K = MID; N = LAT; l = idx - 192; }
    else if (idx < 240) { in = Wq;  out = wb_q;  K = LAT; N = LAT; l = idx - 224; }
    else if (idx < 256) { in = Wk;  out = wb_kv; K = LAT; N = LAT; l = idx - 240; }
    else if (idx < 272) { in = Wv;  out = wb_kv + 128 * LAT; K = LAT; N = LAT; l = idx - 256; }
    else if (idx < 304) { in = Wd1; out = wb_d1; K = LAT; N = MID; l = idx - 272; }
    else                { in = Wd2; out = wb_d2; K = MID; N = HH;  l = idx - 304; }
    int tx = N >> 5;
    int nx = (l % tx) * 32, kx = (l / tx) * 32;
#pragma unroll
    for (int i = 0; i < 32; i += 8)
        t[y + i][x] = in[(long)(kx + y + i) * N + nx + x];
    __syncthreads();
#pragma unroll
    for (int i = 0; i < 32; i += 8)
        out[(long)(nx + y + i) * K + kx + x] = __float2bfloat16(t[x][y + i]);
}

// ---------------------------------------------------------------------------
// bf16 mma GEMM: C = act(A_bf16 @ Wt_bf16^T + bias)
// CTA 128xBN, BK=64 bf16, 3-stage cp.async, m16n8k16.
// ---------------------------------------------------------------------------
#define BPAD 72

template <int ACT, int BN, int OUT32>
__global__ __launch_bounds__(256) void gemm_bf16(
    const bf16* __restrict__ A, const bf16* __restrict__ Wt,
    const float* __restrict__ bias, void* __restrict__ Cv,
    int M, int N, int K)
{
    extern __shared__ char smraw[];
    bf16* smb = (bf16*)smraw;
    constexpr int STG_A = 128 * BPAD;
    constexpr int STG_B = BN * BPAD;
    constexpr int STG   = STG_A + STG_B;
    constexpr int NT    = BN / 32;

    const int tid = threadIdx.x;
    const int wid = tid >> 5, lane = tid & 31;
    const int g = lane >> 2, t4 = lane & 3;
    const int wm = (wid & 1) * 64;
    const int wn = (wid >> 1) * (BN / 4);
    const int m0 = blockIdx.y * 128, n0 = blockIdx.x * BN;

    float c[4][NT][4];
#pragma unroll
    for (int mt = 0; mt < 4; mt++)
#pragma unroll
        for (int nt = 0; nt < NT; nt++)
#pragma unroll
            for (int i = 0; i < 4; i++) c[mt][nt][i] = 0.f;

    const int nk = K >> 6;

    auto load_stage = [&](int kt, int s) {
        bf16* base = smb + s * STG;
#pragma unroll
        for (int i = 0; i < 4; i++) {
            int idx = tid + i * 256;
            int r = idx >> 3, c8 = idx & 7;
            cpa16(smem_u32(base + r * BPAD + c8 * 8),
                  A + (long)(m0 + r) * K + kt * 64 + c8 * 8);
        }
#pragma unroll
        for (int i = 0; i < BN / 32; i++) {
            int idx = tid + i * 256;
            int r = idx >> 3, c8 = idx & 7;
            cpa16(smem_u32(base + STG_A + r * BPAD + c8 * 8),
                  Wt + (long)(n0 + r) * K + kt * 64 + c8 * 8);
        }
    };

    const int mat = lane >> 3, rowin = lane & 7;
    const uint32_t a0 = smem_u32(smb)
        + (uint32_t)((wm + (mat & 1) * 8 + rowin) * BPAD + (mat >> 1) * 8) * 2;
    const uint32_t b0 = smem_u32(smb) + (uint32_t)STG_A * 2
        + (uint32_t)((wn + (mat >> 1) * 8 + rowin) * BPAD + (mat & 1) * 8) * 2;

    load_stage(0, 0); CP_COMMIT();
    load_stage(1, 1); CP_COMMIT();

    for (int kt = 0; kt < nk; kt++) {
        CP_WAIT1();
        __syncthreads();
        if (kt + 2 < nk) load_stage(kt + 2, (kt + 2) % 3);
        CP_COMMIT();

        int s = kt % 3;
        uint32_t ab = a0 + (uint32_t)(s * STG) * 2;
        uint32_t bb = b0 + (uint32_t)(s * STG) * 2;
#pragma unroll
        for (int ks = 0; ks < 4; ks++) {
            uint32_t af[4][4], bfr[NT][2];
#pragma unroll
            for (int mt = 0; mt < 4; mt++)
                ldsm4(af[mt][0], af[mt][1], af[mt][2], af[mt][3],
                      ab + mt * (16 * BPAD * 2) + ks * 32);
#pragma unroll
            for (int p = 0; p < NT / 2; p++)
                ldsm4(bfr[2 * p][0], bfr[2 * p][1], bfr[2 * p + 1][0], bfr[2 * p + 1][1],
                      bb + p * (16 * BPAD * 2) + ks * 32);
#pragma unroll
            for (int mt = 0; mt < 4; mt++)
#pragma unroll
                for (int nt = 0; nt < NT; nt++)
                    mma16(c[mt][nt], af[mt], bfr[nt]);
        }
    }

#pragma unroll
    for (int mt = 0; mt < 4; mt++) {
        int r0 = m0 + wm + mt * 16 + g;
#pragma unroll
        for (int nt = 0; nt < NT; nt++) {
            int col = n0 + wn + nt * 8 + 2 * t4;
            float2 bv = *(const float2*)(bias + col);
            float x0 = c[mt][nt][0] + bv.x;
            float x1 = c[mt][nt][1] + bv.y;
            float x2 = c[mt][nt][2] + bv.x;
            float x3 = c[mt][nt][3] + bv.y;
            if (ACT == 1) {
                x0 = fmaxf(x0, 0.f); x1 = fmaxf(x1, 0.f);
                x2 = fmaxf(x2, 0.f); x3 = fmaxf(x3, 0.f);
            }
            if (ACT == 2) {
                x0 = 1.f / (1.f + __expf(-x0)); x1 = 1.f / (1.f + __expf(-x1));
                x2 = 1.f / (1.f + __expf(-x2)); x3 = 1.f / (1.f + __expf(-x3));
            }
            if (OUT32) {
                float* C = (float*)Cv;
                *(float2*)(C + (long)r0 * N + col)       = make_float2(x0, x1);
                *(float2*)(C + (long)(r0 + 8) * N + col) = make_float2(x2, x3);
            } else {
                bf16* C = (bf16*)Cv;
                *(bf162*)(C + (long)r0 * N + col)       = __floats2bfloat162_rn(x0, x1);
                *(bf162*)(C + (long)(r0 + 8) * N + col) = __floats2bfloat162_rn(x2, x3);
            }
        }
    }
}

// ---------------------------------------------------------------------------
// Stage-1 GEMM, fused fp32->bf16 on A: C_bf16 = relu(A_fp32 @ Wt_bf16^T + b)
// A: LDG fp32 -> regs -> bf16 STS (2-buffer). B: 3-stage cp.async. BN=256.
// ---------------------------------------------------------------------------
__global__ __launch_bounds__(256) void gemm_e1f(
    const float* __restrict__ A, const bf16* __restrict__ Wt,
    const float* __restrict__ bias, bf16* __restrict__ C,
    int M, int N, int K)
{
    extern __shared__ char smraw[];
    bf16* smb = (bf16*)smraw;
    constexpr int BN = 256;
    constexpr int STG_A = 128 * BPAD;
    constexpr int STG_B = BN * BPAD;
    constexpr int NT = 8;
    bf16* Asm = smb;                 // 2 stages
    bf16* Bsm = smb + 2 * STG_A;     // 3 stages

    const int tid = threadIdx.x;
    const int wid = tid >> 5, lane = tid & 31;
    const int g = lane >> 2, t4 = lane & 3;
    const int wm = (wid & 1) * 64;
    const int wn = (wid >> 1) * 64;
    const int m0 = blockIdx.y * 128, n0 = blockIdx.x * BN;

    float c[4][NT][4];
#pragma unroll
    for (int mt = 0; mt < 4; mt++)
#pragma unroll
        for (int nt = 0; nt < NT; nt++)
#pragma unroll
            for (int i = 0; i < 4; i++) c[mt][nt][i] = 0.f;

    const int nk = K >> 6;          // 12 for K=768

    const int arow = tid >> 1, ahalf = (tid & 1) * 32;
    float4 ar[8];
    auto ldA = [&](int kt) {
        const float* Ar = A + (long)(m0 + arow) * K + kt * 64 + ahalf;
#pragma unroll
        for (int i = 0; i < 8; i++) ar[i] = *(const float4*)(Ar + i * 4);
    };
    auto stA = [&](int buf) {
        bf16* d = Asm + buf * STG_A + arow * BPAD + ahalf;
#pragma unroll
        for (int i = 0; i < 4; i++) {
            uint4 u;
            u.x = pkbf(ar[2 * i].x,     ar[2 * i].y);
            u.y = pkbf(ar[2 * i].z,     ar[2 * i].w);
            u.z = pkbf(ar[2 * i + 1].x, ar[2 * i + 1].y);
            u.w = pkbf(ar[2 * i + 1].z, ar[2 * i + 1].w);
            *(uint4*)(d + i * 8) = u;
        }
    };
    auto loadB = [&](int kt, int s) {
        bf16* base = Bsm + s * STG_B;
#pragma unroll
        for (int i = 0; i < 8; i++) {
            int idx = tid + i * 256;
            int r = idx >> 3, c8 = idx & 7;
            cpa16(smem_u32(base + r * BPAD + c8 * 8),
                  Wt + (long)(n0 + r) * K + kt * 64 + c8 * 8);
        }
    };

    const int mat = lane >> 3, rowin = lane & 7;
    const uint32_t a0 = smem_u32(Asm)
        + (uint32_t)((wm + (mat & 1) * 8 + rowin) * BPAD + (mat >> 1) * 8) * 2;
    const uint32_t b0 = smem_u32(Bsm)
        + (uint32_t)((wn + (mat >> 1) * 8 + rowin) * BPAD + (mat & 1) * 8) * 2;

    ldA(0);
    loadB(0, 0); CP_COMMIT();
    loadB(1, 1); CP_COMMIT();
    stA(0);

    for (int kt = 0; kt < nk; kt++) {
        if (kt + 1 < nk) ldA(kt + 1);
        CP_WAIT1();
        __syncthreads();
        if (kt + 2 < nk) loadB(kt + 2, (kt + 2) % 3);
        CP_COMMIT();

        uint32_t ab = a0 + (uint32_t)((kt & 1) * STG_A) * 2;
        uint32_t bb = b0 + (uint32_t)((kt % 3) * STG_B) * 2;
#pragma unroll
        for (int ks = 0; ks < 4; ks++) {
            uint32_t af[4][4], bfr[NT][2];
#pragma unroll
            for (int mt = 0; mt < 4; mt++)
                ldsm4(af[mt][0], af[mt][1], af[mt][2], af[mt][3],
                      ab + mt * (16 * BPAD * 2) + ks * 32);
#pragma unroll
            for (int p = 0; p < NT / 2; p++)
                ldsm4(bfr[2 * p][0], bfr[2 * p][1], bfr[2 * p + 1][0], bfr[2 * p + 1][1],
                      bb + p * (16 * BPAD * 2) + ks * 32);
#pragma unroll
            for (int mt = 0; mt < 4; mt++)
#pragma unroll
                for (int nt = 0; nt < NT; nt++)
                    mma16(c[mt][nt], af[mt], bfr[nt]);
        }
        if (kt + 1 < nk) stA((kt + 1) & 1);
    }

#pragma unroll
    for (int mt = 0; mt < 4; mt++) {
        int r0 = m0 + wm + mt * 16 + g;
#pragma unroll
        for (int nt = 0; nt < NT; nt++) {
            int col = n0 + wn + nt * 8 + 2 * t4;
            float2 bv = *(const float2*)(bias + col);
            float x0 = fmaxf(c[mt][nt][0] + bv.x, 0.f);
            float x1 = fmaxf(c[mt][nt][1] + bv.y, 0.f);
            float x2 = fmaxf(c[mt][nt][2] + bv.x, 0.f);
            float x3 = fmaxf(c[mt][nt][3] + bv.y, 0.f);
            *(bf162*)(C + (long)r0 * N + col)       = __floats2bfloat162_rn(x0, x1);
            *(bf162*)(C + (long)(r0 + 8) * N + col) = __floats2bfloat162_rn(x2, x3);
        }
    }
}

// ---------------------------------------------------------------------------
// Flash attention: register softmax, S->P fragment reuse, double-buffered
// cp.async K/V from packed g_kv (stride 256), Q fragments preloaded.
// ---------------------------------------------------------------------------
#define FA_BM 128
#define FA_BN 64
#define FQS   136
#define FA_SMEM_BYTES ((128 * FQS + 2 * 128 * FQS) * 2)

__global__ __launch_bounds__(256, 1) void flash_attn_bf16(
    const bf16* __restrict__ Q, const bf16* __restrict__ KV,
    bf16* __restrict__ O)
{
    extern __shared__ char smraw[];
    bf16* Qs  = (bf16*)smraw;                // [128][FQS]
    bf16* KVs = Qs + 128 * FQS;              // [2][128][FQS]

    const int tid = threadIdx.x;
    const int b   = blockIdx.y;
    const int m0  = blockIdx.x * FA_BM;

    const bf16* Qb = Q + ((long)b * N1 + m0) * LAT;
    const bf16* Kb = KV + (long)b * N2 * 256;       // cols 0-127 K
    const bf16* Vb = Kb + 128;                      // cols 128-255 V

    const int wid = tid >> 5, lane = tid & 31;
    const int g = lane >> 2, t4 = lane & 3;
    const int mat = lane >> 3, rowin = lane & 7;
    const int qr0 = wid * 16;

    // Load Q tile
#pragma unroll
    for (int i = 0; i < 8; i++) {
        int idx = tid + i * 256;
        int r = idx >> 4, c8 = idx & 15;
        *(uint4*)(Qs + r * FQS + c8 * 8) = *(const uint4*)(Qb + r * LAT + c8 * 8);
    }

    auto loadKV = [&](int t, int s) {
        bf16* base = KVs + s * 128 * FQS;
#pragma unroll
        for (int i = 0; i < 4; i++) {
            int idx = tid + i * 256;
            int r = idx >> 4, c8 = idx & 15;
            cpa16(smem_u32(base + r * FQS + c8 * 8),
                  Kb + (long)(t * FA_BN + r) * 256 + c8 * 8);
        }
#pragma unroll
        for (int i = 0; i < 4; i++) {
            int idx = tid + i * 256;
            int r = idx >> 4, c8 = idx & 15;
            cpa16(smem_u32(base + (64 + r) * FQS + c8 * 8),
                  Vb + (long)(t * FA_BN + r) * 256 + c8 * 8);
        }
    };

    const uint32_t aq = smem_u32(Qs)
        + (uint32_t)((qr0 + (mat & 1) * 8 + rowin) * FQS + (mat >> 1) * 8) * 2;
    const uint32_t bk0 = smem_u32(KVs)
        + (uint32_t)(((mat >> 1) * 8 + rowin) * FQS + (mat & 1) * 8) * 2;
    const uint32_t bv0 = smem_u32(KVs) + (uint32_t)(64 * FQS) * 2
        + (uint32_t)(((mat & 1) * 8 + rowin) * FQS + (mat >> 1) * 8) * 2;

    float m0r = -INFINITY, m1r = -INFINITY, l0 = 0.f, l1 = 0.f;
    float oc[16][4];
#pragma unroll
    for (int nt = 0; nt < 16; nt++)
#pragma unroll
        for (int i = 0; i < 4; i++) oc[nt][i] = 0.f;

    loadKV(0, 0); CP_COMMIT();
    loadKV(1, 1); CP_COMMIT();
    __syncthreads();   // Q visible

    // Preload all Q fragments (K=128 -> 8 ksteps)
    uint32_t qf[8][4];
#pragma unroll
    for (int ks = 0; ks < 8; ks++)
        ldsm4(qf[ks][0], qf[ks][1], qf[ks][2], qf[ks][3], aq + ks * 32);

    const int NTILES = N2 / FA_BN;
    for (int t = 0; t < NTILES; t++) {
        CP_WAIT1();
        __syncthreads();

        int s = t & 1;
        uint32_t bk = bk0 + (uint32_t)(s * 128 * FQS) * 2;
        uint32_t bv = bv0 + (uint32_t)(s * 128 * FQS) * 2;

        // --- S = Q @ K^T ---
        float c[8][4];
#pragma unroll
        for (int nt = 0; nt < 8; nt++)
#pragma unroll
            for (int i = 0; i < 4; i++) c[nt][i] = 0.f;

#pragma unroll
        for (int ks = 0; ks < 8; ks++) {
            uint32_t bfr[8][2];
#pragma unroll
            for (int p = 0; p < 4; p++)
                ldsm4(bfr[2 * p][0], bfr[2 * p][1], bfr[2 * p + 1][0], bfr[2 * p + 1][1],
                      bk + p * (16 * FQS * 2) + ks * 32);
#pragma unroll
            for (int nt = 0; nt < 8; nt++)
                mma16(c[nt], qf[ks], bfr[nt]);
        }

        // --- Register online softmax ---
        float mx0 = c[0][0], mx1 = c[0][2];
#pragma unroll
        for (int nt = 0; nt < 8; nt++) {
            mx0 = fmaxf(mx0, fmaxf(c[nt][0], c[nt][1]));
            mx1 = fmaxf(mx1, fmaxf(c[nt][2], c[nt][3]));
        }
        mx0 = fmaxf(mx0, __shfl_xor_sync(0xFFFFFFFFu, mx0, 1));
        mx0 = fmaxf(mx0, __shfl_xor_sync(0xFFFFFFFFu, mx0, 2));
        mx1 = fmaxf(mx1, __shfl_xor_sync(0xFFFFFFFFu, mx1, 1));
        mx1 = fmaxf(mx1, __shfl_xor_sync(0xFFFFFFFFu, mx1, 2));
        float mn0 = fmaxf(m0r, mx0), mn1 = fmaxf(m1r, mx1);
        float al0 = __expf(m0r - mn0), al1 = __expf(m1r - mn1);
        float s0 = 0.f, s1 = 0.f;
#pragma unroll
        for (int nt = 0; nt < 8; nt++) {
            float e0 = __expf(c[nt][0] - mn0);
            float e1 = __expf(c[nt][1] - mn0);
            float e2 = __expf(c[nt][2] - mn1);
            float e3 = __expf(c[nt][3] - mn1);
            c[nt][0] = e0; c[nt][1] = e1; c[nt][2] = e2; c[nt][3] = e3;
            s0 += e0 + e1; s1 += e2 + e3;
        }
        s0 += __shfl_xor_sync(0xFFFFFFFFu, s0, 1);
        s0 += __shfl_xor_sync(0xFFFFFFFFu, s0, 2);
        s1 += __shfl_xor_sync(0xFFFFFFFFu, s1, 1);
        s1 += __shfl_xor_sync(0xFFFFFFFFu, s1, 2);
        l0 = l0 * al0 + s0; l1 = l1 * al1 + s1;
        m0r = mn0; m1r = mn1;

#pragma unroll
        for (int nt = 0; nt < 16; nt++) {
            oc[nt][0] *= al0; oc[nt][1] *= al0;
            oc[nt][2] *= al1; oc[nt][3] *= al1;
        }

        // --- O += P @ V ---
#pragma unroll
        for (int ks = 0; ks < 4; ks++) {
            uint32_t pf[4];
            pf[0] = pkbf(c[2 * ks][0],     c[2 * ks][1]);
            pf[1] = pkbf(c[2 * ks][2],     c[2 * ks][3]);
            pf[2] = pkbf(c[2 * ks + 1][0], c[2 * ks + 1][1]);
            pf[3] = pkbf(c[2 * ks + 1][2], c[2 * ks + 1][3]);
            uint32_t vf[16][2];
#pragma unroll
            for (int p = 0; p < 8; p++)
                ldsm4t(vf[2 * p][0], vf[2 * p][1], vf[2 * p + 1][0], vf[2 * p + 1][1],
                       bv + ks * (16 * FQS * 2) + p * 32);
#pragma unroll
            for (int nt = 0; nt < 16; nt++)
                mma16(oc[nt], pf, vf[nt]);
        }
        __syncthreads();
        if (t + 2 < NTILES) loadKV(t + 2, s);
        CP_COMMIT();
    }

    // --- Epilogue ---
    float inv0 = 1.f / l0, inv1 = 1.f / l1;
    long row0 = (long)b * N1 + m0 + qr0 + g;
#pragma unroll
    for (int nt = 0; nt < 16; nt++) {
        int col = nt * 8 + 2 * t4;
        *(bf162*)(O + row0 * LAT + col) =
            __floats2bfloat162_rn(oc[nt][0] * inv0, oc[nt][1] * inv0);
        *(bf162*)(O + (row0 + 8) * LAT + col) =
            __floats2bfloat162_rn(oc[nt][2] * inv1, oc[nt][3] * inv1);
    }
}

// ---------------------------------------------------------------------------
// Host launcher
// ---------------------------------------------------------------------------
extern "C" void kernel_launch(void* const* d_in, const int* in_sizes, int n_in,
                              void* d_out, int out_size)
{
    const float* mainf = (const float*)d_in[0];
    const float* feat  = (const float*)d_in[1];
    const float* We1   = (const float*)d_in[2];
    const float* be1   = (const float*)d_in[3];
    const float* We2   = (const float*)d_in[4];
    const float* be2   = (const float*)d_in[5];
    const float* Wq    = (const float*)d_in[6];
    const float* bq    = (const float*)d_in[7];
    const float* Wk    = (const float*)d_in[8];
    const float* bk    = (const float*)d_in[9];
    const float* Wv    = (const float*)d_in[10];
    const float* bv    = (const float*)d_in[11];
    const float* Wd1   = (const float*)d_in[12];
    const float* bd1   = (const float*)d_in[13];
    const float* Wd2   = (const float*)d_in[14];
    const float* bd2   = (const float*)d_in[15];
    float* out = (float*)d_out;

    bf16 *p_mid2, *p_mf, *p_q, *p_kv, *p_attn;
    bf16 *wb_e1, *wb_e2, *wb_q, *wb_kv, *wb_d1, *wb_d2;
    float* bias_kv;
    cudaGetSymbolAddress((void**)&p_mid2, g_mid2);
    cudaGetSymbolAddress((void**)&p_mf,   g_mf);
    cudaGetSymbolAddress((void**)&p_q,    g_q);
    cudaGetSymbolAddress((void**)&p_kv,   g_kv);
    cudaGetSymbolAddress((void**)&p_attn, g_attn);
    cudaGetSymbolAddress((void**)&wb_e1, g_wb_e1);
    cudaGetSymbolAddress((void**)&wb_e2, g_wb_e2);
    cudaGetSymbolAddress((void**)&wb_q,  g_wb_q);
    cudaGetSymbolAddress((void**)&wb_kv, g_wb_kv);
    cudaGetSymbolAddress((void**)&wb_d1, g_wb_d1);
    cudaGetSymbolAddress((void**)&wb_d2, g_wb_d2);
    cudaGetSymbolAddress((void**)&bias_kv, g_bias_kv);

    const int gb256_sm = 3 * (128 + 256) * BPAD * 2;              // 165888
    const int gb128_sm = 3 * (128 + 128) * BPAD * 2;              // 110592
    const int e1f_sm   = (2 * 128 + 3 * 256) * BPAD * 2;          // 147456
    const int fa_sm    = FA_SMEM_BYTES;                           // 104448
    cudaFuncSetAttribute(gemm_bf16<1, 128, 0>, cudaFuncAttributeMaxDynamicSharedMemorySize, gb128_sm);
    cudaFuncSetAttribute(gemm_bf16<0, 128, 0>, cudaFuncAttributeMaxDynamicSharedMemorySize, gb128_sm);
    cudaFuncSetAttribute(gemm_bf16<0, 256, 0>, cudaFuncAttributeMaxDynamicSharedMemorySize, gb256_sm);
    cudaFuncSetAttribute(gemm_bf16<1, 256, 0>, cudaFuncAttributeMaxDynamicSharedMemorySize, gb256_sm);
    cudaFuncSetAttribute(gemm_bf16<2, 256, 1>, cudaFuncAttributeMaxDynamicSharedMemorySize, gb256_sm);
    cudaFuncSetAttribute(gemm_e1f, cudaFuncAttributeMaxDynamicSharedMemorySize, e1f_sm);
    cudaFuncSetAttribute(flash_attn_bf16, cudaFuncAttributeMaxDynamicSharedMemorySize, fa_sm);

    transpose_all<<<497, dim3(32, 8)>>>(We1, wb_e1, We2, wb_e2, Wq, wb_q,
                                        Wk, Wv, wb_kv, Wd1, wb_d1, Wd2, wb_d2,
                                        bk, bv, bias_kv);

    const int M = RTOT;
    // encode stage 1 (fused fp32->bf16)
    gemm_e1f<<<dim3(1, M / 128), 256, e1f_sm>>>(mainf, wb_e1, be1, p_mid2, M, MID, HH);
    gemm_e1f<<<dim3(1, M / 128), 256, e1f_sm>>>(feat, wb_e1, be1, p_mid2 + (long)M * MID, M, MID, HH);
    // encode stage 2, both halves in one launch (M = 65536)
    gemm_bf16<1, 128, 0><<<dim3(1, 2 * M / 128), 256, gb128_sm>>>(p_mid2, wb_e2, be2, p_mf, 2 * M, LAT, MID);
    // q (from m) and fused k+v (from f)
    gemm_bf16<0, 128, 0><<<dim3(1, M / 128), 256, gb128_sm>>>(p_mf, wb_q, bq, p_q, M, LAT, LAT);
    gemm_bf16<0, 256, 0><<<dim3(1, M / 128), 256, gb256_sm>>>(p_mf + (long)M * LAT, wb_kv, bias_kv, p_kv, M, 256, LAT);
    // attention
    flash_attn_bf16<<<dim3(N1 / FA_BM, BB), 256, fa_sm>>>(p_q, p_kv, p_attn);
    // decode
    gemm_bf16<1, 256, 0><<<dim3(1, M / 128), 256, gb256_sm>>>(p_attn, wb_d1, bd1, p_mid2, M, MID, LAT);
    gemm_bf16<2, 256, 1><<<dim3(3, M / 128), 256, gb256_sm>>>(p_mid2, wb_d2, bd2, out, M, HH, MID);
}

// round 15
// speedup vs baseline: 4.9633x; 1.0160x over previous
#include <cuda_runtime.h>
#include <cuda_bf16.h>
#include <math.h>
#include <cstdint>

// Problem dims
#define BB   16
#define N1   2048
#define N2   2048
#define HH   768
#define LAT  128
#define MID  256
#define RTOT (BB * N1)

typedef __nv_bfloat16  bf16;
typedef __nv_bfloat162 bf162;

// ---------------------------------------------------------------------------
// Scratch (device globals)
// ---------------------------------------------------------------------------
__device__ bf16 g_mid2[2 * RTOT * MID];   // [main | feat] hidden; also decode hidden
__device__ bf16 g_mf  [2 * RTOT * LAT];   // [m | f]
__device__ bf16 g_q   [RTOT * LAT];
__device__ bf16 g_kv  [RTOT * 256];       // interleaved: cols 0-127 K, 128-255 V
__device__ bf16 g_attn[RTOT * LAT];
__device__ bf16 g_wb_e1[MID * HH];
__device__ bf16 g_wb_e2[LAT * MID];
__device__ bf16 g_wb_q [LAT * LAT];
__device__ bf16 g_wb_kv[256 * LAT];       // rows 0-127 Wk^T, 128-255 Wv^T
__device__ bf16 g_wb_d1[MID * LAT];
__device__ bf16 g_wb_d2[HH * MID];
__device__ float g_bias_kv[256];

// ---------------------------------------------------------------------------
// Helpers
// ---------------------------------------------------------------------------
__device__ __forceinline__ void mma16(float c[4], const uint32_t a[4], const uint32_t b[2]) {
    asm volatile(
        "mma.sync.aligned.m16n8k16.row.col.f32.bf16.bf16.f32 "
        "{%0,%1,%2,%3}, {%4,%5,%6,%7}, {%8,%9}, {%0,%1,%2,%3};"
        : "+f"(c[0]), "+f"(c[1]), "+f"(c[2]), "+f"(c[3])
        : "r"(a[0]), "r"(a[1]), "r"(a[2]), "r"(a[3]), "r"(b[0]), "r"(b[1]));
}
__device__ __forceinline__ uint32_t smem_u32(const void* p) {
    uint32_t a;
    asm("{ .reg .u64 t; cvta.to.shared.u64 t, %1; cvt.u32.u64 %0, t; }"
        : "=r"(a) : "l"(p));
    return a;
}
__device__ __forceinline__ void ldsm4(uint32_t& r0, uint32_t& r1, uint32_t& r2,
                                      uint32_t& r3, uint32_t addr) {
    asm volatile("ldmatrix.sync.aligned.m8n8.x4.shared.b16 {%0,%1,%2,%3}, [%4];"
                 : "=r"(r0), "=r"(r1), "=r"(r2), "=r"(r3) : "r"(addr));
}
__device__ __forceinline__ void ldsm4t(uint32_t& r0, uint32_t& r1, uint32_t& r2,
                                       uint32_t& r3, uint32_t addr) {
    asm volatile("ldmatrix.sync.aligned.m8n8.x4.trans.shared.b16 {%0,%1,%2,%3}, [%4];"
                 : "=r"(r0), "=r"(r1), "=r"(r2), "=r"(r3) : "r"(addr));
}
__device__ __forceinline__ void cpa16(uint32_t dst, const void* src) {
    asm volatile("cp.async.cg.shared.global [%0], [%1], 16;" :: "r"(dst), "l"(src));
}
#define CP_COMMIT() asm volatile("cp.async.commit_group;")
#define CP_WAIT1()  asm volatile("cp.async.wait_group 1;")
__device__ __forceinline__ uint32_t pkbf(float a, float b) {
    bf162 h = __floats2bfloat162_rn(a, b);
    return *(uint32_t*)&h;
}

// ---------------------------------------------------------------------------
// Fused weight transpose -> bf16 [N,K]; K/V packed into wb_kv; bias_kv packed.
// ---------------------------------------------------------------------------
__global__ void transpose_all(
    const float* __restrict__ We1, bf16* __restrict__ wb_e1,
    const float* __restrict__ We2, bf16* __restrict__ wb_e2,
    const float* __restrict__ Wq,  bf16* __restrict__ wb_q,
    const float* __restrict__ Wk,
    const float* __restrict__ Wv,  bf16* __restrict__ wb_kv,
    const float* __restrict__ Wd1, bf16* __restrict__ wb_d1,
    const float* __restrict__ Wd2, bf16* __restrict__ wb_d2,
    const float* __restrict__ bk, const float* __restrict__ bv,
    float* __restrict__ bias_kv)
{
    __shared__ float t[32][33];
    int idx = blockIdx.x;
    int x = threadIdx.x, y = threadIdx.y;   // 32 x 8
    if (idx == 496) {                       // bias pack block
        int flat = y * 32 + x;
        bias_kv[flat] = (flat < 128) ? bk[flat] : bv[flat - 128];
        return;
    }
    const float* in; bf16* out; int K, N, l;
    if (idx < 192)      { in = We1; out = wb_e1; K = HH;  N = MID; l = idx; }
    else if (idx < 224) { in = We2; out = wb_e2; K = MID; N = LAT; l = idx - 192; }
    else if (idx < 240) { in = Wq;  out = wb_q;  K = LAT; N = LAT; l = idx - 224; }
    else if (idx < 256) { in = Wk;  out = wb_kv; K = LAT; N = LAT; l = idx - 240; }
    else if (idx < 272) { in = Wv;  out = wb_kv + 128 * LAT; K = LAT; N = LAT; l = idx - 256; }
    else if (idx < 304) { in = Wd1; out = wb_d1; K = LAT; N = MID; l = idx - 272; }
    else                { in = Wd2; out = wb_d2; K = MID; N = HH;  l = idx - 304; }
    int tx = N >> 5;
    int nx = (l % tx) * 32, kx = (l / tx) * 32;
#pragma unroll
    for (int i = 0; i < 32; i += 8)
        t[y + i][x] = in[(long)(kx + y + i) * N + nx + x];
    __syncthreads();
#pragma unroll
    for (int i = 0; i < 32; i += 8)
        out[(long)(nx + y + i) * K + kx + x] = __float2bfloat16(t[x][y + i]);
}

// ---------------------------------------------------------------------------
// bf16 mma GEMM: C = act(A_bf16 @ Wt_bf16^T + bias)
// CTA 128xBN, BK=64 bf16, 3-stage cp.async, m16n8k16.
// ---------------------------------------------------------------------------
#define BPAD 72

template <int ACT, int BN, int OUT32>
__global__ __launch_bounds__(256) void gemm_bf16(
    const bf16* __restrict__ A, const bf16* __restrict__ Wt,
    const float* __restrict__ bias, void* __restrict__ Cv,
    int M, int N, int K)
{
    extern __shared__ char smraw[];
    bf16* smb = (bf16*)smraw;
    constexpr int STG_A = 128 * BPAD;
    constexpr int STG_B = BN * BPAD;
    constexpr int STG   = STG_A + STG_B;
    constexpr int NT    = BN / 32;

    const int tid = threadIdx.x;
    const int wid = tid >> 5, lane = tid & 31;
    const int g = lane >> 2, t4 = lane & 3;
    const int wm = (wid & 1) * 64;
    const int wn = (wid >> 1) * (BN / 4);
    const int m0 = blockIdx.y * 128, n0 = blockIdx.x * BN;

    float c[4][NT][4];
#pragma unroll
    for (int mt = 0; mt < 4; mt++)
#pragma unroll
        for (int nt = 0; nt < NT; nt++)
#pragma unroll
            for (int i = 0; i < 4; i++) c[mt][nt][i] = 0.f;

    const int nk = K >> 6;

    auto load_stage = [&](int kt, int s) {
        bf16* base = smb + s * STG;
#pragma unroll
        for (int i = 0; i < 4; i++) {
            int idx = tid + i * 256;
            int r = idx >> 3, c8 = idx & 7;
            cpa16(smem_u32(base + r * BPAD + c8 * 8),
                  A + (long)(m0 + r) * K + kt * 64 + c8 * 8);
        }
#pragma unroll
        for (int i = 0; i < BN / 32; i++) {
            int idx = tid + i * 256;
            int r = idx >> 3, c8 = idx & 7;
            cpa16(smem_u32(base + STG_A + r * BPAD + c8 * 8),
                  Wt + (long)(n0 + r) * K + kt * 64 + c8 * 8);
        }
    };

    const int mat = lane >> 3, rowin = lane & 7;
    const uint32_t a0 = smem_u32(smb)
        + (uint32_t)((wm + (mat & 1) * 8 + rowin) * BPAD + (mat >> 1) * 8) * 2;
    const uint32_t b0 = smem_u32(smb) + (uint32_t)STG_A * 2
        + (uint32_t)((wn + (mat >> 1) * 8 + rowin) * BPAD + (mat & 1) * 8) * 2;

    load_stage(0, 0); CP_COMMIT();
    load_stage(1, 1); CP_COMMIT();

    for (int kt = 0; kt < nk; kt++) {
        CP_WAIT1();
        __syncthreads();
        if (kt + 2 < nk) load_stage(kt + 2, (kt + 2) % 3);
        CP_COMMIT();

        int s = kt % 3;
        uint32_t ab = a0 + (uint32_t)(s * STG) * 2;
        uint32_t bb = b0 + (uint32_t)(s * STG) * 2;
#pragma unroll
        for (int ks = 0; ks < 4; ks++) {
            uint32_t af[4][4], bfr[NT][2];
#pragma unroll
            for (int mt = 0; mt < 4; mt++)
                ldsm4(af[mt][0], af[mt][1], af[mt][2], af[mt][3],
                      ab + mt * (16 * BPAD * 2) + ks * 32);
#pragma unroll
            for (int p = 0; p < NT / 2; p++)
                ldsm4(bfr[2 * p][0], bfr[2 * p][1], bfr[2 * p + 1][0], bfr[2 * p + 1][1],
                      bb + p * (16 * BPAD * 2) + ks * 32);
#pragma unroll
            for (int mt = 0; mt < 4; mt++)
#pragma unroll
                for (int nt = 0; nt < NT; nt++)
                    mma16(c[mt][nt], af[mt], bfr[nt]);
        }
    }

#pragma unroll
    for (int mt = 0; mt < 4; mt++) {
        int r0 = m0 + wm + mt * 16 + g;
#pragma unroll
        for (int nt = 0; nt < NT; nt++) {
            int col = n0 + wn + nt * 8 + 2 * t4;
            float2 bv = *(const float2*)(bias + col);
            float x0 = c[mt][nt][0] + bv.x;
            float x1 = c[mt][nt][1] + bv.y;
            float x2 = c[mt][nt][2] + bv.x;
            float x3 = c[mt][nt][3] + bv.y;
            if (ACT == 1) {
                x0 = fmaxf(x0, 0.f); x1 = fmaxf(x1, 0.f);
                x2 = fmaxf(x2, 0.f); x3 = fmaxf(x3, 0.f);
            }
            if (ACT == 2) {
                x0 = 1.f / (1.f + __expf(-x0)); x1 = 1.f / (1.f + __expf(-x1));
                x2 = 1.f / (1.f + __expf(-x2)); x3 = 1.f / (1.f + __expf(-x3));
            }
            if (OUT32) {
                float* C = (float*)Cv;
                *(float2*)(C + (long)r0 * N + col)       = make_float2(x0, x1);
                *(float2*)(C + (long)(r0 + 8) * N + col) = make_float2(x2, x3);
            } else {
                bf16* C = (bf16*)Cv;
                *(bf162*)(C + (long)r0 * N + col)       = __floats2bfloat162_rn(x0, x1);
                *(bf162*)(C + (long)(r0 + 8) * N + col) = __floats2bfloat162_rn(x2, x3);
            }
        }
    }
}

// ---------------------------------------------------------------------------
// Stage-1 GEMM, fused fp32->bf16 on A, BOTH inputs in one launch.
// blockIdx.y < HB: rows of A0 (main); else rows of A1 (feat).
// ---------------------------------------------------------------------------
__global__ __launch_bounds__(256) void gemm_e1f(
    const float* __restrict__ A0, const float* __restrict__ A1,
    const bf16* __restrict__ Wt,
    const float* __restrict__ bias, bf16* __restrict__ C,
    int Mhalf, int N, int K)
{
    extern __shared__ char smraw[];
    bf16* smb = (bf16*)smraw;
    constexpr int BN = 256;
    constexpr int STG_A = 128 * BPAD;
    constexpr int STG_B = BN * BPAD;
    constexpr int NT = 8;
    bf16* Asm = smb;                 // 2 stages
    bf16* Bsm = smb + 2 * STG_A;     // 3 stages

    const int tid = threadIdx.x;
    const int wid = tid >> 5, lane = tid & 31;
    const int g = lane >> 2, t4 = lane & 3;
    const int wm = (wid & 1) * 64;
    const int wn = (wid >> 1) * 64;

    const int hb = Mhalf / 128;
    const int half = blockIdx.y >= hb;
    const float* A = half ? A1 : A0;
    const int m0 = (blockIdx.y - half * hb) * 128;   // row in A
    const long crow0 = (long)blockIdx.y * 128;       // row in C (contiguous halves)
    const int n0 = blockIdx.x * BN;

    float c[4][NT][4];
#pragma unroll
    for (int mt = 0; mt < 4; mt++)
#pragma unroll
        for (int nt = 0; nt < NT; nt++)
#pragma unroll
            for (int i = 0; i < 4; i++) c[mt][nt][i] = 0.f;

    const int nk = K >> 6;          // 12 for K=768

    const int arow = tid >> 1, ahalf = (tid & 1) * 32;
    float4 ar[8];
    auto ldA = [&](int kt) {
        const float* Ar = A + (long)(m0 + arow) * K + kt * 64 + ahalf;
#pragma unroll
        for (int i = 0; i < 8; i++) ar[i] = *(const float4*)(Ar + i * 4);
    };
    auto stA = [&](int buf) {
        bf16* d = Asm + buf * STG_A + arow * BPAD + ahalf;
#pragma unroll
        for (int i = 0; i < 4; i++) {
            uint4 u;
            u.x = pkbf(ar[2 * i].x,     ar[2 * i].y);
            u.y = pkbf(ar[2 * i].z,     ar[2 * i].w);
            u.z = pkbf(ar[2 * i + 1].x, ar[2 * i + 1].y);
            u.w = pkbf(ar[2 * i + 1].z, ar[2 * i + 1].w);
            *(uint4*)(d + i * 8) = u;
        }
    };
    auto loadB = [&](int kt, int s) {
        bf16* base = Bsm + s * STG_B;
#pragma unroll
        for (int i = 0; i < 8; i++) {
            int idx = tid + i * 256;
            int r = idx >> 3, c8 = idx & 7;
            cpa16(smem_u32(base + r * BPAD + c8 * 8),
                  Wt + (long)(n0 + r) * K + kt * 64 + c8 * 8);
        }
    };

    const int mat = lane >> 3, rowin = lane & 7;
    const uint32_t a0 = smem_u32(Asm)
        + (uint32_t)((wm + (mat & 1) * 8 + rowin) * BPAD + (mat >> 1) * 8) * 2;
    const uint32_t b0 = smem_u32(Bsm)
        + (uint32_t)((wn + (mat >> 1) * 8 + rowin) * BPAD + (mat & 1) * 8) * 2;

    ldA(0);
    loadB(0, 0); CP_COMMIT();
    loadB(1, 1); CP_COMMIT();
    stA(0);

    for (int kt = 0; kt < nk; kt++) {
        if (kt + 1 < nk) ldA(kt + 1);
        CP_WAIT1();
        __syncthreads();
        if (kt + 2 < nk) loadB(kt + 2, (kt + 2) % 3);
        CP_COMMIT();

        uint32_t ab = a0 + (uint32_t)((kt & 1) * STG_A) * 2;
        uint32_t bb = b0 + (uint32_t)((kt % 3) * STG_B) * 2;
#pragma unroll
        for (int ks = 0; ks < 4; ks++) {
            uint32_t af[4][4], bfr[NT][2];
#pragma unroll
            for (int mt = 0; mt < 4; mt++)
                ldsm4(af[mt][0], af[mt][1], af[mt][2], af[mt][3],
                      ab + mt * (16 * BPAD * 2) + ks * 32);
#pragma unroll
            for (int p = 0; p < NT / 2; p++)
                ldsm4(bfr[2 * p][0], bfr[2 * p][1], bfr[2 * p + 1][0], bfr[2 * p + 1][1],
                      bb + p * (16 * BPAD * 2) + ks * 32);
#pragma unroll
            for (int mt = 0; mt < 4; mt++)
#pragma unroll
                for (int nt = 0; nt < NT; nt++)
                    mma16(c[mt][nt], af[mt], bfr[nt]);
        }
        if (kt + 1 < nk) stA((kt + 1) & 1);
    }

#pragma unroll
    for (int mt = 0; mt < 4; mt++) {
        long r0 = crow0 + wm + mt * 16 + g;
#pragma unroll
        for (int nt = 0; nt < NT; nt++) {
            int col = n0 + wn + nt * 8 + 2 * t4;
            float2 bv = *(const float2*)(bias + col);
            float x0 = fmaxf(c[mt][nt][0] + bv.x, 0.f);
            float x1 = fmaxf(c[mt][nt][1] + bv.y, 0.f);
            float x2 = fmaxf(c[mt][nt][2] + bv.x, 0.f);
            float x3 = fmaxf(c[mt][nt][3] + bv.y, 0.f);
            *(bf162*)(C + r0 * N + col)       = __floats2bfloat162_rn(x0, x1);
            *(bf162*)(C + (r0 + 8) * N + col) = __floats2bfloat162_rn(x2, x3);
        }
    }
}

// ---------------------------------------------------------------------------
// Flash attention: BN=128 key tiles, register softmax, S->P fragment reuse,
// double-buffered cp.async K/V from packed g_kv, Q fragments preloaded.
// ---------------------------------------------------------------------------
#define FA_BM 128
#define FA_BN 128
#define FQS   136
// smem: Qs [128][FQS] + 2 x KV stage [256][FQS] (K rows 0-127, V rows 128-255)
#define FA_SMEM_BYTES ((128 * FQS + 2 * 256 * FQS) * 2)

__global__ __launch_bounds__(256, 1) void flash_attn_bf16(
    const bf16* __restrict__ Q, const bf16* __restrict__ KV,
    bf16* __restrict__ O)
{
    extern __shared__ char smraw[];
    bf16* Qs  = (bf16*)smraw;                // [128][FQS]
    bf16* KVs = Qs + 128 * FQS;              // [2][256][FQS]

    const int tid = threadIdx.x;
    const int b   = blockIdx.y;
    const int m0  = blockIdx.x * FA_BM;

    const bf16* Qb = Q + ((long)b * N1 + m0) * LAT;
    const bf16* Kb = KV + (long)b * N2 * 256;       // cols 0-127 K
    const bf16* Vb = Kb + 128;                      // cols 128-255 V

    const int wid = tid >> 5, lane = tid & 31;
    const int g = lane >> 2, t4 = lane & 3;
    const int mat = lane >> 3, rowin = lane & 7;
    const int qr0 = wid * 16;

    // Load Q tile
#pragma unroll
    for (int i = 0; i < 8; i++) {
        int idx = tid + i * 256;
        int r = idx >> 4, c8 = idx & 15;
        *(uint4*)(Qs + r * FQS + c8 * 8) = *(const uint4*)(Qb + r * LAT + c8 * 8);
    }

    auto loadKV = [&](int t, int s) {
        bf16* base = KVs + s * 256 * FQS;
#pragma unroll
        for (int i = 0; i < 8; i++) {
            int idx = tid + i * 256;
            int r = idx >> 4, c8 = idx & 15;
            cpa16(smem_u32(base + r * FQS + c8 * 8),
                  Kb + (long)(t * FA_BN + r) * 256 + c8 * 8);
        }
#pragma unroll
        for (int i = 0; i < 8; i++) {
            int idx = tid + i * 256;
            int r = idx >> 4, c8 = idx & 15;
            cpa16(smem_u32(base + (128 + r) * FQS + c8 * 8),
                  Vb + (long)(t * FA_BN + r) * 256 + c8 * 8);
        }
    };

    const uint32_t aq = smem_u32(Qs)
        + (uint32_t)((qr0 + (mat & 1) * 8 + rowin) * FQS + (mat >> 1) * 8) * 2;
    const uint32_t bk0 = smem_u32(KVs)
        + (uint32_t)(((mat >> 1) * 8 + rowin) * FQS + (mat & 1) * 8) * 2;
    const uint32_t bv0 = smem_u32(KVs) + (uint32_t)(128 * FQS) * 2
        + (uint32_t)(((mat & 1) * 8 + rowin) * FQS + (mat >> 1) * 8) * 2;

    float m0r = -INFINITY, m1r = -INFINITY, l0 = 0.f, l1 = 0.f;
    float oc[16][4];
#pragma unroll
    for (int nt = 0; nt < 16; nt++)
#pragma unroll
        for (int i = 0; i < 4; i++) oc[nt][i] = 0.f;

    loadKV(0, 0); CP_COMMIT();
    loadKV(1, 1); CP_COMMIT();
    __syncthreads();   // Q visible

    // Preload all Q fragments (K=128 -> 8 ksteps)
    uint32_t qf[8][4];
#pragma unroll
    for (int ks = 0; ks < 8; ks++)
        ldsm4(qf[ks][0], qf[ks][1], qf[ks][2], qf[ks][3], aq + ks * 32);

    const int NTILES = N2 / FA_BN;   // 16
    for (int t = 0; t < NTILES; t++) {
        CP_WAIT1();
        __syncthreads();

        int s = t & 1;
        uint32_t bk = bk0 + (uint32_t)(s * 256 * FQS) * 2;
        uint32_t bv = bv0 + (uint32_t)(s * 256 * FQS) * 2;

        // --- S = Q @ K^T (8 ksteps over d; 128 keys = 16 n-tiles) ---
        float c[16][4];
#pragma unroll
        for (int nt = 0; nt < 16; nt++)
#pragma unroll
            for (int i = 0; i < 4; i++) c[nt][i] = 0.f;

#pragma unroll
        for (int ks = 0; ks < 8; ks++) {
            uint32_t bfr[16][2];
#pragma unroll
            for (int p = 0; p < 8; p++)
                ldsm4(bfr[2 * p][0], bfr[2 * p][1], bfr[2 * p + 1][0], bfr[2 * p + 1][1],
                      bk + p * (16 * FQS * 2) + ks * 32);
#pragma unroll
            for (int nt = 0; nt < 16; nt++)
                mma16(c[nt], qf[ks], bfr[nt]);
        }

        // --- Register online softmax (rows qr0+g and qr0+g+8) ---
        float mx0 = c[0][0], mx1 = c[0][2];
#pragma unroll
        for (int nt = 0; nt < 16; nt++) {
            mx0 = fmaxf(mx0, fmaxf(c[nt][0], c[nt][1]));
            mx1 = fmaxf(mx1, fmaxf(c[nt][2], c[nt][3]));
        }
        mx0 = fmaxf(mx0, __shfl_xor_sync(0xFFFFFFFFu, mx0, 1));
        mx0 = fmaxf(mx0, __shfl_xor_sync(0xFFFFFFFFu, mx0, 2));
        mx1 = fmaxf(mx1, __shfl_xor_sync(0xFFFFFFFFu, mx1, 1));
        mx1 = fmaxf(mx1, __shfl_xor_sync(0xFFFFFFFFu, mx1, 2));
        float mn0 = fmaxf(m0r, mx0), mn1 = fmaxf(m1r, mx1);
        float al0 = __expf(m0r - mn0), al1 = __expf(m1r - mn1);
        float s0 = 0.f, s1 = 0.f;
#pragma unroll
        for (int nt = 0; nt < 16; nt++) {
            float e0 = __expf(c[nt][0] - mn0);
            float e1 = __expf(c[nt][1] - mn0);
            float e2 = __expf(c[nt][2] - mn1);
            float e3 = __expf(c[nt][3] - mn1);
            c[nt][0] = e0; c[nt][1] = e1; c[nt][2] = e2; c[nt][3] = e3;
            s0 += e0 + e1; s1 += e2 + e3;
        }
        s0 += __shfl_xor_sync(0xFFFFFFFFu, s0, 1);
        s0 += __shfl_xor_sync(0xFFFFFFFFu, s0, 2);
        s1 += __shfl_xor_sync(0xFFFFFFFFu, s1, 1);
        s1 += __shfl_xor_sync(0xFFFFFFFFu, s1, 2);
        l0 = l0 * al0 + s0; l1 = l1 * al1 + s1;
        m0r = mn0; m1r = mn1;

#pragma unroll
        for (int nt = 0; nt < 16; nt++) {
            oc[nt][0] *= al0; oc[nt][1] *= al0;
            oc[nt][2] *= al1; oc[nt][3] *= al1;
        }

        // --- O += P @ V (8 ksteps over 128 keys; d = 16 n-tiles) ---
#pragma unroll
        for (int ks = 0; ks < 8; ks++) {
            uint32_t pf[4];
            pf[0] = pkbf(c[2 * ks][0],     c[2 * ks][1]);
            pf[1] = pkbf(c[2 * ks][2],     c[2 * ks][3]);
            pf[2] = pkbf(c[2 * ks + 1][0], c[2 * ks + 1][1]);
            pf[3] = pkbf(c[2 * ks + 1][2], c[2 * ks + 1][3]);
            uint32_t vf[16][2];
#pragma unroll
            for (int p = 0; p < 8; p++)
                ldsm4t(vf[2 * p][0], vf[2 * p][1], vf[2 * p + 1][0], vf[2 * p + 1][1],
                       bv + ks * (16 * FQS * 2) + p * 32);
#pragma unroll
            for (int nt = 0; nt < 16; nt++)
                mma16(oc[nt], pf, vf[nt]);
        }
        __syncthreads();
        if (t + 2 < NTILES) loadKV(t + 2, s);
        CP_COMMIT();
    }

    // --- Epilogue ---
    float inv0 = 1.f / l0, inv1 = 1.f / l1;
    long row0 = (long)b * N1 + m0 + qr0 + g;
#pragma unroll
    for (int nt = 0; nt < 16; nt++) {
        int col = nt * 8 + 2 * t4;
        *(bf162*)(O + row0 * LAT + col) =
            __floats2bfloat162_rn(oc[nt][0] * inv0, oc[nt][1] * inv0);
        *(bf162*)(O + (row0 + 8) * LAT + col) =
            __floats2bfloat162_rn(oc[nt][2] * inv1, oc[nt][3] * inv1);
    }
}

// ---------------------------------------------------------------------------
// Host launcher
// ---------------------------------------------------------------------------
extern "C" void kernel_launch(void* const* d_in, const int* in_sizes, int n_in,
                              void* d_out, int out_size)
{
    const float* mainf = (const float*)d_in[0];
    const float* feat  = (const float*)d_in[1];
    const float* We1   = (const float*)d_in[2];
    const float* be1   = (const float*)d_in[3];
    const float* We2   = (const float*)d_in[4];
    const float* be2   = (const float*)d_in[5];
    const float* Wq    = (const float*)d_in[6];
    const float* bq    = (const float*)d_in[7];
    const float* Wk    = (const float*)d_in[8];
    const float* bk    = (const float*)d_in[9];
    const float* Wv    = (const float*)d_in[10];
    const float* bv    = (const float*)d_in[11];
    const float* Wd1   = (const float*)d_in[12];
    const float* bd1   = (const float*)d_in[13];
    const float* Wd2   = (const float*)d_in[14];
    const float* bd2   = (const float*)d_in[15];
    float* out = (float*)d_out;

    bf16 *p_mid2, *p_mf, *p_q, *p_kv, *p_attn;
    bf16 *wb_e1, *wb_e2, *wb_q, *wb_kv, *wb_d1, *wb_d2;
    float* bias_kv;
    cudaGetSymbolAddress((void**)&p_mid2, g_mid2);
    cudaGetSymbolAddress((void**)&p_mf,   g_mf);
    cudaGetSymbolAddress((void**)&p_q,    g_q);
    cudaGetSymbolAddress((void**)&p_kv,   g_kv);
    cudaGetSymbolAddress((void**)&p_attn, g_attn);
    cudaGetSymbolAddress((void**)&wb_e1, g_wb_e1);
    cudaGetSymbolAddress((void**)&wb_e2, g_wb_e2);
    cudaGetSymbolAddress((void**)&wb_q,  g_wb_q);
    cudaGetSymbolAddress((void**)&wb_kv, g_wb_kv);
    cudaGetSymbolAddress((void**)&wb_d1, g_wb_d1);
    cudaGetSymbolAddress((void**)&wb_d2, g_wb_d2);
    cudaGetSymbolAddress((void**)&bias_kv, g_bias_kv);

    const int gb256_sm = 3 * (128 + 256) * BPAD * 2;              // 165888
    const int gb128_sm = 3 * (128 + 128) * BPAD * 2;              // 110592
    const int e1f_sm   = (2 * 128 + 3 * 256) * BPAD * 2;          // 147456
    const int fa_sm    = FA_SMEM_BYTES;                           // 174080
    cudaFuncSetAttribute(gemm_bf16<1, 128, 0>, cudaFuncAttributeMaxDynamicSharedMemorySize, gb128_sm);
    cudaFuncSetAttribute(gemm_bf16<0, 128, 0>, cudaFuncAttributeMaxDynamicSharedMemorySize, gb128_sm);
    cudaFuncSetAttribute(gemm_bf16<0, 256, 0>, cudaFuncAttributeMaxDynamicSharedMemorySize, gb256_sm);
    cudaFuncSetAttribute(gemm_bf16<1, 256, 0>, cudaFuncAttributeMaxDynamicSharedMemorySize, gb256_sm);
    cudaFuncSetAttribute(gemm_bf16<2, 256, 1>, cudaFuncAttributeMaxDynamicSharedMemorySize, gb256_sm);
    cudaFuncSetAttribute(gemm_e1f, cudaFuncAttributeMaxDynamicSharedMemorySize, e1f_sm);
    cudaFuncSetAttribute(flash_attn_bf16, cudaFuncAttributeMaxDynamicSharedMemorySize, fa_sm);

    transpose_all<<<497, dim3(32, 8)>>>(We1, wb_e1, We2, wb_e2, Wq, wb_q,
                                        Wk, Wv, wb_kv, Wd1, wb_d1, Wd2, wb_d2,
                                        bk, bv, bias_kv);

    const int M = RTOT;
    // encode stage 1: both inputs in one launch (grid 512)
    gemm_e1f<<<dim3(1, 2 * M / 128), 256, e1f_sm>>>(mainf, feat, wb_e1, be1, p_mid2, M, MID, HH);
    // encode stage 2, both halves in one launch (M = 65536)
    gemm_bf16<1, 128, 0><<<dim3(1, 2 * M / 128), 256, gb128_sm>>>(p_mid2, wb_e2, be2, p_mf, 2 * M, LAT, MID);
    // q (from m) and fused k+v (from f)
    gemm_bf16<0, 128, 0><<<dim3(1, M / 128), 256, gb128_sm>>>(p_mf, wb_q, bq, p_q, M, LAT, LAT);
    gemm_bf16<0, 256, 0><<<dim3(1, M / 128), 256, gb256_sm>>>(p_mf + (long)M * LAT, wb_kv, bias_kv, p_kv, M, 256, LAT);
    // attention
    flash_attn_bf16<<<dim3(N1 / FA_BM, BB), 256, fa_sm>>>(p_q, p_kv, p_attn);
    // decode
    gemm_bf16<1, 256, 0><<<dim3(1, M / 128), 256, gb256_sm>>>(p_attn, wb_d1, bd1, p_mid2, M, MID, LAT);
    gemm_bf16<2, 256, 1><<<dim3(3, M / 128), 256, gb256_sm>>>(p_mid2, wb_d2, bd2, out, M, HH, MID);
}